// round 1
// baseline (speedup 1.0000x reference)
#include <cuda_runtime.h>
#include <math.h>

// Problem constants
#define B_SZ  512
#define DIN   64
#define DCL   4998
#define DTRF  5120
#define PADN  61
#define PP    32
#define EE    160
#define DOUT  3000

// Global scratch (device statics; no allocation APIs anywhere)
__device__ float g_cl[B_SZ * DCL];   // compact cl (pre-pad)
__device__ float g_y [B_SZ * DTRF];  // transformer output y

// ---------------------------------------------------------------------------
// Kernel 1: cl = (x*std + mean) @ mat     [512,64] @ [64,4998] -> g_cl compact
// Tile: 32 rows x 128 cols per block, 256 threads, 4x4 per-thread register tile
// ---------------------------------------------------------------------------
__global__ __launch_bounds__(256) void k1_clgemm(
    const float* __restrict__ x, const float* __restrict__ stdv,
    const float* __restrict__ meanv, const float* __restrict__ mat)
{
    __shared__ float u_s[32 * 64];
    const int rbase = blockIdx.y * 32;
    const int cbase = blockIdx.x * 128;
    const int tid = threadIdx.x;

    // load + un-normalize x tile into smem
    for (int idx = tid; idx < 32 * 64; idx += 256) {
        int r = idx >> 6, k = idx & 63;
        u_s[idx] = x[(rbase + r) * DIN + k] * stdv[k] + meanv[k];
    }
    __syncthreads();

    const int ty = tid >> 5;   // 0..7  (row group)
    const int tx = tid & 31;   // 0..31 (col lane)
    int   c[4];  bool cv[4];
#pragma unroll
    for (int j = 0; j < 4; j++) { c[j] = cbase + tx + 32 * j; cv[j] = (c[j] < DCL); }

    float acc[4][4] = {};
    for (int k = 0; k < 64; k++) {
        float a[4], b[4];
#pragma unroll
        for (int i = 0; i < 4; i++) a[i] = u_s[(ty + 8 * i) * 64 + k];
#pragma unroll
        for (int j = 0; j < 4; j++) b[j] = cv[j] ? mat[k * DCL + c[j]] : 0.f;
#pragma unroll
        for (int i = 0; i < 4; i++)
#pragma unroll
            for (int j = 0; j < 4; j++)
                acc[i][j] += a[i] * b[j];
    }
#pragma unroll
    for (int i = 0; i < 4; i++) {
        int row = rbase + ty + 8 * i;
#pragma unroll
        for (int j = 0; j < 4; j++)
            if (cv[j]) g_cl[row * DCL + c[j]] = acc[i][j];
    }
}

// ---------------------------------------------------------------------------
// Kernel 2: per-batch fused block: pad+LN -> QKV -> attn(softmax dim=1) ->
//           residual -> BT matmul -> Supact -> y.    512 blocks x 640 threads.
// Dynamic smem layout (floats):
//   s_cl[5120] | s_xn[5120](->h) | s_q[5120](->x2) | s_k[5120] | s_v[5120]
//   | s_att[1024] | s_red[64]        total 26688 floats = 106752 B
// ---------------------------------------------------------------------------
__global__ __launch_bounds__(640) void k2_block(
    const float* __restrict__ ln_g, const float* __restrict__ ln_b,
    const float* __restrict__ wq, const float* __restrict__ bq,
    const float* __restrict__ wk, const float* __restrict__ bk,
    const float* __restrict__ wv, const float* __restrict__ bv,
    const float* __restrict__ bt_w, const float* __restrict__ bt_b,
    const float* __restrict__ bt_gain, const float* __restrict__ bt_bias,
    const float* __restrict__ sup_gamma, const float* __restrict__ sup_beta)
{
    extern __shared__ float s[];
    float* s_cl  = s;
    float* s_xn  = s + 5120;    // later reused as h
    float* s_q   = s + 10240;   // later reused as x2
    float* s_k   = s + 15360;
    float* s_v   = s + 20480;
    float* s_att = s + 25600;   // 1024
    float* s_red = s + 26624;   // 64

    const int b = blockIdx.x;
    const int t = threadIdx.x;
    const float* clrow = g_cl + (size_t)b * DCL;

    // ---- load padded cl, accumulate LN stats ----
    float lsum = 0.f, lsq = 0.f;
#pragma unroll
    for (int r = 0; r < 8; r++) {
        int idx = t + 640 * r;
        float v = 0.f;
        if (idx >= PADN && idx < PADN + DCL) v = clrow[idx - PADN];
        s_cl[idx] = v;
        lsum += v; lsq += v * v;
    }
#pragma unroll
    for (int o = 16; o > 0; o >>= 1) {
        lsum += __shfl_xor_sync(~0u, lsum, o);
        lsq  += __shfl_xor_sync(~0u, lsq,  o);
    }
    const int warp = t >> 5, lane = t & 31;
    if (lane == 0) { s_red[warp] = lsum; s_red[32 + warp] = lsq; }
    __syncthreads();
    if (warp == 0) {
        float a  = (lane < 20) ? s_red[lane]      : 0.f;
        float c2 = (lane < 20) ? s_red[32 + lane] : 0.f;
#pragma unroll
        for (int o = 16; o > 0; o >>= 1) {
            a  += __shfl_xor_sync(~0u, a,  o);
            c2 += __shfl_xor_sync(~0u, c2, o);
        }
        if (lane == 0) {
            float mu  = a / (float)DTRF;
            float var = c2 / (float)DTRF - mu * mu;
            s_red[0] = mu;
            s_red[1] = rsqrtf(var + 1e-5f);
        }
    }
    __syncthreads();
    const float mu = s_red[0], rstd = s_red[1];

    // ---- LayerNorm ----
#pragma unroll
    for (int r = 0; r < 8; r++) {
        int idx = t + 640 * r;
        s_xn[idx] = (s_cl[idx] - mu) * rstd * ln_g[idx] + ln_b[idx];
    }
    __syncthreads();

    // ---- QKV: thread owns column f, 8 rows p0..p0+7; xn shared across Q,K,V
    const int f  = t % 160;            // warps are uniform in t/160 (160 = 5*32)
    const int p0 = (t / 160) * 8;
    {
        float aq[8] = {}, ak[8] = {}, av[8] = {};
        const float4* wq4 = (const float4*)(wq + f * EE);
        const float4* wk4 = (const float4*)(wk + f * EE);
        const float4* wv4 = (const float4*)(wv + f * EE);
#pragma unroll 2
        for (int e4 = 0; e4 < 40; e4++) {
            float4 q4 = wq4[e4], k4 = wk4[e4], v4 = wv4[e4];
#pragma unroll
            for (int i = 0; i < 8; i++) {
                float4 xv = *(const float4*)&s_xn[(p0 + i) * EE + e4 * 4];
                aq[i] += xv.x * q4.x + xv.y * q4.y + xv.z * q4.z + xv.w * q4.w;
                ak[i] += xv.x * k4.x + xv.y * k4.y + xv.z * k4.z + xv.w * k4.w;
                av[i] += xv.x * v4.x + xv.y * v4.y + xv.z * v4.z + xv.w * v4.w;
            }
        }
        const float bqf = bq[f], bkf = bk[f], bvf = bv[f];
#pragma unroll
        for (int i = 0; i < 8; i++) {
            s_q[(p0 + i) * EE + f] = aq[i] + bqf;
            s_k[(p0 + i) * EE + f] = ak[i] + bkf;
            s_v[(p0 + i) * EE + f] = av[i] + bvf;
        }
    }
    __syncthreads();

    // ---- dot[p][q] = Q[p].K[q] / sqrt(E) ----
    const float inv_scale = 1.0f / sqrtf(160.0f);
    for (int idx = t; idx < 1024; idx += 640) {
        int p = idx >> 5, q = idx & 31;
        float acc = 0.f;
#pragma unroll 4
        for (int e4 = 0; e4 < 40; e4++) {
            float4 qv = *(const float4*)&s_q[p * EE + e4 * 4];
            float4 kv = *(const float4*)&s_k[q * EE + e4 * 4];
            acc += qv.x * kv.x + qv.y * kv.y + qv.z * kv.z + qv.w * kv.w;
        }
        s_att[idx] = acc * inv_scale;
    }
    __syncthreads();

    // ---- softmax over p (dim=1): column-wise, one lane per column q ----
    if (t < 32) {
        int q = t;
        float m = -1e30f;
#pragma unroll
        for (int p = 0; p < 32; p++) m = fmaxf(m, s_att[p * 32 + q]);
        float ssum = 0.f;
#pragma unroll
        for (int p = 0; p < 32; p++) {
            float e = __expf(s_att[p * 32 + q] - m);
            s_att[p * 32 + q] = e;
            ssum += e;
        }
        float inv = 1.f / ssum;
#pragma unroll
        for (int p = 0; p < 32; p++) s_att[p * 32 + q] *= inv;
    }
    __syncthreads();

    // ---- h = att @ V + cl ; x2 = h*bt_gain + bt_bias  (h->s_xn, x2->s_q) ----
    const float btg = bt_gain[0], btb = bt_bias[0];
#pragma unroll
    for (int r = 0; r < 8; r++) {
        int idx = t + 640 * r;
        int p = idx / EE, e = idx % EE;
        float acc = 0.f;
#pragma unroll
        for (int q = 0; q < 32; q++)
            acc += s_att[p * 32 + q] * s_v[q * EE + e];
        float hv = acc + s_cl[idx];
        s_xn[idx] = hv;                 // h (residual source)
        s_q[idx]  = hv * btg + btb;     // x2 (BT input)
    }
    __syncthreads();

    // ---- BT matmul: o[p][f] = sum_e x2[p][e]*bt_w[e][f] + bt_b[f] ----
    float oacc[8] = {};
#pragma unroll 2
    for (int e = 0; e < 160; e += 4) {
        float w0 = bt_w[(e + 0) * EE + f];
        float w1 = bt_w[(e + 1) * EE + f];
        float w2 = bt_w[(e + 2) * EE + f];
        float w3 = bt_w[(e + 3) * EE + f];
#pragma unroll
        for (int i = 0; i < 8; i++) {
            float4 xv = *(const float4*)&s_q[(p0 + i) * EE + e];
            oacc[i] += xv.x * w0 + xv.y * w1 + xv.z * w2 + xv.w * w3;
        }
    }

    // ---- Supact + residual, write y ----
    const float btbf = bt_b[f];
    float* yrow = g_y + (size_t)b * DTRF;
#pragma unroll
    for (int i = 0; i < 8; i++) {
        int idx = (p0 + i) * EE + f;
        float o  = oacc[i] + btbf;
        float gm = sup_gamma[idx];
        float sg = 1.f / (1.f + __expf(-sup_beta[idx] * o));
        yrow[idx] = (gm + sg * (1.f - gm)) * o + s_xn[idx];
    }
}

// ---------------------------------------------------------------------------
// Kernel 3: z = y @ lin_w^T (+lin_b) * out_gain + out_bias
// M=512, N=3000, K=5120.  64x64 tile, BK=16, 256 threads, 4x4 per thread.
// ---------------------------------------------------------------------------
#define BM 64
#define BN 64
#define BK 16

__global__ __launch_bounds__(256) void k3_gemm(
    const float* __restrict__ lin_w, const float* __restrict__ lin_b,
    const float* __restrict__ og_p, const float* __restrict__ ob_p,
    float* __restrict__ out)
{
    __shared__ float As[BK][BM + 4];
    __shared__ float Bs[BK][BN + 4];
    const int t = threadIdx.x;
    const int mbase = blockIdx.y * BM;
    const int nbase = blockIdx.x * BN;

    const int lr = t >> 2;          // 0..63 row within tile
    const int lk = (t & 3) * 4;     // 0,4,8,12

    const float* Arow = g_y + (size_t)(mbase + lr) * DTRF;
    const int   brow = nbase + lr;
    const bool  bval = (brow < DOUT);
    const float* Brow = lin_w + (size_t)(bval ? brow : 0) * DTRF;

    const int tx = t & 15, ty = t >> 4;
    float acc[4][4] = {};

    for (int k0 = 0; k0 < DTRF; k0 += BK) {
        float4 a4 = *(const float4*)&Arow[k0 + lk];
        float4 b4 = bval ? *(const float4*)&Brow[k0 + lk]
                         : make_float4(0.f, 0.f, 0.f, 0.f);
        __syncthreads();
        As[lk + 0][lr] = a4.x; As[lk + 1][lr] = a4.y;
        As[lk + 2][lr] = a4.z; As[lk + 3][lr] = a4.w;
        Bs[lk + 0][lr] = b4.x; Bs[lk + 1][lr] = b4.y;
        Bs[lk + 2][lr] = b4.z; Bs[lk + 3][lr] = b4.w;
        __syncthreads();
#pragma unroll
        for (int kk = 0; kk < BK; kk++) {
            float4 av = *(const float4*)&As[kk][ty * 4];
            float4 bv = *(const float4*)&Bs[kk][tx * 4];
            acc[0][0] += av.x * bv.x; acc[0][1] += av.x * bv.y;
            acc[0][2] += av.x * bv.z; acc[0][3] += av.x * bv.w;
            acc[1][0] += av.y * bv.x; acc[1][1] += av.y * bv.y;
            acc[1][2] += av.y * bv.z; acc[1][3] += av.y * bv.w;
            acc[2][0] += av.z * bv.x; acc[2][1] += av.z * bv.y;
            acc[2][2] += av.z * bv.z; acc[2][3] += av.z * bv.w;
            acc[3][0] += av.w * bv.x; acc[3][1] += av.w * bv.y;
            acc[3][2] += av.w * bv.z; acc[3][3] += av.w * bv.w;
        }
    }

    const float og = og_p[0], ob = ob_p[0];
#pragma unroll
    for (int i = 0; i < 4; i++) {
        int m = mbase + ty * 4 + i;
#pragma unroll
        for (int j = 0; j < 4; j++) {
            int n = nbase + tx * 4 + j;
            if (n < DOUT)
                out[(size_t)m * DOUT + n] = (acc[i][j] + lin_b[n]) * og + ob;
        }
    }
}

// ---------------------------------------------------------------------------
extern "C" void kernel_launch(void* const* d_in, const int* in_sizes, int n_in,
                              void* d_out, int out_size)
{
    const float* x         = (const float*)d_in[0];
    const float* stdv      = (const float*)d_in[1];
    const float* meanv     = (const float*)d_in[2];
    const float* mat       = (const float*)d_in[3];
    const float* ln_g      = (const float*)d_in[4];
    const float* ln_b      = (const float*)d_in[5];
    const float* wq        = (const float*)d_in[6];
    const float* bq        = (const float*)d_in[7];
    const float* wk        = (const float*)d_in[8];
    const float* bk        = (const float*)d_in[9];
    const float* wv        = (const float*)d_in[10];
    const float* bv        = (const float*)d_in[11];
    const float* bt_w      = (const float*)d_in[12];
    const float* bt_b      = (const float*)d_in[13];
    const float* bt_gain   = (const float*)d_in[14];
    const float* bt_bias   = (const float*)d_in[15];
    const float* sup_gamma = (const float*)d_in[16];
    const float* sup_beta  = (const float*)d_in[17];
    const float* lin_w     = (const float*)d_in[18];
    const float* lin_b     = (const float*)d_in[19];
    const float* out_gain  = (const float*)d_in[20];
    const float* out_bias  = (const float*)d_in[21];
    float* out = (float*)d_out;

    const size_t smem2 = 26688 * sizeof(float);  // 106752 B
    cudaFuncSetAttribute(k2_block, cudaFuncAttributeMaxDynamicSharedMemorySize,
                         (int)smem2);

    k1_clgemm<<<dim3(40, 16), 256>>>(x, stdv, meanv, mat);
    k2_block<<<512, 640, smem2>>>(ln_g, ln_b, wq, bq, wk, bk, wv, bv,
                                  bt_w, bt_b, bt_gain, bt_bias,
                                  sup_gamma, sup_beta);
    k3_gemm<<<dim3((DOUT + BN - 1) / BN, B_SZ / BM), 256>>>(
        lin_w, lin_b, out_gain, out_bias, out);
}

// round 2
// speedup vs baseline: 1.2214x; 1.2214x over previous
#include <cuda_runtime.h>
#include <math.h>
#include <stdint.h>

// Problem constants
#define B_SZ  512
#define DIN   64
#define DCL   4998
#define DTRF  5120
#define PADN  61
#define PP    32
#define EE    160
#define DOUT  3000

// Global scratch (device statics; no allocation APIs anywhere)
__device__ float g_cl[B_SZ * DCL];   // compact cl (pre-pad)
__device__ float g_y [B_SZ * DTRF];  // transformer output y

// ---------------------------------------------------------------------------
// Kernel 1: cl = (x*std + mean) @ mat     [512,64] @ [64,4998] -> g_cl compact
// ---------------------------------------------------------------------------
__global__ __launch_bounds__(256) void k1_clgemm(
    const float* __restrict__ x, const float* __restrict__ stdv,
    const float* __restrict__ meanv, const float* __restrict__ mat)
{
    __shared__ float u_s[32 * 64];
    const int rbase = blockIdx.y * 32;
    const int cbase = blockIdx.x * 128;
    const int tid = threadIdx.x;

    for (int idx = tid; idx < 32 * 64; idx += 256) {
        int r = idx >> 6, k = idx & 63;
        u_s[idx] = x[(rbase + r) * DIN + k] * stdv[k] + meanv[k];
    }
    __syncthreads();

    const int ty = tid >> 5;
    const int tx = tid & 31;
    int   c[4];  bool cv[4];
#pragma unroll
    for (int j = 0; j < 4; j++) { c[j] = cbase + tx + 32 * j; cv[j] = (c[j] < DCL); }

    float acc[4][4] = {};
    for (int k = 0; k < 64; k++) {
        float a[4], b[4];
#pragma unroll
        for (int i = 0; i < 4; i++) a[i] = u_s[(ty + 8 * i) * 64 + k];
#pragma unroll
        for (int j = 0; j < 4; j++) b[j] = cv[j] ? mat[k * DCL + c[j]] : 0.f;
#pragma unroll
        for (int i = 0; i < 4; i++)
#pragma unroll
            for (int j = 0; j < 4; j++)
                acc[i][j] += a[i] * b[j];
    }
#pragma unroll
    for (int i = 0; i < 4; i++) {
        int row = rbase + ty + 8 * i;
#pragma unroll
        for (int j = 0; j < 4; j++)
            if (cv[j]) g_cl[row * DCL + c[j]] = acc[i][j];
    }
}

// ---------------------------------------------------------------------------
// Kernel 2: per-batch fused block (unchanged this round)
// ---------------------------------------------------------------------------
__global__ __launch_bounds__(640) void k2_block(
    const float* __restrict__ ln_g, const float* __restrict__ ln_b,
    const float* __restrict__ wq, const float* __restrict__ bq,
    const float* __restrict__ wk, const float* __restrict__ bk,
    const float* __restrict__ wv, const float* __restrict__ bv,
    const float* __restrict__ bt_w, const float* __restrict__ bt_b,
    const float* __restrict__ bt_gain, const float* __restrict__ bt_bias,
    const float* __restrict__ sup_gamma, const float* __restrict__ sup_beta)
{
    extern __shared__ float s[];
    float* s_cl  = s;
    float* s_xn  = s + 5120;
    float* s_q   = s + 10240;
    float* s_k   = s + 15360;
    float* s_v   = s + 20480;
    float* s_att = s + 25600;
    float* s_red = s + 26624;

    const int b = blockIdx.x;
    const int t = threadIdx.x;
    const float* clrow = g_cl + (size_t)b * DCL;

    float lsum = 0.f, lsq = 0.f;
#pragma unroll
    for (int r = 0; r < 8; r++) {
        int idx = t + 640 * r;
        float v = 0.f;
        if (idx >= PADN && idx < PADN + DCL) v = clrow[idx - PADN];
        s_cl[idx] = v;
        lsum += v; lsq += v * v;
    }
#pragma unroll
    for (int o = 16; o > 0; o >>= 1) {
        lsum += __shfl_xor_sync(~0u, lsum, o);
        lsq  += __shfl_xor_sync(~0u, lsq,  o);
    }
    const int warp = t >> 5, lane = t & 31;
    if (lane == 0) { s_red[warp] = lsum; s_red[32 + warp] = lsq; }
    __syncthreads();
    if (warp == 0) {
        float a  = (lane < 20) ? s_red[lane]      : 0.f;
        float c2 = (lane < 20) ? s_red[32 + lane] : 0.f;
#pragma unroll
        for (int o = 16; o > 0; o >>= 1) {
            a  += __shfl_xor_sync(~0u, a,  o);
            c2 += __shfl_xor_sync(~0u, c2, o);
        }
        if (lane == 0) {
            float mu  = a / (float)DTRF;
            float var = c2 / (float)DTRF - mu * mu;
            s_red[0] = mu;
            s_red[1] = rsqrtf(var + 1e-5f);
        }
    }
    __syncthreads();
    const float mu = s_red[0], rstd = s_red[1];

#pragma unroll
    for (int r = 0; r < 8; r++) {
        int idx = t + 640 * r;
        s_xn[idx] = (s_cl[idx] - mu) * rstd * ln_g[idx] + ln_b[idx];
    }
    __syncthreads();

    const int f  = t % 160;
    const int p0 = (t / 160) * 8;
    {
        float aq[8] = {}, ak[8] = {}, av[8] = {};
        const float4* wq4 = (const float4*)(wq + f * EE);
        const float4* wk4 = (const float4*)(wk + f * EE);
        const float4* wv4 = (const float4*)(wv + f * EE);
#pragma unroll 2
        for (int e4 = 0; e4 < 40; e4++) {
            float4 q4 = wq4[e4], k4 = wk4[e4], v4 = wv4[e4];
#pragma unroll
            for (int i = 0; i < 8; i++) {
                float4 xv = *(const float4*)&s_xn[(p0 + i) * EE + e4 * 4];
                aq[i] += xv.x * q4.x + xv.y * q4.y + xv.z * q4.z + xv.w * q4.w;
                ak[i] += xv.x * k4.x + xv.y * k4.y + xv.z * k4.z + xv.w * k4.w;
                av[i] += xv.x * v4.x + xv.y * v4.y + xv.z * v4.z + xv.w * v4.w;
            }
        }
        const float bqf = bq[f], bkf = bk[f], bvf = bv[f];
#pragma unroll
        for (int i = 0; i < 8; i++) {
            s_q[(p0 + i) * EE + f] = aq[i] + bqf;
            s_k[(p0 + i) * EE + f] = ak[i] + bkf;
            s_v[(p0 + i) * EE + f] = av[i] + bvf;
        }
    }
    __syncthreads();

    const float inv_scale = 1.0f / sqrtf(160.0f);
    for (int idx = t; idx < 1024; idx += 640) {
        int p = idx >> 5, q = idx & 31;
        float acc = 0.f;
#pragma unroll 4
        for (int e4 = 0; e4 < 40; e4++) {
            float4 qv = *(const float4*)&s_q[p * EE + e4 * 4];
            float4 kv = *(const float4*)&s_k[q * EE + e4 * 4];
            acc += qv.x * kv.x + qv.y * kv.y + qv.z * kv.z + qv.w * kv.w;
        }
        s_att[idx] = acc * inv_scale;
    }
    __syncthreads();

    if (t < 32) {
        int q = t;
        float m = -1e30f;
#pragma unroll
        for (int p = 0; p < 32; p++) m = fmaxf(m, s_att[p * 32 + q]);
        float ssum = 0.f;
#pragma unroll
        for (int p = 0; p < 32; p++) {
            float e = __expf(s_att[p * 32 + q] - m);
            s_att[p * 32 + q] = e;
            ssum += e;
        }
        float inv = 1.f / ssum;
#pragma unroll
        for (int p = 0; p < 32; p++) s_att[p * 32 + q] *= inv;
    }
    __syncthreads();

    const float btg = bt_gain[0], btb = bt_bias[0];
#pragma unroll
    for (int r = 0; r < 8; r++) {
        int idx = t + 640 * r;
        int p = idx / EE, e = idx % EE;
        float acc = 0.f;
#pragma unroll
        for (int q = 0; q < 32; q++)
            acc += s_att[p * 32 + q] * s_v[q * EE + e];
        float hv = acc + s_cl[idx];
        s_xn[idx] = hv;
        s_q[idx]  = hv * btg + btb;
    }
    __syncthreads();

    float oacc[8] = {};
#pragma unroll 2
    for (int e = 0; e < 160; e += 4) {
        float w0 = bt_w[(e + 0) * EE + f];
        float w1 = bt_w[(e + 1) * EE + f];
        float w2 = bt_w[(e + 2) * EE + f];
        float w3 = bt_w[(e + 3) * EE + f];
#pragma unroll
        for (int i = 0; i < 8; i++) {
            float4 xv = *(const float4*)&s_q[(p0 + i) * EE + e];
            oacc[i] += xv.x * w0 + xv.y * w1 + xv.z * w2 + xv.w * w3;
        }
    }

    const float btbf = bt_b[f];
    float* yrow = g_y + (size_t)b * DTRF;
#pragma unroll
    for (int i = 0; i < 8; i++) {
        int idx = (p0 + i) * EE + f;
        float o  = oacc[i] + btbf;
        float gm = sup_gamma[idx];
        float sg = 1.f / (1.f + __expf(-sup_beta[idx] * o));
        yrow[idx] = (gm + sg * (1.f - gm)) * o + s_xn[idx];
    }
}

// ---------------------------------------------------------------------------
// Kernel 3 (NEW): z = y @ lin_w^T via tf32 mma.sync tensor cores
// M=512, N=3000, K=5120.  BM=128, BN=64, BK=32, 128 threads.
// Warp grid 2x2, warp tile 64x32 -> m16n8k8 frags: 4 (M) x 4 (N).
// smem tiles [row][36] (pad -> conflict-free fragment LDS).
// ---------------------------------------------------------------------------
#define K3_BM 128
#define K3_BN 64
#define K3_BK 32
#define K3_LD 36

__device__ __forceinline__ uint32_t f2tf32(float f) {
    uint32_t u;
    asm("cvt.rna.tf32.f32 %0, %1;" : "=r"(u) : "f"(f));
    return u;
}

__device__ __forceinline__ void mma_tf32(float* c, const uint32_t* a,
                                         const uint32_t* b) {
    asm volatile(
        "mma.sync.aligned.m16n8k8.row.col.f32.tf32.tf32.f32 "
        "{%0,%1,%2,%3}, {%4,%5,%6,%7}, {%8,%9}, {%0,%1,%2,%3};\n"
        : "+f"(c[0]), "+f"(c[1]), "+f"(c[2]), "+f"(c[3])
        : "r"(a[0]), "r"(a[1]), "r"(a[2]), "r"(a[3]),
          "r"(b[0]), "r"(b[1]));
}

__global__ __launch_bounds__(128) void k3_tf32(
    const float* __restrict__ lin_w, const float* __restrict__ lin_b,
    const float* __restrict__ og_p, const float* __restrict__ ob_p,
    float* __restrict__ out)
{
    __shared__ uint32_t As[K3_BM][K3_LD];   // 18432 B
    __shared__ uint32_t Bs[K3_BN][K3_LD];   //  9216 B

    const int t    = threadIdx.x;
    const int lane = t & 31;
    const int warp = t >> 5;
    const int wm   = warp >> 1;   // 0..1
    const int wn   = warp & 1;    // 0..1
    const int g    = lane >> 2;   // 0..7
    const int tg   = lane & 3;    // 0..3

    const int mbase = blockIdx.y * K3_BM;
    const int nbase = blockIdx.x * K3_BN;

    // A: thread t owns tile row t (32 floats = 8 float4 per BK chunk)
    const float* Ag = g_y + (size_t)(mbase + t) * DTRF;
    // B: thread t owns half of tile row t>>1
    const int   brow = nbase + (t >> 1);
    const bool  bval = (brow < DOUT);
    const float* Bg  = lin_w + (size_t)(bval ? brow : 0) * DTRF + (t & 1) * 16;

    float acc[4][4][4] = {};   // [mi][ni][c0..c3]

    // staging registers
    float4 a_st[8];
    float4 b_st[4];

    // preload k0 = 0
#pragma unroll
    for (int i = 0; i < 8; i++) a_st[i] = *(const float4*)&Ag[i * 4];
#pragma unroll
    for (int i = 0; i < 4; i++)
        b_st[i] = bval ? *(const float4*)&Bg[i * 4]
                       : make_float4(0.f, 0.f, 0.f, 0.f);

    for (int it = 0; it < DTRF / K3_BK; it++) {
        __syncthreads();
        // store staging -> smem (convert to tf32)
        {
            uint32_t* arow = &As[t][0];
#pragma unroll
            for (int i = 0; i < 8; i++) {
                arow[i * 4 + 0] = f2tf32(a_st[i].x);
                arow[i * 4 + 1] = f2tf32(a_st[i].y);
                arow[i * 4 + 2] = f2tf32(a_st[i].z);
                arow[i * 4 + 3] = f2tf32(a_st[i].w);
            }
            uint32_t* brw = &Bs[t >> 1][(t & 1) * 16];
#pragma unroll
            for (int i = 0; i < 4; i++) {
                brw[i * 4 + 0] = f2tf32(b_st[i].x);
                brw[i * 4 + 1] = f2tf32(b_st[i].y);
                brw[i * 4 + 2] = f2tf32(b_st[i].z);
                brw[i * 4 + 3] = f2tf32(b_st[i].w);
            }
        }
        __syncthreads();

        // prefetch next chunk (overlaps with mma below)
        if (it + 1 < DTRF / K3_BK) {
            const float* An = Ag + (it + 1) * K3_BK;
            const float* Bn = Bg + (it + 1) * K3_BK;
#pragma unroll
            for (int i = 0; i < 8; i++) a_st[i] = *(const float4*)&An[i * 4];
#pragma unroll
            for (int i = 0; i < 4; i++)
                b_st[i] = bval ? *(const float4*)&Bn[i * 4]
                               : make_float4(0.f, 0.f, 0.f, 0.f);
        }

        // compute: 4 k-steps of 8
#pragma unroll
        for (int ks = 0; ks < 4; ks++) {
            const int kk = ks * 8;
            uint32_t af[4][4];
#pragma unroll
            for (int mi = 0; mi < 4; mi++) {
                const int r = wm * 64 + mi * 16;
                af[mi][0] = As[r + g][kk + tg];
                af[mi][1] = As[r + g + 8][kk + tg];
                af[mi][2] = As[r + g][kk + tg + 4];
                af[mi][3] = As[r + g + 8][kk + tg + 4];
            }
            uint32_t bf[4][2];
#pragma unroll
            for (int ni = 0; ni < 4; ni++) {
                const int r = wn * 32 + ni * 8;
                bf[ni][0] = Bs[r + g][kk + tg];
                bf[ni][1] = Bs[r + g][kk + tg + 4];
            }
#pragma unroll
            for (int mi = 0; mi < 4; mi++)
#pragma unroll
                for (int ni = 0; ni < 4; ni++)
                    mma_tf32(acc[mi][ni], af[mi], bf[ni]);
        }
    }

    // epilogue
    const float og = og_p[0], ob = ob_p[0];
#pragma unroll
    for (int mi = 0; mi < 4; mi++) {
        const int m0 = mbase + wm * 64 + mi * 16 + g;
#pragma unroll
        for (int ni = 0; ni < 4; ni++) {
            const int n0 = nbase + wn * 32 + ni * 8 + tg * 2;
            if (n0 + 1 < DOUT) {
                const float lb0 = lin_b[n0], lb1 = lin_b[n0 + 1];
                out[(size_t)m0 * DOUT + n0]           = (acc[mi][ni][0] + lb0) * og + ob;
                out[(size_t)m0 * DOUT + n0 + 1]       = (acc[mi][ni][1] + lb1) * og + ob;
                out[(size_t)(m0 + 8) * DOUT + n0]     = (acc[mi][ni][2] + lb0) * og + ob;
                out[(size_t)(m0 + 8) * DOUT + n0 + 1] = (acc[mi][ni][3] + lb1) * og + ob;
            } else if (n0 < DOUT) {
                const float lb0 = lin_b[n0];
                out[(size_t)m0 * DOUT + n0]       = (acc[mi][ni][0] + lb0) * og + ob;
                out[(size_t)(m0 + 8) * DOUT + n0] = (acc[mi][ni][2] + lb0) * og + ob;
            }
        }
    }
}

// ---------------------------------------------------------------------------
extern "C" void kernel_launch(void* const* d_in, const int* in_sizes, int n_in,
                              void* d_out, int out_size)
{
    const float* x         = (const float*)d_in[0];
    const float* stdv      = (const float*)d_in[1];
    const float* meanv     = (const float*)d_in[2];
    const float* mat       = (const float*)d_in[3];
    const float* ln_g      = (const float*)d_in[4];
    const float* ln_b      = (const float*)d_in[5];
    const float* wq        = (const float*)d_in[6];
    const float* bq        = (const float*)d_in[7];
    const float* wk        = (const float*)d_in[8];
    const float* bk        = (const float*)d_in[9];
    const float* wv        = (const float*)d_in[10];
    const float* bv        = (const float*)d_in[11];
    const float* bt_w      = (const float*)d_in[12];
    const float* bt_b      = (const float*)d_in[13];
    const float* bt_gain   = (const float*)d_in[14];
    const float* bt_bias   = (const float*)d_in[15];
    const float* sup_gamma = (const float*)d_in[16];
    const float* sup_beta  = (const float*)d_in[17];
    const float* lin_w     = (const float*)d_in[18];
    const float* lin_b     = (const float*)d_in[19];
    const float* out_gain  = (const float*)d_in[20];
    const float* out_bias  = (const float*)d_in[21];
    float* out = (float*)d_out;

    const size_t smem2 = 26688 * sizeof(float);
    cudaFuncSetAttribute(k2_block, cudaFuncAttributeMaxDynamicSharedMemorySize,
                         (int)smem2);

    k1_clgemm<<<dim3(40, 16), 256>>>(x, stdv, meanv, mat);
    k2_block<<<512, 640, smem2>>>(ln_g, ln_b, wq, bq, wk, bk, wv, bv,
                                  bt_w, bt_b, bt_gain, bt_bias,
                                  sup_gamma, sup_beta);
    k3_tf32<<<dim3((DOUT + K3_BN - 1) / K3_BN, B_SZ / K3_BM), 128>>>(
        lin_w, lin_b, out_gain, out_bias, out);
}

// round 3
// speedup vs baseline: 1.9803x; 1.6213x over previous
#include <cuda_runtime.h>
#include <math.h>
#include <stdint.h>

// Problem constants
#define B_SZ  512
#define DIN   64
#define DCL   4998
#define DTRF  5120
#define PADN  61
#define PP    32
#define EE    160
#define DOUT  3000
#define M2    (B_SZ * PP)          // 16384 rows of 160

// Global scratch
__device__ float g_cl[B_SZ * DCL];
__device__ float g_xn[M2 * EE];
__device__ float g_q [M2 * EE];
__device__ float g_k [M2 * EE];
__device__ float g_v [M2 * EE];
__device__ float g_h [M2 * EE];
__device__ float g_y [M2 * EE];

// ---------------------------------------------------------------------------
// tf32 helpers
// ---------------------------------------------------------------------------
__device__ __forceinline__ uint32_t f2tf32(float f) {
    uint32_t u;
    asm("cvt.rna.tf32.f32 %0, %1;" : "=r"(u) : "f"(f));
    return u;
}
__device__ __forceinline__ void mma_tf32(float* c, const uint32_t* a,
                                         const uint32_t* b) {
    asm volatile(
        "mma.sync.aligned.m16n8k8.row.col.f32.tf32.tf32.f32 "
        "{%0,%1,%2,%3}, {%4,%5,%6,%7}, {%8,%9}, {%0,%1,%2,%3};\n"
        : "+f"(c[0]), "+f"(c[1]), "+f"(c[2]), "+f"(c[3])
        : "r"(a[0]), "r"(a[1]), "r"(a[2]), "r"(a[3]),
          "r"(b[0]), "r"(b[1]));
}

// ---------------------------------------------------------------------------
// Kernel 1: cl = (x*std + mean) @ mat     [512,64]@[64,4998] -> g_cl
// ---------------------------------------------------------------------------
__global__ __launch_bounds__(256) void k1_clgemm(
    const float* __restrict__ x, const float* __restrict__ stdv,
    const float* __restrict__ meanv, const float* __restrict__ mat)
{
    __shared__ float u_s[32 * 64];
    const int rbase = blockIdx.y * 32;
    const int cbase = blockIdx.x * 128;
    const int tid = threadIdx.x;

    for (int idx = tid; idx < 32 * 64; idx += 256) {
        int r = idx >> 6, k = idx & 63;
        u_s[idx] = x[(rbase + r) * DIN + k] * stdv[k] + meanv[k];
    }
    __syncthreads();

    const int ty = tid >> 5;
    const int tx = tid & 31;
    int   c[4];  bool cv[4];
#pragma unroll
    for (int j = 0; j < 4; j++) { c[j] = cbase + tx + 32 * j; cv[j] = (c[j] < DCL); }

    float acc[4][4] = {};
#pragma unroll 4
    for (int k = 0; k < 64; k++) {
        float a[4], b[4];
#pragma unroll
        for (int i = 0; i < 4; i++) a[i] = u_s[(ty + 8 * i) * 64 + k];
#pragma unroll
        for (int j = 0; j < 4; j++) b[j] = cv[j] ? mat[k * DCL + c[j]] : 0.f;
#pragma unroll
        for (int i = 0; i < 4; i++)
#pragma unroll
            for (int j = 0; j < 4; j++)
                acc[i][j] += a[i] * b[j];
    }
#pragma unroll
    for (int i = 0; i < 4; i++) {
        int row = rbase + ty + 8 * i;
#pragma unroll
        for (int j = 0; j < 4; j++)
            if (cv[j]) g_cl[row * DCL + c[j]] = acc[i][j];
    }
}

// ---------------------------------------------------------------------------
// Kernel 2a: LayerNorm of padded cl -> g_xn [512 x 5120]
// ---------------------------------------------------------------------------
__global__ __launch_bounds__(256) void k2a_ln(
    const float* __restrict__ ln_g, const float* __restrict__ ln_b)
{
    __shared__ float red[64];
    const int b = blockIdx.x;
    const int t = threadIdx.x;
    const float* clrow = g_cl + (size_t)b * DCL;

    float lsum = 0.f, lsq = 0.f;
    for (int i = t; i < DCL; i += 256) {
        float v = clrow[i];
        lsum += v; lsq += v * v;
    }
#pragma unroll
    for (int o = 16; o > 0; o >>= 1) {
        lsum += __shfl_xor_sync(~0u, lsum, o);
        lsq  += __shfl_xor_sync(~0u, lsq,  o);
    }
    const int warp = t >> 5, lane = t & 31;
    if (lane == 0) { red[warp] = lsum; red[32 + warp] = lsq; }
    __syncthreads();
    if (warp == 0) {
        float a  = (lane < 8) ? red[lane]      : 0.f;
        float c2 = (lane < 8) ? red[32 + lane] : 0.f;
#pragma unroll
        for (int o = 4; o > 0; o >>= 1) {
            a  += __shfl_xor_sync(~0u, a,  o);
            c2 += __shfl_xor_sync(~0u, c2, o);
        }
        if (lane == 0) {
            float mu  = a / (float)DTRF;
            float var = c2 / (float)DTRF - mu * mu;
            red[0] = mu;
            red[1] = rsqrtf(var + 1e-5f);
        }
    }
    __syncthreads();
    const float mu = red[0], rstd = red[1];
    float* xnrow = g_xn + (size_t)b * DTRF;
    for (int d = t; d < DTRF; d += 256) {
        float v = (d >= PADN && d < PADN + DCL) ? clrow[d - PADN] : 0.f;
        xnrow[d] = (v - mu) * rstd * ln_g[d] + ln_b[d];
    }
}

// ---------------------------------------------------------------------------
// Kernel 2b: fused QKV GEMM  [16384,160] @ w^T -> g_q, g_k, g_v
// 384 threads = 12 warps; warps 0-3 -> Q, 4-7 -> K, 8-11 -> V.
// BM=64 rows per block (warp m16 tile each), full N=160, K chunks of 16.
// smem: As[64][164] tf32 (41984 B) + Bs[2][3][160][20] (76800 B)
// ---------------------------------------------------------------------------
__global__ __launch_bounds__(384) void k2b_qkv(
    const float* __restrict__ wq, const float* __restrict__ bq,
    const float* __restrict__ wk, const float* __restrict__ bk,
    const float* __restrict__ wv, const float* __restrict__ bv)
{
    extern __shared__ uint32_t sm2b[];
    uint32_t (*As)[164] = (uint32_t(*)[164])sm2b;                 // [64][164]
    uint32_t (*Bs)[3][160][20] =
        (uint32_t(*)[3][160][20])(sm2b + 64 * 164);               // [2][3][160][20]

    const int t    = threadIdx.x;
    const int lane = t & 31;
    const int warp = t >> 5;          // 0..11
    const int mat  = warp >> 2;       // 0..2
    const int wm   = warp & 3;        // 0..3 -> rows wm*16
    const int g    = lane >> 2;
    const int tg   = lane & 3;
    const int mb   = blockIdx.x * 64;

    const float* W[3]  = {wq, wk, wv};
    const float* BI[3] = {bq, bk, bv};
    float*       O[3]  = {g_q, g_k, g_v};

    // stage regs for first B chunk (1920 float4 per chunk / 384 = 5 each)
    float4 bst[5];
#pragma unroll
    for (int i = 0; i < 5; i++) {
        int idx = t + i * 384;
        int m = idx / 640, rem = idx % 640;
        int n = rem >> 2, c = rem & 3;
        bst[i] = *(const float4*)&W[m][n * EE + c * 4];
    }

    // load A tile (64 x 160) -> tf32 smem, STS.128
    for (int i = t; i < 2560; i += 384) {
        int r = i / 40, c4 = i % 40;
        float4 v = *(const float4*)&g_xn[(size_t)(mb + r) * EE + c4 * 4];
        uint4 u = make_uint4(f2tf32(v.x), f2tf32(v.y), f2tf32(v.z), f2tf32(v.w));
        *(uint4*)&As[r][c4 * 4] = u;
    }

    float acc[20][4] = {};
    for (int kc = 0; kc < 10; kc++) {
        const int buf = kc & 1;
        // store staged B -> smem
#pragma unroll
        for (int i = 0; i < 5; i++) {
            int idx = t + i * 384;
            int m = idx / 640, rem = idx % 640;
            int n = rem >> 2, c = rem & 3;
            uint4 u = make_uint4(f2tf32(bst[i].x), f2tf32(bst[i].y),
                                 f2tf32(bst[i].z), f2tf32(bst[i].w));
            *(uint4*)&Bs[buf][m][n][c * 4] = u;
        }
        __syncthreads();
        // prefetch next chunk
        if (kc + 1 < 10) {
            int k0 = (kc + 1) * 16;
#pragma unroll
            for (int i = 0; i < 5; i++) {
                int idx = t + i * 384;
                int m = idx / 640, rem = idx % 640;
                int n = rem >> 2, c = rem & 3;
                bst[i] = *(const float4*)&W[m][n * EE + k0 + c * 4];
            }
        }
        // compute 2 k8 steps
#pragma unroll
        for (int ks = 0; ks < 2; ks++) {
            const int kA = kc * 16 + ks * 8;
            uint32_t af[4];
            af[0] = As[wm * 16 + g][kA + tg];
            af[1] = As[wm * 16 + g + 8][kA + tg];
            af[2] = As[wm * 16 + g][kA + tg + 4];
            af[3] = As[wm * 16 + g + 8][kA + tg + 4];
#pragma unroll
            for (int n8 = 0; n8 < 20; n8++) {
                uint32_t bf[2];
                bf[0] = Bs[buf][mat][n8 * 8 + g][ks * 8 + tg];
                bf[1] = Bs[buf][mat][n8 * 8 + g][ks * 8 + tg + 4];
                mma_tf32(acc[n8], af, bf);
            }
        }
    }

    // epilogue: + bias, store
    const float* bias = BI[mat];
    float* out = O[mat];
    const int r0 = mb + wm * 16 + g;
#pragma unroll
    for (int n8 = 0; n8 < 20; n8++) {
        const int n0 = n8 * 8 + tg * 2;
        const float b0 = bias[n0], b1 = bias[n0 + 1];
        out[(size_t)r0 * EE + n0]           = acc[n8][0] + b0;
        out[(size_t)r0 * EE + n0 + 1]       = acc[n8][1] + b1;
        out[(size_t)(r0 + 8) * EE + n0]     = acc[n8][2] + b0;
        out[(size_t)(r0 + 8) * EE + n0 + 1] = acc[n8][3] + b1;
    }
}

// ---------------------------------------------------------------------------
// Kernel 2c: attention per batch row. 512 blocks x 128 threads.
// smem: q[32][164] | kt[160][36] | v[32][164] | att[32][33]
// ---------------------------------------------------------------------------
__global__ __launch_bounds__(128) void k2c_attn()
{
    extern __shared__ float sm2c[];
    float (*sq)[164]  = (float(*)[164])sm2c;
    float (*kt)[36]   = (float(*)[36]) (sm2c + 32 * 164);
    float (*sv)[164]  = (float(*)[164])(sm2c + 32 * 164 + 160 * 36);
    float (*att)[33]  = (float(*)[33]) (sm2c + 32 * 164 + 160 * 36 + 32 * 164);

    const int b = blockIdx.x;
    const int t = threadIdx.x;
    const float inv_scale = rsqrtf(160.0f);
    const size_t base = (size_t)b * PP * EE;

    // load Q (pre-scaled), K transposed, V
    for (int i = t; i < PP * EE; i += 128) {
        int p = i / EE, e = i % EE;
        sq[p][e] = g_q[base + i] * inv_scale;
        kt[e][p] = g_k[base + i];
        sv[p][e] = g_v[base + i];
    }
    __syncthreads();

    // dot[p][q] : 256 (p,q4) entries, 2 per thread
#pragma unroll
    for (int i = 0; i < 2; i++) {
        int idx = t + i * 128;
        int p = idx >> 3, q4 = idx & 7;
        float4 a = make_float4(0.f, 0.f, 0.f, 0.f);
        for (int e = 0; e < EE; e++) {
            float qv = sq[p][e];
            float4 kv = *(const float4*)&kt[e][q4 * 4];
            a.x += qv * kv.x; a.y += qv * kv.y;
            a.z += qv * kv.z; a.w += qv * kv.w;
        }
        att[p][q4 * 4 + 0] = a.x; att[p][q4 * 4 + 1] = a.y;
        att[p][q4 * 4 + 2] = a.z; att[p][q4 * 4 + 3] = a.w;
    }
    __syncthreads();

    // softmax over p (dim=1), one thread per column q
    if (t < 32) {
        int q = t;
        float m = -1e30f;
#pragma unroll
        for (int p = 0; p < 32; p++) m = fmaxf(m, att[p][q]);
        float ssum = 0.f;
#pragma unroll
        for (int p = 0; p < 32; p++) {
            float e = __expf(att[p][q] - m);
            att[p][q] = e;
            ssum += e;
        }
        float inv = 1.f / ssum;
#pragma unroll
        for (int p = 0; p < 32; p++) att[p][q] *= inv;
    }
    __syncthreads();

    // h = att @ V + cl_padded  -> g_h
    const float* clrow = g_cl + (size_t)b * DCL;
#pragma unroll
    for (int i = 0; i < 10; i++) {
        int idx = t + i * 128;           // (p, e4)
        int p = idx / 40, e4 = idx % 40;
        float4 a = make_float4(0.f, 0.f, 0.f, 0.f);
#pragma unroll
        for (int q = 0; q < 32; q++) {
            float w = att[p][q];
            float4 vv = *(const float4*)&sv[q][e4 * 4];
            a.x += w * vv.x; a.y += w * vv.y;
            a.z += w * vv.z; a.w += w * vv.w;
        }
        int d = p * EE + e4 * 4;
        float cl0 = (d + 0 >= PADN && d + 0 < PADN + DCL) ? clrow[d + 0 - PADN] : 0.f;
        float cl1 = (d + 1 >= PADN && d + 1 < PADN + DCL) ? clrow[d + 1 - PADN] : 0.f;
        float cl2 = (d + 2 >= PADN && d + 2 < PADN + DCL) ? clrow[d + 2 - PADN] : 0.f;
        float cl3 = (d + 3 >= PADN && d + 3 < PADN + DCL) ? clrow[d + 3 - PADN] : 0.f;
        float4 hv = make_float4(a.x + cl0, a.y + cl1, a.z + cl2, a.w + cl3);
        *(float4*)&g_h[base + d] = hv;
    }
}

// ---------------------------------------------------------------------------
// Kernel 2d: BT GEMM + Supact + residual.
// o = (h*btg+btb) @ bt_w + bt_b ; y = supact(o) + h -> g_y
// BM=128, 256 threads (8 warps, m16 each), full N=160, K chunks of 16.
// smem: As[128][164] (83968 B) + Bs[2][16][168] (21504 B)  [k][n] layout
// ---------------------------------------------------------------------------
__global__ __launch_bounds__(256) void k2d_bt(
    const float* __restrict__ bt_w, const float* __restrict__ bt_b,
    const float* __restrict__ bt_gain, const float* __restrict__ bt_bias,
    const float* __restrict__ sup_gamma, const float* __restrict__ sup_beta)
{
    extern __shared__ uint32_t sm2d[];
    uint32_t (*As)[164]     = (uint32_t(*)[164])sm2d;             // [128][164]
    uint32_t (*Bs)[16][168] = (uint32_t(*)[16][168])(sm2d + 128 * 164);

    const int t    = threadIdx.x;
    const int lane = t & 31;
    const int warp = t >> 5;          // 0..7 -> rows warp*16
    const int g    = lane >> 2;
    const int tg   = lane & 3;
    const int mb   = blockIdx.x * 128;
    const float btg = bt_gain[0], btb = bt_bias[0];

    // stage regs for first B chunk (16 x 160 = 640 float4 / 256 -> 3 w/ guard)
    float4 bst[3];
#pragma unroll
    for (int i = 0; i < 3; i++) {
        int idx = t + i * 256;
        if (idx < 640) {
            int e = idx / 40, f4 = idx % 40;
            bst[i] = *(const float4*)&bt_w[(size_t)e * EE + f4 * 4];
        }
    }

    // load A tile: x2 = h*btg + btb -> tf32 smem (128 x 160 = 5120 float4)
    for (int i = t; i < 5120; i += 256) {
        int r = i / 40, c4 = i % 40;
        float4 v = *(const float4*)&g_h[(size_t)(mb + r) * EE + c4 * 4];
        uint4 u = make_uint4(f2tf32(v.x * btg + btb), f2tf32(v.y * btg + btb),
                             f2tf32(v.z * btg + btb), f2tf32(v.w * btg + btb));
        *(uint4*)&As[r][c4 * 4] = u;
    }

    float acc[20][4] = {};
    for (int kc = 0; kc < 10; kc++) {
        const int buf = kc & 1;
#pragma unroll
        for (int i = 0; i < 3; i++) {
            int idx = t + i * 256;
            if (idx < 640) {
                int e = idx / 40, f4 = idx % 40;
                uint4 u = make_uint4(f2tf32(bst[i].x), f2tf32(bst[i].y),
                                     f2tf32(bst[i].z), f2tf32(bst[i].w));
                *(uint4*)&Bs[buf][e][f4 * 4] = u;   // [k_local][n], STS.128
            }
        }
        __syncthreads();
        if (kc + 1 < 10) {
            int k0 = (kc + 1) * 16;
#pragma unroll
            for (int i = 0; i < 3; i++) {
                int idx = t + i * 256;
                if (idx < 640) {
                    int e = idx / 40, f4 = idx % 40;
                    bst[i] = *(const float4*)&bt_w[(size_t)(k0 + e) * EE + f4 * 4];
                }
            }
        }
#pragma unroll
        for (int ks = 0; ks < 2; ks++) {
            const int kA = kc * 16 + ks * 8;
            uint32_t af[4];
            af[0] = As[warp * 16 + g][kA + tg];
            af[1] = As[warp * 16 + g + 8][kA + tg];
            af[2] = As[warp * 16 + g][kA + tg + 4];
            af[3] = As[warp * 16 + g + 8][kA + tg + 4];
#pragma unroll
            for (int n8 = 0; n8 < 20; n8++) {
                uint32_t bf[2];
                bf[0] = Bs[buf][ks * 8 + tg][n8 * 8 + g];
                bf[1] = Bs[buf][ks * 8 + tg + 4][n8 * 8 + g];
                mma_tf32(acc[n8], af, bf);
            }
        }
    }

    // epilogue: bias + Supact + residual h
    const int r0 = mb + warp * 16 + g;
#pragma unroll
    for (int n8 = 0; n8 < 20; n8++) {
        const int n0 = n8 * 8 + tg * 2;
        const float bb0 = bt_b[n0], bb1 = bt_b[n0 + 1];
#pragma unroll
        for (int half = 0; half < 2; half++) {
            const int row = r0 + half * 8;
            const int gi0 = (row & 31) * EE + n0;
            float o0 = acc[n8][half * 2 + 0] + bb0;
            float o1 = acc[n8][half * 2 + 1] + bb1;
            float gm0 = sup_gamma[gi0],     gm1 = sup_gamma[gi0 + 1];
            float sb0 = sup_beta[gi0],      sb1 = sup_beta[gi0 + 1];
            float h0  = g_h[(size_t)row * EE + n0];
            float h1  = g_h[(size_t)row * EE + n0 + 1];
            float s0 = 1.f / (1.f + __expf(-sb0 * o0));
            float s1 = 1.f / (1.f + __expf(-sb1 * o1));
            g_y[(size_t)row * EE + n0]     = (gm0 + s0 * (1.f - gm0)) * o0 + h0;
            g_y[(size_t)row * EE + n0 + 1] = (gm1 + s1 * (1.f - gm1)) * o1 + h1;
        }
    }
}

// ---------------------------------------------------------------------------
// Kernel 3: z = y @ lin_w^T  (tf32 mma, double-buffered)
// M=512, N=3000, K=5120. BM=128, BN=64, BK=32, 256 threads (8 warps 4x2).
// ---------------------------------------------------------------------------
#define K3_BM 128
#define K3_BN 64
#define K3_BK 32
#define K3_LD 36

__global__ __launch_bounds__(256) void k3_tf32(
    const float* __restrict__ lin_w, const float* __restrict__ lin_b,
    const float* __restrict__ og_p, const float* __restrict__ ob_p,
    float* __restrict__ out)
{
    extern __shared__ uint32_t sm3[];
    uint32_t (*As)[K3_BM][K3_LD] = (uint32_t(*)[K3_BM][K3_LD])sm3;
    uint32_t (*Bs)[K3_BN][K3_LD] =
        (uint32_t(*)[K3_BN][K3_LD])(sm3 + 2 * K3_BM * K3_LD);

    const int t    = threadIdx.x;
    const int lane = t & 31;
    const int warp = t >> 5;
    const int wm   = warp >> 1;   // 0..3 -> rows wm*32
    const int wn   = warp & 1;    // 0..1 -> cols wn*32
    const int g    = lane >> 2;
    const int tg   = lane & 3;

    const int mbase = blockIdx.y * K3_BM;
    const int nbase = blockIdx.x * K3_BN;

    // A: thread t -> row t>>1, k-offset (t&1)*16 (4 float4)
    const int  ar = t >> 1, ak = (t & 1) * 16;
    const float* Ag = g_y + (size_t)(mbase + ar) * DTRF + ak;
    // B: thread t -> row t>>2, k-offset (t&3)*8 (2 float4)
    const int  br = t >> 2, bk = (t & 3) * 8;
    const int  brow = nbase + br;
    const bool bval = (brow < DOUT);
    const float* Bg = lin_w + (size_t)(bval ? brow : 0) * DTRF + bk;

    float acc[2][4][4] = {};
    float4 a_st[4], b_st[2];

#pragma unroll
    for (int i = 0; i < 4; i++) a_st[i] = *(const float4*)&Ag[i * 4];
#pragma unroll
    for (int i = 0; i < 2; i++)
        b_st[i] = bval ? *(const float4*)&Bg[i * 4]
                       : make_float4(0.f, 0.f, 0.f, 0.f);

    const int NIT = DTRF / K3_BK;   // 160
    for (int it = 0; it < NIT; it++) {
        const int buf = it & 1;
#pragma unroll
        for (int i = 0; i < 4; i++) {
            uint4 u = make_uint4(f2tf32(a_st[i].x), f2tf32(a_st[i].y),
                                 f2tf32(a_st[i].z), f2tf32(a_st[i].w));
            *(uint4*)&As[buf][ar][ak + i * 4] = u;
        }
#pragma unroll
        for (int i = 0; i < 2; i++) {
            uint4 u = make_uint4(f2tf32(b_st[i].x), f2tf32(b_st[i].y),
                                 f2tf32(b_st[i].z), f2tf32(b_st[i].w));
            *(uint4*)&Bs[buf][br][bk + i * 4] = u;
        }
        __syncthreads();

        if (it + 1 < NIT) {
            const float* An = Ag + (it + 1) * K3_BK;
            const float* Bn = Bg + (it + 1) * K3_BK;
#pragma unroll
            for (int i = 0; i < 4; i++) a_st[i] = *(const float4*)&An[i * 4];
#pragma unroll
            for (int i = 0; i < 2; i++)
                b_st[i] = bval ? *(const float4*)&Bn[i * 4]
                               : make_float4(0.f, 0.f, 0.f, 0.f);
        }

#pragma unroll
        for (int ks = 0; ks < 4; ks++) {
            const int kk = ks * 8;
            uint32_t af[2][4];
#pragma unroll
            for (int mi = 0; mi < 2; mi++) {
                const int r = wm * 32 + mi * 16;
                af[mi][0] = As[buf][r + g][kk + tg];
                af[mi][1] = As[buf][r + g + 8][kk + tg];
                af[mi][2] = As[buf][r + g][kk + tg + 4];
                af[mi][3] = As[buf][r + g + 8][kk + tg + 4];
            }
#pragma unroll
            for (int ni = 0; ni < 4; ni++) {
                uint32_t bf[2];
                const int r = wn * 32 + ni * 8;
                bf[0] = Bs[buf][r + g][kk + tg];
                bf[1] = Bs[buf][r + g][kk + tg + 4];
#pragma unroll
                for (int mi = 0; mi < 2; mi++)
                    mma_tf32(acc[mi][ni], af[mi], bf);
            }
        }
    }

    const float og = og_p[0], ob = ob_p[0];
#pragma unroll
    for (int mi = 0; mi < 2; mi++) {
        const int m0 = mbase + wm * 32 + mi * 16 + g;
#pragma unroll
        for (int ni = 0; ni < 4; ni++) {
            const int n0 = nbase + wn * 32 + ni * 8 + tg * 2;
            if (n0 + 1 < DOUT) {
                const float lb0 = lin_b[n0], lb1 = lin_b[n0 + 1];
                out[(size_t)m0 * DOUT + n0]           = (acc[mi][ni][0] + lb0) * og + ob;
                out[(size_t)m0 * DOUT + n0 + 1]       = (acc[mi][ni][1] + lb1) * og + ob;
                out[(size_t)(m0 + 8) * DOUT + n0]     = (acc[mi][ni][2] + lb0) * og + ob;
                out[(size_t)(m0 + 8) * DOUT + n0 + 1] = (acc[mi][ni][3] + lb1) * og + ob;
            } else if (n0 < DOUT) {
                const float lb0 = lin_b[n0];
                out[(size_t)m0 * DOUT + n0]       = (acc[mi][ni][0] + lb0) * og + ob;
                out[(size_t)(m0 + 8) * DOUT + n0] = (acc[mi][ni][2] + lb0) * og + ob;
            }
        }
    }
}

// ---------------------------------------------------------------------------
extern "C" void kernel_launch(void* const* d_in, const int* in_sizes, int n_in,
                              void* d_out, int out_size)
{
    const float* x         = (const float*)d_in[0];
    const float* stdv      = (const float*)d_in[1];
    const float* meanv     = (const float*)d_in[2];
    const float* mat       = (const float*)d_in[3];
    const float* ln_g      = (const float*)d_in[4];
    const float* ln_b      = (const float*)d_in[5];
    const float* wq        = (const float*)d_in[6];
    const float* bq        = (const float*)d_in[7];
    const float* wk        = (const float*)d_in[8];
    const float* bk        = (const float*)d_in[9];
    const float* wv        = (const float*)d_in[10];
    const float* bv        = (const float*)d_in[11];
    const float* bt_w      = (const float*)d_in[12];
    const float* bt_b      = (const float*)d_in[13];
    const float* bt_gain   = (const float*)d_in[14];
    const float* bt_bias   = (const float*)d_in[15];
    const float* sup_gamma = (const float*)d_in[16];
    const float* sup_beta  = (const float*)d_in[17];
    const float* lin_w     = (const float*)d_in[18];
    const float* lin_b     = (const float*)d_in[19];
    const float* out_gain  = (const float*)d_in[20];
    const float* out_bias  = (const float*)d_in[21];
    float* out = (float*)d_out;

    const int smem2b = (64 * 164 + 2 * 3 * 160 * 20) * 4;          // 118784
    const int smem2c = (32 * 164 + 160 * 36 + 32 * 164 + 32 * 33) * 4; // 69248
    const int smem2d = (128 * 164 + 2 * 16 * 168) * 4;             // 105472
    const int smem3  = (2 * K3_BM * K3_LD + 2 * K3_BN * K3_LD) * 4; // 55296

    cudaFuncSetAttribute(k2b_qkv, cudaFuncAttributeMaxDynamicSharedMemorySize, smem2b);
    cudaFuncSetAttribute(k2c_attn, cudaFuncAttributeMaxDynamicSharedMemorySize, smem2c);
    cudaFuncSetAttribute(k2d_bt,  cudaFuncAttributeMaxDynamicSharedMemorySize, smem2d);
    cudaFuncSetAttribute(k3_tf32, cudaFuncAttributeMaxDynamicSharedMemorySize, smem3);

    k1_clgemm<<<dim3(40, 16), 256>>>(x, stdv, meanv, mat);
    k2a_ln  <<<B_SZ, 256>>>(ln_g, ln_b);
    k2b_qkv <<<M2 / 64, 384, smem2b>>>(wq, bq, wk, bk, wv, bv);
    k2c_attn<<<B_SZ, 128, smem2c>>>();
    k2d_bt  <<<M2 / 128, 256, smem2d>>>(bt_w, bt_b, bt_gain, bt_bias,
                                        sup_gamma, sup_beta);
    k3_tf32 <<<dim3((DOUT + K3_BN - 1) / K3_BN, B_SZ / K3_BM), 256, smem3>>>(
        lin_w, lin_b, out_gain, out_bias, out);
}

// round 5
// speedup vs baseline: 2.0929x; 1.0569x over previous
#include <cuda_runtime.h>
#include <math.h>
#include <stdint.h>

// Problem constants
#define B_SZ  512
#define DIN   64
#define DCL   4998
#define DTRF  5120
#define PADN  61
#define PP    32
#define EE    160
#define DOUT  3000
#define M2    (B_SZ * PP)          // 16384 rows of 160

// Global scratch
__device__ float g_cl[B_SZ * DCL];
__device__ float g_xn[M2 * EE];
__device__ float g_q [M2 * EE];
__device__ float g_k [M2 * EE];
__device__ float g_v [M2 * EE];
__device__ float g_h [M2 * EE];
__device__ float g_y [M2 * EE];

// ---------------------------------------------------------------------------
// tf32 helpers (mma.sync path; tcgen05 is unavailable under this toolchain)
// ---------------------------------------------------------------------------
__device__ __forceinline__ uint32_t f2tf32(float f) {
    uint32_t u;
    asm("cvt.rna.tf32.f32 %0, %1;" : "=r"(u) : "f"(f));
    return u;
}
__device__ __forceinline__ void mma_tf32(float* c, const uint32_t* a,
                                         const uint32_t* b) {
    asm volatile(
        "mma.sync.aligned.m16n8k8.row.col.f32.tf32.tf32.f32 "
        "{%0,%1,%2,%3}, {%4,%5,%6,%7}, {%8,%9}, {%0,%1,%2,%3};\n"
        : "+f"(c[0]), "+f"(c[1]), "+f"(c[2]), "+f"(c[3])
        : "r"(a[0]), "r"(a[1]), "r"(a[2]), "r"(a[3]),
          "r"(b[0]), "r"(b[1]));
}

// ---------------------------------------------------------------------------
// Kernel 1: cl = (x*std + mean) @ mat   64x128 tile, 8x4 per thread
// ---------------------------------------------------------------------------
__global__ __launch_bounds__(256) void k1_clgemm(
    const float* __restrict__ x, const float* __restrict__ stdv,
    const float* __restrict__ meanv, const float* __restrict__ mat)
{
    __shared__ float u_s[64 * 64];
    const int rbase = blockIdx.y * 64;
    const int cbase = blockIdx.x * 128;
    const int tid = threadIdx.x;

    for (int idx = tid; idx < 64 * 64; idx += 256) {
        int r = idx >> 6, k = idx & 63;
        u_s[idx] = x[(rbase + r) * DIN + k] * stdv[k] + meanv[k];
    }
    __syncthreads();

    const int ty = tid >> 5;   // 0..7
    const int tx = tid & 31;
    int   c[4];  bool cv[4];
#pragma unroll
    for (int j = 0; j < 4; j++) { c[j] = cbase + tx + 32 * j; cv[j] = (c[j] < DCL); }

    float acc[8][4] = {};
#pragma unroll 4
    for (int k = 0; k < 64; k++) {
        float a[8], b[4];
#pragma unroll
        for (int i = 0; i < 8; i++) a[i] = u_s[(ty + 8 * i) * 64 + k];
#pragma unroll
        for (int j = 0; j < 4; j++) b[j] = cv[j] ? mat[k * DCL + c[j]] : 0.f;
#pragma unroll
        for (int i = 0; i < 8; i++)
#pragma unroll
            for (int j = 0; j < 4; j++)
                acc[i][j] += a[i] * b[j];
    }
#pragma unroll
    for (int i = 0; i < 8; i++) {
        int row = rbase + ty + 8 * i;
#pragma unroll
        for (int j = 0; j < 4; j++)
            if (cv[j]) g_cl[row * DCL + c[j]] = acc[i][j];
    }
}

// ---------------------------------------------------------------------------
// Kernel 2a: LayerNorm of padded cl -> g_xn [512 x 5120]
// ---------------------------------------------------------------------------
__global__ __launch_bounds__(256) void k2a_ln(
    const float* __restrict__ ln_g, const float* __restrict__ ln_b)
{
    __shared__ float red[64];
    const int b = blockIdx.x;
    const int t = threadIdx.x;
    const float* clrow = g_cl + (size_t)b * DCL;

    float lsum = 0.f, lsq = 0.f;
    for (int i = t; i < DCL; i += 256) {
        float v = clrow[i];
        lsum += v; lsq += v * v;
    }
#pragma unroll
    for (int o = 16; o > 0; o >>= 1) {
        lsum += __shfl_xor_sync(~0u, lsum, o);
        lsq  += __shfl_xor_sync(~0u, lsq,  o);
    }
    const int warp = t >> 5, lane = t & 31;
    if (lane == 0) { red[warp] = lsum; red[32 + warp] = lsq; }
    __syncthreads();
    if (warp == 0) {
        float a  = (lane < 8) ? red[lane]      : 0.f;
        float c2 = (lane < 8) ? red[32 + lane] : 0.f;
#pragma unroll
        for (int o = 4; o > 0; o >>= 1) {
            a  += __shfl_xor_sync(~0u, a,  o);
            c2 += __shfl_xor_sync(~0u, c2, o);
        }
        if (lane == 0) {
            float mu  = a / (float)DTRF;
            float var = c2 / (float)DTRF - mu * mu;
            red[0] = mu;
            red[1] = rsqrtf(var + 1e-5f);
        }
    }
    __syncthreads();
    const float mu = red[0], rstd = red[1];
    float* xnrow = g_xn + (size_t)b * DTRF;
    for (int d = t; d < DTRF; d += 256) {
        float v = (d >= PADN && d < PADN + DCL) ? clrow[d - PADN] : 0.f;
        xnrow[d] = (v - mu) * rstd * ln_g[d] + ln_b[d];
    }
}

// ---------------------------------------------------------------------------
// Kernel 2b: fused QKV GEMM  [16384,160] @ w^T -> g_q, g_k, g_v  (tf32 mma)
// ---------------------------------------------------------------------------
__global__ __launch_bounds__(384) void k2b_qkv(
    const float* __restrict__ wq, const float* __restrict__ bq,
    const float* __restrict__ wk, const float* __restrict__ bk,
    const float* __restrict__ wv, const float* __restrict__ bv)
{
    extern __shared__ uint32_t sm2b[];
    uint32_t (*As)[164] = (uint32_t(*)[164])sm2b;
    uint32_t (*Bs)[3][160][20] =
        (uint32_t(*)[3][160][20])(sm2b + 64 * 164);

    const int t    = threadIdx.x;
    const int lane = t & 31;
    const int warp = t >> 5;
    const int mat  = warp >> 2;
    const int wm   = warp & 3;
    const int g    = lane >> 2;
    const int tg   = lane & 3;
    const int mb   = blockIdx.x * 64;

    const float* W[3]  = {wq, wk, wv};
    const float* BI[3] = {bq, bk, bv};
    float*       O[3]  = {g_q, g_k, g_v};

    float4 bst[5];
#pragma unroll
    for (int i = 0; i < 5; i++) {
        int idx = t + i * 384;
        int m = idx / 640, rem = idx % 640;
        int n = rem >> 2, c = rem & 3;
        bst[i] = *(const float4*)&W[m][n * EE + c * 4];
    }

    for (int i = t; i < 2560; i += 384) {
        int r = i / 40, c4 = i % 40;
        float4 v = *(const float4*)&g_xn[(size_t)(mb + r) * EE + c4 * 4];
        uint4 u = make_uint4(f2tf32(v.x), f2tf32(v.y), f2tf32(v.z), f2tf32(v.w));
        *(uint4*)&As[r][c4 * 4] = u;
    }

    float acc[20][4] = {};
    for (int kc = 0; kc < 10; kc++) {
        const int buf = kc & 1;
#pragma unroll
        for (int i = 0; i < 5; i++) {
            int idx = t + i * 384;
            int m = idx / 640, rem = idx % 640;
            int n = rem >> 2, c = rem & 3;
            uint4 u = make_uint4(f2tf32(bst[i].x), f2tf32(bst[i].y),
                                 f2tf32(bst[i].z), f2tf32(bst[i].w));
            *(uint4*)&Bs[buf][m][n][c * 4] = u;
        }
        __syncthreads();
        if (kc + 1 < 10) {
            int k0 = (kc + 1) * 16;
#pragma unroll
            for (int i = 0; i < 5; i++) {
                int idx = t + i * 384;
                int m = idx / 640, rem = idx % 640;
                int n = rem >> 2, c = rem & 3;
                bst[i] = *(const float4*)&W[m][n * EE + k0 + c * 4];
            }
        }
#pragma unroll
        for (int ks = 0; ks < 2; ks++) {
            const int kA = kc * 16 + ks * 8;
            uint32_t af[4];
            af[0] = As[wm * 16 + g][kA + tg];
            af[1] = As[wm * 16 + g + 8][kA + tg];
            af[2] = As[wm * 16 + g][kA + tg + 4];
            af[3] = As[wm * 16 + g + 8][kA + tg + 4];
#pragma unroll
            for (int n8 = 0; n8 < 20; n8++) {
                uint32_t bf[2];
                bf[0] = Bs[buf][mat][n8 * 8 + g][ks * 8 + tg];
                bf[1] = Bs[buf][mat][n8 * 8 + g][ks * 8 + tg + 4];
                mma_tf32(acc[n8], af, bf);
            }
        }
    }

    const float* bias = BI[mat];
    float* out = O[mat];
    const int r0 = mb + wm * 16 + g;
#pragma unroll
    for (int n8 = 0; n8 < 20; n8++) {
        const int n0 = n8 * 8 + tg * 2;
        const float b0 = bias[n0], b1 = bias[n0 + 1];
        out[(size_t)r0 * EE + n0]           = acc[n8][0] + b0;
        out[(size_t)r0 * EE + n0 + 1]       = acc[n8][1] + b1;
        out[(size_t)(r0 + 8) * EE + n0]     = acc[n8][2] + b0;
        out[(size_t)(r0 + 8) * EE + n0 + 1] = acc[n8][3] + b1;
    }
}

// ---------------------------------------------------------------------------
// Kernel 2c: attention per batch row. 512 blocks x 256 threads.
// ---------------------------------------------------------------------------
__global__ __launch_bounds__(256) void k2c_attn()
{
    extern __shared__ float sm2c[];
    float (*sq)[164]  = (float(*)[164])sm2c;
    float (*kt)[36]   = (float(*)[36]) (sm2c + 32 * 164);
    float (*sv)[164]  = (float(*)[164])(sm2c + 32 * 164 + 160 * 36);
    float (*att)[33]  = (float(*)[33]) (sm2c + 32 * 164 + 160 * 36 + 32 * 164);

    const int b = blockIdx.x;
    const int t = threadIdx.x;
    const float inv_scale = rsqrtf(160.0f);
    const size_t base = (size_t)b * PP * EE;

    for (int i = t; i < PP * EE; i += 256) {
        int p = i / EE, e = i % EE;
        float qv = g_q[base + i];
        sq[p][e] = qv * inv_scale;
        kt[e][p] = g_k[base + i];
        sv[p][e] = g_v[base + i];
    }
    __syncthreads();

    // dot[p][q]: 256 (p,q4) entries, one per thread
    {
        int p = t >> 3, q4 = t & 7;
        float4 a = make_float4(0.f, 0.f, 0.f, 0.f);
#pragma unroll 4
        for (int e = 0; e < EE; e++) {
            float qv = sq[p][e];
            float4 kv = *(const float4*)&kt[e][q4 * 4];
            a.x += qv * kv.x; a.y += qv * kv.y;
            a.z += qv * kv.z; a.w += qv * kv.w;
        }
        att[p][q4 * 4 + 0] = a.x; att[p][q4 * 4 + 1] = a.y;
        att[p][q4 * 4 + 2] = a.z; att[p][q4 * 4 + 3] = a.w;
    }
    __syncthreads();

    if (t < 32) {
        int q = t;
        float m = -1e30f;
#pragma unroll
        for (int p = 0; p < 32; p++) m = fmaxf(m, att[p][q]);
        float ssum = 0.f;
#pragma unroll
        for (int p = 0; p < 32; p++) {
            float e = __expf(att[p][q] - m);
            att[p][q] = e;
            ssum += e;
        }
        float inv = 1.f / ssum;
#pragma unroll
        for (int p = 0; p < 32; p++) att[p][q] *= inv;
    }
    __syncthreads();

    const float* clrow = g_cl + (size_t)b * DCL;
#pragma unroll
    for (int i = 0; i < 5; i++) {
        int idx = t + i * 256;           // (p, e4)
        int p = idx / 40, e4 = idx % 40;
        float4 a = make_float4(0.f, 0.f, 0.f, 0.f);
#pragma unroll
        for (int q = 0; q < 32; q++) {
            float w = att[p][q];
            float4 vv = *(const float4*)&sv[q][e4 * 4];
            a.x += w * vv.x; a.y += w * vv.y;
            a.z += w * vv.z; a.w += w * vv.w;
        }
        int d = p * EE + e4 * 4;
        float cl0 = (d + 0 >= PADN && d + 0 < PADN + DCL) ? clrow[d + 0 - PADN] : 0.f;
        float cl1 = (d + 1 >= PADN && d + 1 < PADN + DCL) ? clrow[d + 1 - PADN] : 0.f;
        float cl2 = (d + 2 >= PADN && d + 2 < PADN + DCL) ? clrow[d + 2 - PADN] : 0.f;
        float cl3 = (d + 3 >= PADN && d + 3 < PADN + DCL) ? clrow[d + 3 - PADN] : 0.f;
        float4 hv = make_float4(a.x + cl0, a.y + cl1, a.z + cl2, a.w + cl3);
        *(float4*)&g_h[base + d] = hv;
    }
}

// ---------------------------------------------------------------------------
// Kernel 2d: BT GEMM + Supact + residual (tf32 mma)
// ---------------------------------------------------------------------------
__global__ __launch_bounds__(256) void k2d_bt(
    const float* __restrict__ bt_w, const float* __restrict__ bt_b,
    const float* __restrict__ bt_gain, const float* __restrict__ bt_bias,
    const float* __restrict__ sup_gamma, const float* __restrict__ sup_beta)
{
    extern __shared__ uint32_t sm2d[];
    uint32_t (*As)[164]     = (uint32_t(*)[164])sm2d;
    uint32_t (*Bs)[16][168] = (uint32_t(*)[16][168])(sm2d + 128 * 164);

    const int t    = threadIdx.x;
    const int lane = t & 31;
    const int warp = t >> 5;
    const int g    = lane >> 2;
    const int tg   = lane & 3;
    const int mb   = blockIdx.x * 128;
    const float btg = bt_gain[0], btb = bt_bias[0];

    float4 bst[3];
#pragma unroll
    for (int i = 0; i < 3; i++) {
        int idx = t + i * 256;
        if (idx < 640) {
            int e = idx / 40, f4 = idx % 40;
            bst[i] = *(const float4*)&bt_w[(size_t)e * EE + f4 * 4];
        }
    }

    for (int i = t; i < 5120; i += 256) {
        int r = i / 40, c4 = i % 40;
        float4 v = *(const float4*)&g_h[(size_t)(mb + r) * EE + c4 * 4];
        uint4 u = make_uint4(f2tf32(v.x * btg + btb), f2tf32(v.y * btg + btb),
                             f2tf32(v.z * btg + btb), f2tf32(v.w * btg + btb));
        *(uint4*)&As[r][c4 * 4] = u;
    }

    float acc[20][4] = {};
    for (int kc = 0; kc < 10; kc++) {
        const int buf = kc & 1;
#pragma unroll
        for (int i = 0; i < 3; i++) {
            int idx = t + i * 256;
            if (idx < 640) {
                int e = idx / 40, f4 = idx % 40;
                uint4 u = make_uint4(f2tf32(bst[i].x), f2tf32(bst[i].y),
                                     f2tf32(bst[i].z), f2tf32(bst[i].w));
                *(uint4*)&Bs[buf][e][f4 * 4] = u;
            }
        }
        __syncthreads();
        if (kc + 1 < 10) {
            int k0 = (kc + 1) * 16;
#pragma unroll
            for (int i = 0; i < 3; i++) {
                int idx = t + i * 256;
                if (idx < 640) {
                    int e = idx / 40, f4 = idx % 40;
                    bst[i] = *(const float4*)&bt_w[(size_t)(k0 + e) * EE + f4 * 4];
                }
            }
        }
#pragma unroll
        for (int ks = 0; ks < 2; ks++) {
            const int kA = kc * 16 + ks * 8;
            uint32_t af[4];
            af[0] = As[warp * 16 + g][kA + tg];
            af[1] = As[warp * 16 + g + 8][kA + tg];
            af[2] = As[warp * 16 + g][kA + tg + 4];
            af[3] = As[warp * 16 + g + 8][kA + tg + 4];
#pragma unroll
            for (int n8 = 0; n8 < 20; n8++) {
                uint32_t bf[2];
                bf[0] = Bs[buf][ks * 8 + tg][n8 * 8 + g];
                bf[1] = Bs[buf][ks * 8 + tg + 4][n8 * 8 + g];
                mma_tf32(acc[n8], af, bf);
            }
        }
    }

    const int r0 = mb + warp * 16 + g;
#pragma unroll
    for (int n8 = 0; n8 < 20; n8++) {
        const int n0 = n8 * 8 + tg * 2;
        const float bb0 = bt_b[n0], bb1 = bt_b[n0 + 1];
#pragma unroll
        for (int half = 0; half < 2; half++) {
            const int row = r0 + half * 8;
            const int gi0 = (row & 31) * EE + n0;
            float o0 = acc[n8][half * 2 + 0] + bb0;
            float o1 = acc[n8][half * 2 + 1] + bb1;
            float gm0 = sup_gamma[gi0],     gm1 = sup_gamma[gi0 + 1];
            float sb0 = sup_beta[gi0],      sb1 = sup_beta[gi0 + 1];
            float h0  = g_h[(size_t)row * EE + n0];
            float h1  = g_h[(size_t)row * EE + n0 + 1];
            float s0 = 1.f / (1.f + __expf(-sb0 * o0));
            float s1 = 1.f / (1.f + __expf(-sb1 * o1));
            g_y[(size_t)row * EE + n0]     = (gm0 + s0 * (1.f - gm0)) * o0 + h0;
            g_y[(size_t)row * EE + n0 + 1] = (gm1 + s1 * (1.f - gm1)) * o1 + h1;
        }
    }
}

// ---------------------------------------------------------------------------
// Kernel 3: z = y @ lin_w^T  (tf32 mma, small tiles, full chip coverage)
// M=512, N=3000, K=5120. BM=64, BN=64, BK=32, 128 threads (4 warps 2x2,
// warp tile 32x32). Grid (47,8)=376 CTAs. Double-buffered static smem 36.8KB.
// ---------------------------------------------------------------------------
#define K3_BM 64
#define K3_BN 64
#define K3_BK 32
#define K3_LD 36

__global__ __launch_bounds__(128) void k3_tf32(
    const float* __restrict__ lin_w, const float* __restrict__ lin_b,
    const float* __restrict__ og_p, const float* __restrict__ ob_p,
    float* __restrict__ out)
{
    __shared__ uint32_t As[2][K3_BM][K3_LD];   // 18432 B
    __shared__ uint32_t Bs[2][K3_BN][K3_LD];   // 18432 B

    const int t    = threadIdx.x;
    const int lane = t & 31;
    const int warp = t >> 5;
    const int wm   = warp >> 1;   // 0..1 -> rows wm*32
    const int wn   = warp & 1;    // 0..1 -> cols wn*32
    const int g    = lane >> 2;
    const int tg   = lane & 3;

    const int mbase = blockIdx.y * K3_BM;
    const int nbase = blockIdx.x * K3_BN;

    // loaders: thread t -> row t>>1 (0..63), k-offset (t&1)*16 (4 float4)
    const int  r  = t >> 1, kh = (t & 1) * 16;
    const float* Ag = g_y + (size_t)(mbase + r) * DTRF + kh;
    const int  brow = nbase + r;
    const bool bok  = (brow < DOUT);
    const float* Bg = lin_w + (size_t)(bok ? brow : 0) * DTRF + kh;

    float acc[2][4][4] = {};
    float4 a_st[4], b_st[4];

#pragma unroll
    for (int i = 0; i < 4; i++) {
        a_st[i] = *(const float4*)&Ag[i * 4];
        b_st[i] = bok ? *(const float4*)&Bg[i * 4]
                      : make_float4(0.f, 0.f, 0.f, 0.f);
    }

    const int NIT = DTRF / K3_BK;   // 160
    for (int it = 0; it < NIT; it++) {
        const int buf = it & 1;
#pragma unroll
        for (int i = 0; i < 4; i++) {
            uint4 ua = make_uint4(f2tf32(a_st[i].x), f2tf32(a_st[i].y),
                                  f2tf32(a_st[i].z), f2tf32(a_st[i].w));
            *(uint4*)&As[buf][r][kh + i * 4] = ua;
            uint4 ub = make_uint4(f2tf32(b_st[i].x), f2tf32(b_st[i].y),
                                  f2tf32(b_st[i].z), f2tf32(b_st[i].w));
            *(uint4*)&Bs[buf][r][kh + i * 4] = ub;
        }
        __syncthreads();

        if (it + 1 < NIT) {
            const float* An = Ag + (it + 1) * K3_BK;
            const float* Bn = Bg + (it + 1) * K3_BK;
#pragma unroll
            for (int i = 0; i < 4; i++) {
                a_st[i] = *(const float4*)&An[i * 4];
                b_st[i] = bok ? *(const float4*)&Bn[i * 4]
                              : make_float4(0.f, 0.f, 0.f, 0.f);
            }
        }

#pragma unroll
        for (int ks = 0; ks < 4; ks++) {
            const int kk = ks * 8;
            uint32_t af[2][4];
#pragma unroll
            for (int mi = 0; mi < 2; mi++) {
                const int rr = wm * 32 + mi * 16;
                af[mi][0] = As[buf][rr + g][kk + tg];
                af[mi][1] = As[buf][rr + g + 8][kk + tg];
                af[mi][2] = As[buf][rr + g][kk + tg + 4];
                af[mi][3] = As[buf][rr + g + 8][kk + tg + 4];
            }
#pragma unroll
            for (int ni = 0; ni < 4; ni++) {
                uint32_t bf[2];
                const int rr = wn * 32 + ni * 8;
                bf[0] = Bs[buf][rr + g][kk + tg];
                bf[1] = Bs[buf][rr + g][kk + tg + 4];
#pragma unroll
                for (int mi = 0; mi < 2; mi++)
                    mma_tf32(acc[mi][ni], af[mi], bf);
            }
        }
    }

    const float og = og_p[0], ob = ob_p[0];
#pragma unroll
    for (int mi = 0; mi < 2; mi++) {
        const int m0 = mbase + wm * 32 + mi * 16 + g;
#pragma unroll
        for (int ni = 0; ni < 4; ni++) {
            const int n0 = nbase + wn * 32 + ni * 8 + tg * 2;
            if (n0 + 1 < DOUT) {
                const float lb0 = lin_b[n0], lb1 = lin_b[n0 + 1];
                out[(size_t)m0 * DOUT + n0]           = (acc[mi][ni][0] + lb0) * og + ob;
                out[(size_t)m0 * DOUT + n0 + 1]       = (acc[mi][ni][1] + lb1) * og + ob;
                out[(size_t)(m0 + 8) * DOUT + n0]     = (acc[mi][ni][2] + lb0) * og + ob;
                out[(size_t)(m0 + 8) * DOUT + n0 + 1] = (acc[mi][ni][3] + lb1) * og + ob;
            } else if (n0 < DOUT) {
                const float lb0 = lin_b[n0];
                out[(size_t)m0 * DOUT + n0]       = (acc[mi][ni][0] + lb0) * og + ob;
                out[(size_t)(m0 + 8) * DOUT + n0] = (acc[mi][ni][2] + lb0) * og + ob;
            }
        }
    }
}

// ---------------------------------------------------------------------------
extern "C" void kernel_launch(void* const* d_in, const int* in_sizes, int n_in,
                              void* d_out, int out_size)
{
    const float* x         = (const float*)d_in[0];
    const float* stdv      = (const float*)d_in[1];
    const float* meanv     = (const float*)d_in[2];
    const float* mat       = (const float*)d_in[3];
    const float* ln_g      = (const float*)d_in[4];
    const float* ln_b      = (const float*)d_in[5];
    const float* wq        = (const float*)d_in[6];
    const float* bq        = (const float*)d_in[7];
    const float* wk        = (const float*)d_in[8];
    const float* bk        = (const float*)d_in[9];
    const float* wv        = (const float*)d_in[10];
    const float* bv        = (const float*)d_in[11];
    const float* bt_w      = (const float*)d_in[12];
    const float* bt_b      = (const float*)d_in[13];
    const float* bt_gain   = (const float*)d_in[14];
    const float* bt_bias   = (const float*)d_in[15];
    const float* sup_gamma = (const float*)d_in[16];
    const float* sup_beta  = (const float*)d_in[17];
    const float* lin_w     = (const float*)d_in[18];
    const float* lin_b     = (const float*)d_in[19];
    const float* out_gain  = (const float*)d_in[20];
    const float* out_bias  = (const float*)d_in[21];
    float* out = (float*)d_out;

    const int smem2b = (64 * 164 + 2 * 3 * 160 * 20) * 4;              // 118784
    const int smem2c = (32 * 164 + 160 * 36 + 32 * 164 + 32 * 33) * 4; // 69248
    const int smem2d = (128 * 164 + 2 * 16 * 168) * 4;                 // 105472

    cudaFuncSetAttribute(k2b_qkv, cudaFuncAttributeMaxDynamicSharedMemorySize, smem2b);
    cudaFuncSetAttribute(k2c_attn, cudaFuncAttributeMaxDynamicSharedMemorySize, smem2c);
    cudaFuncSetAttribute(k2d_bt,  cudaFuncAttributeMaxDynamicSharedMemorySize, smem2d);

    k1_clgemm<<<dim3(40, 8), 256>>>(x, stdv, meanv, mat);
    k2a_ln  <<<B_SZ, 256>>>(ln_g, ln_b);
    k2b_qkv <<<M2 / 64, 384, smem2b>>>(wq, bq, wk, bk, wv, bv);
    k2c_attn<<<B_SZ, 256, smem2c>>>();
    k2d_bt  <<<M2 / 128, 256, smem2d>>>(bt_w, bt_b, bt_gain, bt_bias,
                                        sup_gamma, sup_beta);
    k3_tf32 <<<dim3((DOUT + K3_BN - 1) / K3_BN, B_SZ / K3_BM), 128>>>(
        lin_w, lin_b, out_gain, out_bias, out);
}

// round 6
// speedup vs baseline: 2.4206x; 1.1566x over previous
#include <cuda_runtime.h>
#include <cuda_fp16.h>
#include <math.h>
#include <stdint.h>

// Problem constants
#define B_SZ  512
#define DIN   64
#define DCL   4998
#define DTRF  5120
#define PADN  61
#define PP    32
#define EE    160
#define DOUT  3000
#define M2    (B_SZ * PP)          // 16384 rows of 160

// Global scratch
__device__ float g_cl[B_SZ * DCL];
__device__ float g_xn[M2 * EE];
__device__ float g_q [M2 * EE];
__device__ float g_k [M2 * EE];
__device__ float g_v [M2 * EE];
__device__ float g_h [M2 * EE];
__device__ float g_y [M2 * EE];

// ---------------------------------------------------------------------------
// helpers
// ---------------------------------------------------------------------------
__device__ __forceinline__ uint32_t f2tf32(float f) {
    uint32_t u;
    asm("cvt.rna.tf32.f32 %0, %1;" : "=r"(u) : "f"(f));
    return u;
}
__device__ __forceinline__ void mma_tf32(float* c, const uint32_t* a,
                                         const uint32_t* b) {
    asm volatile(
        "mma.sync.aligned.m16n8k8.row.col.f32.tf32.tf32.f32 "
        "{%0,%1,%2,%3}, {%4,%5,%6,%7}, {%8,%9}, {%0,%1,%2,%3};\n"
        : "+f"(c[0]), "+f"(c[1]), "+f"(c[2]), "+f"(c[3])
        : "r"(a[0]), "r"(a[1]), "r"(a[2]), "r"(a[3]),
          "r"(b[0]), "r"(b[1]));
}
__device__ __forceinline__ uint32_t pack2h(float a, float b) {
    __half2 h = __floats2half2_rn(a, b);
    return *(uint32_t*)&h;
}
__device__ __forceinline__ void mma_f16(float* c, const uint32_t* a,
                                        uint32_t b0, uint32_t b1) {
    asm volatile(
        "mma.sync.aligned.m16n8k16.row.col.f32.f16.f16.f32 "
        "{%0,%1,%2,%3}, {%4,%5,%6,%7}, {%8,%9}, {%0,%1,%2,%3};\n"
        : "+f"(c[0]), "+f"(c[1]), "+f"(c[2]), "+f"(c[3])
        : "r"(a[0]), "r"(a[1]), "r"(a[2]), "r"(a[3]),
          "r"(b0), "r"(b1));
}
__device__ __forceinline__ void ldsm_x4(uint32_t& r0, uint32_t& r1,
                                        uint32_t& r2, uint32_t& r3,
                                        uint32_t addr) {
    asm volatile(
        "ldmatrix.sync.aligned.m8n8.x4.shared.b16 {%0,%1,%2,%3}, [%4];"
        : "=r"(r0), "=r"(r1), "=r"(r2), "=r"(r3) : "r"(addr));
}

// ---------------------------------------------------------------------------
// Kernel 1: cl = (x*std + mean) @ mat   64x128 tile, 8x4 per thread
// ---------------------------------------------------------------------------
__global__ __launch_bounds__(256) void k1_clgemm(
    const float* __restrict__ x, const float* __restrict__ stdv,
    const float* __restrict__ meanv, const float* __restrict__ mat)
{
    __shared__ float u_s[64 * 64];
    const int rbase = blockIdx.y * 64;
    const int cbase = blockIdx.x * 128;
    const int tid = threadIdx.x;

    for (int idx = tid; idx < 64 * 64; idx += 256) {
        int r = idx >> 6, k = idx & 63;
        u_s[idx] = x[(rbase + r) * DIN + k] * stdv[k] + meanv[k];
    }
    __syncthreads();

    const int ty = tid >> 5;
    const int tx = tid & 31;
    int   c[4];  bool cv[4];
#pragma unroll
    for (int j = 0; j < 4; j++) { c[j] = cbase + tx + 32 * j; cv[j] = (c[j] < DCL); }

    float acc[8][4] = {};
#pragma unroll 4
    for (int k = 0; k < 64; k++) {
        float a[8], b[4];
#pragma unroll
        for (int i = 0; i < 8; i++) a[i] = u_s[(ty + 8 * i) * 64 + k];
#pragma unroll
        for (int j = 0; j < 4; j++) b[j] = cv[j] ? mat[k * DCL + c[j]] : 0.f;
#pragma unroll
        for (int i = 0; i < 8; i++)
#pragma unroll
            for (int j = 0; j < 4; j++)
                acc[i][j] += a[i] * b[j];
    }
#pragma unroll
    for (int i = 0; i < 8; i++) {
        int row = rbase + ty + 8 * i;
#pragma unroll
        for (int j = 0; j < 4; j++)
            if (cv[j]) g_cl[row * DCL + c[j]] = acc[i][j];
    }
}

// ---------------------------------------------------------------------------
// Kernel 2a: LayerNorm of padded cl -> g_xn [512 x 5120]
// ---------------------------------------------------------------------------
__global__ __launch_bounds__(256) void k2a_ln(
    const float* __restrict__ ln_g, const float* __restrict__ ln_b)
{
    __shared__ float red[64];
    const int b = blockIdx.x;
    const int t = threadIdx.x;
    const float* clrow = g_cl + (size_t)b * DCL;

    float lsum = 0.f, lsq = 0.f;
    for (int i = t; i < DCL; i += 256) {
        float v = clrow[i];
        lsum += v; lsq += v * v;
    }
#pragma unroll
    for (int o = 16; o > 0; o >>= 1) {
        lsum += __shfl_xor_sync(~0u, lsum, o);
        lsq  += __shfl_xor_sync(~0u, lsq,  o);
    }
    const int warp = t >> 5, lane = t & 31;
    if (lane == 0) { red[warp] = lsum; red[32 + warp] = lsq; }
    __syncthreads();
    if (warp == 0) {
        float a  = (lane < 8) ? red[lane]      : 0.f;
        float c2 = (lane < 8) ? red[32 + lane] : 0.f;
#pragma unroll
        for (int o = 4; o > 0; o >>= 1) {
            a  += __shfl_xor_sync(~0u, a,  o);
            c2 += __shfl_xor_sync(~0u, c2, o);
        }
        if (lane == 0) {
            float mu  = a / (float)DTRF;
            float var = c2 / (float)DTRF - mu * mu;
            red[0] = mu;
            red[1] = rsqrtf(var + 1e-5f);
        }
    }
    __syncthreads();
    const float mu = red[0], rstd = red[1];
    float* xnrow = g_xn + (size_t)b * DTRF;
    for (int d = t; d < DTRF; d += 256) {
        float v = (d >= PADN && d < PADN + DCL) ? clrow[d - PADN] : 0.f;
        xnrow[d] = (v - mu) * rstd * ln_g[d] + ln_b[d];
    }
}

// ---------------------------------------------------------------------------
// Kernel 2b: fused QKV GEMM  [16384,160] @ w^T -> g_q, g_k, g_v  (tf32 mma)
// single-buffered Bs (smem 80KB -> 2 CTAs/SM)
// ---------------------------------------------------------------------------
__global__ __launch_bounds__(384) void k2b_qkv(
    const float* __restrict__ wq, const float* __restrict__ bq,
    const float* __restrict__ wk, const float* __restrict__ bk,
    const float* __restrict__ wv, const float* __restrict__ bv)
{
    extern __shared__ uint32_t sm2b[];
    uint32_t (*As)[164] = (uint32_t(*)[164])sm2b;                 // [64][164]
    uint32_t (*Bs)[160][20] = (uint32_t(*)[160][20])(sm2b + 64 * 164); // [3][160][20]

    const int t    = threadIdx.x;
    const int lane = t & 31;
    const int warp = t >> 5;
    const int mat  = warp >> 2;
    const int wm   = warp & 3;
    const int g    = lane >> 2;
    const int tg   = lane & 3;
    const int mb   = blockIdx.x * 64;

    const float* W[3]  = {wq, wk, wv};
    const float* BI[3] = {bq, bk, bv};
    float*       O[3]  = {g_q, g_k, g_v};

    float4 bst[5];
#pragma unroll
    for (int i = 0; i < 5; i++) {
        int idx = t + i * 384;
        int m = idx / 640, rem = idx % 640;
        int n = rem >> 2, c = rem & 3;
        bst[i] = *(const float4*)&W[m][n * EE + c * 4];
    }

    for (int i = t; i < 2560; i += 384) {
        int r = i / 40, c4 = i % 40;
        float4 v = *(const float4*)&g_xn[(size_t)(mb + r) * EE + c4 * 4];
        uint4 u = make_uint4(f2tf32(v.x), f2tf32(v.y), f2tf32(v.z), f2tf32(v.w));
        *(uint4*)&As[r][c4 * 4] = u;
    }

    float acc[20][4] = {};
    for (int kc = 0; kc < 10; kc++) {
        if (kc) __syncthreads();   // prev compute done before overwrite
#pragma unroll
        for (int i = 0; i < 5; i++) {
            int idx = t + i * 384;
            int m = idx / 640, rem = idx % 640;
            int n = rem >> 2, c = rem & 3;
            uint4 u = make_uint4(f2tf32(bst[i].x), f2tf32(bst[i].y),
                                 f2tf32(bst[i].z), f2tf32(bst[i].w));
            *(uint4*)&Bs[m][n][c * 4] = u;
        }
        __syncthreads();
        if (kc + 1 < 10) {
            int k0 = (kc + 1) * 16;
#pragma unroll
            for (int i = 0; i < 5; i++) {
                int idx = t + i * 384;
                int m = idx / 640, rem = idx % 640;
                int n = rem >> 2, c = rem & 3;
                bst[i] = *(const float4*)&W[m][n * EE + k0 + c * 4];
            }
        }
#pragma unroll
        for (int ks = 0; ks < 2; ks++) {
            const int kA = kc * 16 + ks * 8;
            uint32_t af[4];
            af[0] = As[wm * 16 + g][kA + tg];
            af[1] = As[wm * 16 + g + 8][kA + tg];
            af[2] = As[wm * 16 + g][kA + tg + 4];
            af[3] = As[wm * 16 + g + 8][kA + tg + 4];
#pragma unroll
            for (int n8 = 0; n8 < 20; n8++) {
                uint32_t bf[2];
                bf[0] = Bs[mat][n8 * 8 + g][ks * 8 + tg];
                bf[1] = Bs[mat][n8 * 8 + g][ks * 8 + tg + 4];
                mma_tf32(acc[n8], af, bf);
            }
        }
    }

    const float* bias = BI[mat];
    float* out = O[mat];
    const int r0 = mb + wm * 16 + g;
#pragma unroll
    for (int n8 = 0; n8 < 20; n8++) {
        const int n0 = n8 * 8 + tg * 2;
        const float b0 = bias[n0], b1 = bias[n0 + 1];
        out[(size_t)r0 * EE + n0]           = acc[n8][0] + b0;
        out[(size_t)r0 * EE + n0 + 1]       = acc[n8][1] + b1;
        out[(size_t)(r0 + 8) * EE + n0]     = acc[n8][2] + b0;
        out[(size_t)(r0 + 8) * EE + n0 + 1] = acc[n8][3] + b1;
    }
}

// ---------------------------------------------------------------------------
// Kernel 2c: attention per batch row. 512 blocks x 128 threads.
// Conflict-free layout: rows padded to 165 floats (stride ≡ 5 mod 32).
// ---------------------------------------------------------------------------
#define AT_LD 165
__global__ __launch_bounds__(128) void k2c_attn()
{
    extern __shared__ float sm2c[];
    float (*sq)[AT_LD] = (float(*)[AT_LD])sm2c;
    float (*sk)[AT_LD] = (float(*)[AT_LD])(sm2c + 32 * AT_LD);
    float (*sv)[AT_LD] = (float(*)[AT_LD])(sm2c + 64 * AT_LD);
    float (*att)[33]   = (float(*)[33])  (sm2c + 96 * AT_LD);

    const int b = blockIdx.x;
    const int t = threadIdx.x;
    const int warp = t >> 5, lane = t & 31;
    const float inv_scale = rsqrtf(160.0f);
    const size_t base = (size_t)b * PP * EE;

    // load row-major (coalesced LDG, conflict-free STS)
    for (int i = t; i < PP * EE; i += 128) {
        int p = i / EE, e = i % EE;
        sq[p][e] = g_q[base + i] * inv_scale;
        sk[p][e] = g_k[base + i];
        sv[p][e] = g_v[base + i];
    }
    __syncthreads();

    // dot[p][q]: warp-uniform p (broadcast), q = lane (stride-165 conflict-free)
#pragma unroll
    for (int pass = 0; pass < 8; pass++) {
        const int p = pass * 4 + warp;
        float acc = 0.f;
#pragma unroll 4
        for (int e = 0; e < EE; e++)
            acc += sq[p][e] * sk[lane][e];
        att[p][lane] = acc;
    }
    __syncthreads();

    // softmax over p (dim=1), one thread per column q
    if (t < 32) {
        int q = t;
        float m = -1e30f;
#pragma unroll
        for (int p = 0; p < 32; p++) m = fmaxf(m, att[p][q]);
        float ssum = 0.f;
#pragma unroll
        for (int p = 0; p < 32; p++) {
            float e = __expf(att[p][q] - m);
            att[p][q] = e;
            ssum += e;
        }
        float inv = 1.f / ssum;
#pragma unroll
        for (int p = 0; p < 32; p++) att[p][q] *= inv;
    }
    __syncthreads();

    // h = att @ V + cl_padded  -> g_h
    const float* clrow = g_cl + (size_t)b * DCL;
#pragma unroll 2
    for (int j = 0; j < 40; j++) {
        int idx = t + j * 128;         // = p*160 + e
        int p = idx / EE, e = idx % EE;
        float acc = 0.f;
#pragma unroll
        for (int q = 0; q < 32; q++)
            acc += att[p][q] * sv[q][e];
        float cl = (idx >= PADN && idx < PADN + DCL) ? clrow[idx - PADN] : 0.f;
        g_h[base + idx] = acc + cl;
    }
}

// ---------------------------------------------------------------------------
// Kernel 2d: BT GEMM + Supact + residual (tf32 mma)
// ---------------------------------------------------------------------------
__global__ __launch_bounds__(256) void k2d_bt(
    const float* __restrict__ bt_w, const float* __restrict__ bt_b,
    const float* __restrict__ bt_gain, const float* __restrict__ bt_bias,
    const float* __restrict__ sup_gamma, const float* __restrict__ sup_beta)
{
    extern __shared__ uint32_t sm2d[];
    uint32_t (*As)[164]     = (uint32_t(*)[164])sm2d;
    uint32_t (*Bs)[16][168] = (uint32_t(*)[16][168])(sm2d + 128 * 164);

    const int t    = threadIdx.x;
    const int lane = t & 31;
    const int warp = t >> 5;
    const int g    = lane >> 2;
    const int tg   = lane & 3;
    const int mb   = blockIdx.x * 128;
    const float btg = bt_gain[0], btb = bt_bias[0];

    float4 bst[3];
#pragma unroll
    for (int i = 0; i < 3; i++) {
        int idx = t + i * 256;
        if (idx < 640) {
            int e = idx / 40, f4 = idx % 40;
            bst[i] = *(const float4*)&bt_w[(size_t)e * EE + f4 * 4];
        }
    }

    for (int i = t; i < 5120; i += 256) {
        int r = i / 40, c4 = i % 40;
        float4 v = *(const float4*)&g_h[(size_t)(mb + r) * EE + c4 * 4];
        uint4 u = make_uint4(f2tf32(v.x * btg + btb), f2tf32(v.y * btg + btb),
                             f2tf32(v.z * btg + btb), f2tf32(v.w * btg + btb));
        *(uint4*)&As[r][c4 * 4] = u;
    }

    float acc[20][4] = {};
    for (int kc = 0; kc < 10; kc++) {
        const int buf = kc & 1;
#pragma unroll
        for (int i = 0; i < 3; i++) {
            int idx = t + i * 256;
            if (idx < 640) {
                int e = idx / 40, f4 = idx % 40;
                uint4 u = make_uint4(f2tf32(bst[i].x), f2tf32(bst[i].y),
                                     f2tf32(bst[i].z), f2tf32(bst[i].w));
                *(uint4*)&Bs[buf][e][f4 * 4] = u;
            }
        }
        __syncthreads();
        if (kc + 1 < 10) {
            int k0 = (kc + 1) * 16;
#pragma unroll
            for (int i = 0; i < 3; i++) {
                int idx = t + i * 256;
                if (idx < 640) {
                    int e = idx / 40, f4 = idx % 40;
                    bst[i] = *(const float4*)&bt_w[(size_t)(k0 + e) * EE + f4 * 4];
                }
            }
        }
#pragma unroll
        for (int ks = 0; ks < 2; ks++) {
            const int kA = kc * 16 + ks * 8;
            uint32_t af[4];
            af[0] = As[warp * 16 + g][kA + tg];
            af[1] = As[warp * 16 + g + 8][kA + tg];
            af[2] = As[warp * 16 + g][kA + tg + 4];
            af[3] = As[warp * 16 + g + 8][kA + tg + 4];
#pragma unroll
            for (int n8 = 0; n8 < 20; n8++) {
                uint32_t bf[2];
                bf[0] = Bs[buf][ks * 8 + tg][n8 * 8 + g];
                bf[1] = Bs[buf][ks * 8 + tg + 4][n8 * 8 + g];
                mma_tf32(acc[n8], af, bf);
            }
        }
    }

    const int r0 = mb + warp * 16 + g;
#pragma unroll
    for (int n8 = 0; n8 < 20; n8++) {
        const int n0 = n8 * 8 + tg * 2;
        const float bb0 = bt_b[n0], bb1 = bt_b[n0 + 1];
#pragma unroll
        for (int half = 0; half < 2; half++) {
            const int row = r0 + half * 8;
            const int gi0 = (row & 31) * EE + n0;
            float o0 = acc[n8][half * 2 + 0] + bb0;
            float o1 = acc[n8][half * 2 + 1] + bb1;
            float gm0 = sup_gamma[gi0],     gm1 = sup_gamma[gi0 + 1];
            float sb0 = sup_beta[gi0],      sb1 = sup_beta[gi0 + 1];
            float h0  = g_h[(size_t)row * EE + n0];
            float h1  = g_h[(size_t)row * EE + n0 + 1];
            float s0 = 1.f / (1.f + __expf(-sb0 * o0));
            float s1 = 1.f / (1.f + __expf(-sb1 * o1));
            g_y[(size_t)row * EE + n0]     = (gm0 + s0 * (1.f - gm0)) * o0 + h0;
            g_y[(size_t)row * EE + n0 + 1] = (gm1 + s1 * (1.f - gm1)) * o1 + h1;
        }
    }
}

// ---------------------------------------------------------------------------
// Kernel 3: z = y @ lin_w^T  (fp16 m16n8k16 mma + ldmatrix, fp32 accum)
// M=512, N=3000, K=5120. BM=128, BN=64, BK=32, 256 threads (8 warps 4x2,
// warp tile 32x32). Grid (47,4)=188 CTAs. Double-buffered, rows pad 40 halves.
// ---------------------------------------------------------------------------
#define K3_BM 128
#define K3_BN 64
#define K3_BK 32
#define K3_LDH 40   // halves per row (80B: ldmatrix-conflict-free)

__global__ __launch_bounds__(256) void k3_f16(
    const float* __restrict__ lin_w, const float* __restrict__ lin_b,
    const float* __restrict__ og_p, const float* __restrict__ ob_p,
    float* __restrict__ out)
{
    __shared__ __half As[2][K3_BM][K3_LDH];   // 20480 B
    __shared__ __half Bs[2][K3_BN][K3_LDH];   // 10240 B

    const int t    = threadIdx.x;
    const int lane = t & 31;
    const int warp = t >> 5;
    const int wm   = warp >> 1;   // 0..3 -> rows wm*32
    const int wn   = warp & 1;    // 0..1 -> cols wn*32
    const int g    = lane >> 2;
    const int tg   = lane & 3;

    const int mbase = blockIdx.y * K3_BM;
    const int nbase = blockIdx.x * K3_BN;

    // loader mapping
    const int  ar = t >> 1, akh = (t & 1) * 16;      // A: 16 halves
    const int  br = t >> 2, bkh = (t & 3) * 8;       // B: 8 halves
    const float* Ag = g_y + (size_t)(mbase + ar) * DTRF + akh;
    const int  brow = nbase + br;
    const bool bok  = (brow < DOUT);
    const float* Bg = lin_w + (size_t)(bok ? brow : 0) * DTRF + bkh;

    // precompute ldmatrix shared addresses (per buf) lazily below
    float acc[2][4][4] = {};
    float4 a_st[4];  float4 b_st[2];

#pragma unroll
    for (int i = 0; i < 4; i++) a_st[i] = *(const float4*)&Ag[i * 4];
#pragma unroll
    for (int i = 0; i < 2; i++)
        b_st[i] = bok ? *(const float4*)&Bg[i * 4]
                      : make_float4(0.f, 0.f, 0.f, 0.f);

    const int NIT = DTRF / K3_BK;   // 160
    for (int it = 0; it < NIT; it++) {
        const int buf = it & 1;
        // convert + store
        {
            uint32_t w0 = pack2h(a_st[0].x, a_st[0].y);
            uint32_t w1 = pack2h(a_st[0].z, a_st[0].w);
            uint32_t w2 = pack2h(a_st[1].x, a_st[1].y);
            uint32_t w3 = pack2h(a_st[1].z, a_st[1].w);
            *(uint4*)&As[buf][ar][akh] = make_uint4(w0, w1, w2, w3);
            w0 = pack2h(a_st[2].x, a_st[2].y);
            w1 = pack2h(a_st[2].z, a_st[2].w);
            w2 = pack2h(a_st[3].x, a_st[3].y);
            w3 = pack2h(a_st[3].z, a_st[3].w);
            *(uint4*)&As[buf][ar][akh + 8] = make_uint4(w0, w1, w2, w3);
            w0 = pack2h(b_st[0].x, b_st[0].y);
            w1 = pack2h(b_st[0].z, b_st[0].w);
            w2 = pack2h(b_st[1].x, b_st[1].y);
            w3 = pack2h(b_st[1].z, b_st[1].w);
            *(uint4*)&Bs[buf][br][bkh] = make_uint4(w0, w1, w2, w3);
        }
        __syncthreads();

        // prefetch next
        if (it + 1 < NIT) {
            const float* An = Ag + (it + 1) * K3_BK;
            const float* Bn = Bg + (it + 1) * K3_BK;
#pragma unroll
            for (int i = 0; i < 4; i++) a_st[i] = *(const float4*)&An[i * 4];
#pragma unroll
            for (int i = 0; i < 2; i++)
                b_st[i] = bok ? *(const float4*)&Bn[i * 4]
                              : make_float4(0.f, 0.f, 0.f, 0.f);
        }

        // compute: 2 k16 steps
#pragma unroll
        for (int ks = 0; ks < 2; ks++) {
            const int k0 = ks * 16;
            // A frags: 2 m16 tiles
            uint32_t af[2][4];
#pragma unroll
            for (int mi = 0; mi < 2; mi++) {
                const int rbase2 = wm * 32 + mi * 16;
                uint32_t addr = (uint32_t)__cvta_generic_to_shared(
                    &As[buf][rbase2 + (lane & 15)][k0 + (lane >> 4) * 8]);
                ldsm_x4(af[mi][0], af[mi][1], af[mi][2], af[mi][3], addr);
            }
            // B frags: 2 x4 loads cover n 32 (4 n8 tiles x {b0,b1})
            uint32_t bf[2][4];
#pragma unroll
            for (int nh = 0; nh < 2; nh++) {
                const int nbase2 = wn * 32 + nh * 16;
                uint32_t addr = (uint32_t)__cvta_generic_to_shared(
                    &Bs[buf][nbase2 + (lane & 7) + ((lane >> 4) & 1) * 8]
                          [k0 + ((lane >> 3) & 1) * 8]);
                ldsm_x4(bf[nh][0], bf[nh][1], bf[nh][2], bf[nh][3], addr);
            }
#pragma unroll
            for (int mi = 0; mi < 2; mi++)
#pragma unroll
                for (int ni = 0; ni < 4; ni++) {
                    const int nh = ni >> 1, sub = ni & 1;
                    mma_f16(acc[mi][ni], af[mi],
                            bf[nh][sub * 2], bf[nh][sub * 2 + 1]);
                }
        }
    }

    const float og = og_p[0], ob = ob_p[0];
#pragma unroll
    for (int mi = 0; mi < 2; mi++) {
        const int m0 = mbase + wm * 32 + mi * 16 + g;
#pragma unroll
        for (int ni = 0; ni < 4; ni++) {
            const int n0 = nbase + wn * 32 + ni * 8 + tg * 2;
            if (n0 + 1 < DOUT) {
                const float lb0 = lin_b[n0], lb1 = lin_b[n0 + 1];
                out[(size_t)m0 * DOUT + n0]           = (acc[mi][ni][0] + lb0) * og + ob;
                out[(size_t)m0 * DOUT + n0 + 1]       = (acc[mi][ni][1] + lb1) * og + ob;
                out[(size_t)(m0 + 8) * DOUT + n0]     = (acc[mi][ni][2] + lb0) * og + ob;
                out[(size_t)(m0 + 8) * DOUT + n0 + 1] = (acc[mi][ni][3] + lb1) * og + ob;
            } else if (n0 < DOUT) {
                const float lb0 = lin_b[n0];
                out[(size_t)m0 * DOUT + n0]       = (acc[mi][ni][0] + lb0) * og + ob;
                out[(size_t)(m0 + 8) * DOUT + n0] = (acc[mi][ni][2] + lb0) * og + ob;
            }
        }
    }
}

// ---------------------------------------------------------------------------
extern "C" void kernel_launch(void* const* d_in, const int* in_sizes, int n_in,
                              void* d_out, int out_size)
{
    const float* x         = (const float*)d_in[0];
    const float* stdv      = (const float*)d_in[1];
    const float* meanv     = (const float*)d_in[2];
    const float* mat       = (const float*)d_in[3];
    const float* ln_g      = (const float*)d_in[4];
    const float* ln_b      = (const float*)d_in[5];
    const float* wq        = (const float*)d_in[6];
    const float* bq        = (const float*)d_in[7];
    const float* wk        = (const float*)d_in[8];
    const float* bk        = (const float*)d_in[9];
    const float* wv        = (const float*)d_in[10];
    const float* bv        = (const float*)d_in[11];
    const float* bt_w      = (const float*)d_in[12];
    const float* bt_b      = (const float*)d_in[13];
    const float* bt_gain   = (const float*)d_in[14];
    const float* bt_bias   = (const float*)d_in[15];
    const float* sup_gamma = (const float*)d_in[16];
    const float* sup_beta  = (const float*)d_in[17];
    const float* lin_w     = (const float*)d_in[18];
    const float* lin_b     = (const float*)d_in[19];
    const float* out_gain  = (const float*)d_in[20];
    const float* out_bias  = (const float*)d_in[21];
    float* out = (float*)d_out;

    const int smem2b = (64 * 164 + 3 * 160 * 20) * 4;              // 80384
    const int smem2c = (96 * AT_LD + 32 * 33) * 4;                 // 67584
    const int smem2d = (128 * 164 + 2 * 16 * 168) * 4;             // 105472

    cudaFuncSetAttribute(k2b_qkv, cudaFuncAttributeMaxDynamicSharedMemorySize, smem2b);
    cudaFuncSetAttribute(k2c_attn, cudaFuncAttributeMaxDynamicSharedMemorySize, smem2c);
    cudaFuncSetAttribute(k2d_bt,  cudaFuncAttributeMaxDynamicSharedMemorySize, smem2d);

    k1_clgemm<<<dim3(40, 8), 256>>>(x, stdv, meanv, mat);
    k2a_ln  <<<B_SZ, 256>>>(ln_g, ln_b);
    k2b_qkv <<<M2 / 64, 384, smem2b>>>(wq, bq, wk, bk, wv, bv);
    k2c_attn<<<B_SZ, 128, smem2c>>>();
    k2d_bt  <<<M2 / 128, 256, smem2d>>>(bt_w, bt_b, bt_gain, bt_bias,
                                        sup_gamma, sup_beta);
    k3_f16  <<<dim3((DOUT + K3_BN - 1) / K3_BN, B_SZ / K3_BM), 256>>>(
        lin_w, lin_b, out_gain, out_bias, out);
}

// round 8
// speedup vs baseline: 2.5027x; 1.0339x over previous
#include <cuda_runtime.h>
#include <cuda_fp16.h>
#include <math.h>
#include <stdint.h>

// Problem constants
#define B_SZ  512
#define DIN   64
#define DCL   4998
#define DTRF  5120
#define PADN  61
#define PP    32
#define EE    160
#define DOUT  3000
#define M2    (B_SZ * PP)          // 16384 rows of 160

// Global scratch
__device__ float g_cl[B_SZ * DCL];
__device__ float g_q [M2 * EE];
__device__ float g_k [M2 * EE];
__device__ float g_v [M2 * EE];
__device__ float g_h [M2 * EE];
__device__ float g_y [M2 * EE];

// ---------------------------------------------------------------------------
// helpers
// ---------------------------------------------------------------------------
__device__ __forceinline__ uint32_t f2tf32(float f) {
    uint32_t u;
    asm("cvt.rna.tf32.f32 %0, %1;" : "=r"(u) : "f"(f));
    return u;
}
__device__ __forceinline__ void mma_tf32(float* c, const uint32_t* a,
                                         const uint32_t* b) {
    asm volatile(
        "mma.sync.aligned.m16n8k8.row.col.f32.tf32.tf32.f32 "
        "{%0,%1,%2,%3}, {%4,%5,%6,%7}, {%8,%9}, {%0,%1,%2,%3};\n"
        : "+f"(c[0]), "+f"(c[1]), "+f"(c[2]), "+f"(c[3])
        : "r"(a[0]), "r"(a[1]), "r"(a[2]), "r"(a[3]),
          "r"(b[0]), "r"(b[1]));
}
__device__ __forceinline__ uint32_t pack2h(float a, float b) {
    __half2 h = __floats2half2_rn(a, b);
    return *(uint32_t*)&h;
}
__device__ __forceinline__ void mma_f16(float* c, const uint32_t* a,
                                        uint32_t b0, uint32_t b1) {
    asm volatile(
        "mma.sync.aligned.m16n8k16.row.col.f32.f16.f16.f32 "
        "{%0,%1,%2,%3}, {%4,%5,%6,%7}, {%8,%9}, {%0,%1,%2,%3};\n"
        : "+f"(c[0]), "+f"(c[1]), "+f"(c[2]), "+f"(c[3])
        : "r"(a[0]), "r"(a[1]), "r"(a[2]), "r"(a[3]),
          "r"(b0), "r"(b1));
}
__device__ __forceinline__ void ldsm_x4(uint32_t& r0, uint32_t& r1,
                                        uint32_t& r2, uint32_t& r3,
                                        uint32_t addr) {
    asm volatile(
        "ldmatrix.sync.aligned.m8n8.x4.shared.b16 {%0,%1,%2,%3}, [%4];"
        : "=r"(r0), "=r"(r1), "=r"(r2), "=r"(r3) : "r"(addr));
}

// ---------------------------------------------------------------------------
// Kernel 1: cl = (x*std + mean) @ mat   64x128 tile, 8x4 per thread
// ---------------------------------------------------------------------------
__global__ __launch_bounds__(256) void k1_clgemm(
    const float* __restrict__ x, const float* __restrict__ stdv,
    const float* __restrict__ meanv, const float* __restrict__ mat)
{
    __shared__ float u_s[64 * 64];
    const int rbase = blockIdx.y * 64;
    const int cbase = blockIdx.x * 128;
    const int tid = threadIdx.x;

    for (int idx = tid; idx < 64 * 64; idx += 256) {
        int r = idx >> 6, k = idx & 63;
        u_s[idx] = x[(rbase + r) * DIN + k] * stdv[k] + meanv[k];
    }
    __syncthreads();

    const int ty = tid >> 5;
    const int tx = tid & 31;
    int   c[4];  bool cv[4];
#pragma unroll
    for (int j = 0; j < 4; j++) { c[j] = cbase + tx + 32 * j; cv[j] = (c[j] < DCL); }

    float acc[8][4] = {};
#pragma unroll 4
    for (int k = 0; k < 64; k++) {
        float a[8], b[4];
#pragma unroll
        for (int i = 0; i < 8; i++) a[i] = u_s[(ty + 8 * i) * 64 + k];
#pragma unroll
        for (int j = 0; j < 4; j++) b[j] = cv[j] ? mat[k * DCL + c[j]] : 0.f;
#pragma unroll
        for (int i = 0; i < 8; i++)
#pragma unroll
            for (int j = 0; j < 4; j++)
                acc[i][j] += a[i] * b[j];
    }
#pragma unroll
    for (int i = 0; i < 8; i++) {
        int row = rbase + ty + 8 * i;
#pragma unroll
        for (int j = 0; j < 4; j++)
            if (cv[j]) g_cl[row * DCL + c[j]] = acc[i][j];
    }
}

// ---------------------------------------------------------------------------
// Kernel 2b: fused LayerNorm + QKV GEMM (tf32 mma).
// Block covers 64 M2-rows = 2 batch rows; LN computed in-block from g_cl.
// ---------------------------------------------------------------------------
__global__ __launch_bounds__(384) void k2b_qkv(
    const float* __restrict__ ln_g, const float* __restrict__ ln_b,
    const float* __restrict__ wq, const float* __restrict__ bq,
    const float* __restrict__ wk, const float* __restrict__ bk,
    const float* __restrict__ wv, const float* __restrict__ bv)
{
    extern __shared__ uint32_t sm2b[];
    uint32_t (*As)[164] = (uint32_t(*)[164])sm2b;                      // [64][164]
    uint32_t (*Bs)[160][20] = (uint32_t(*)[160][20])(sm2b + 64 * 164); // [3][160][20]
    __shared__ float red[64];

    const int t    = threadIdx.x;
    const int lane = t & 31;
    const int warp = t >> 5;
    const int mat  = warp >> 2;
    const int wm   = warp & 3;
    const int g    = lane >> 2;
    const int tg   = lane & 3;
    const int mb   = blockIdx.x * 64;
    const int b0   = mb >> 5;

    const float* W[3]  = {wq, wk, wv};
    const float* BI[3] = {bq, bk, bv};
    float*       O[3]  = {g_q, g_k, g_v};

    float4 bst[5];
#pragma unroll
    for (int i = 0; i < 5; i++) {
        int idx = t + i * 384;
        int m = idx / 640, rem = idx % 640;
        int n = rem >> 2, c = rem & 3;
        bst[i] = *(const float4*)&W[m][n * EE + c * 4];
    }

    // ---- phase 1: load padded cl into As (raw float bits) + LN partials ----
    const float* cl0 = g_cl + (size_t)b0 * DCL;
    const float* cl1 = g_cl + (size_t)(b0 + 1) * DCL;
    float s0 = 0.f, q0 = 0.f, s1 = 0.f, q1 = 0.f;
    for (int i = t; i < 2560; i += 384) {
        int r = i / 40, c4 = i % 40;
        int hb = r >> 5, p = r & 31;
        int d = p * EE + c4 * 4;
        const float* clr = hb ? cl1 : cl0;
        float v[4];
#pragma unroll
        for (int j = 0; j < 4; j++) {
            int dd = d + j;
            v[j] = (dd >= PADN && dd < PADN + DCL) ? clr[dd - PADN] : 0.f;
        }
        *(float4*)&As[r][c4 * 4] = make_float4(v[0], v[1], v[2], v[3]);
        float ls = v[0] + v[1] + v[2] + v[3];
        float lq = v[0] * v[0] + v[1] * v[1] + v[2] * v[2] + v[3] * v[3];
        if (hb) { s1 += ls; q1 += lq; } else { s0 += ls; q0 += lq; }
    }
#pragma unroll
    for (int o = 16; o > 0; o >>= 1) {
        s0 += __shfl_xor_sync(~0u, s0, o);
        q0 += __shfl_xor_sync(~0u, q0, o);
        s1 += __shfl_xor_sync(~0u, s1, o);
        q1 += __shfl_xor_sync(~0u, q1, o);
    }
    if (lane == 0) {
        red[warp * 4 + 0] = s0; red[warp * 4 + 1] = q0;
        red[warp * 4 + 2] = s1; red[warp * 4 + 3] = q1;
    }
    __syncthreads();
    if (t < 2) {
        float s = 0.f, qq = 0.f;
        for (int w = 0; w < 12; w++) {
            s  += red[w * 4 + 2 * t];
            qq += red[w * 4 + 2 * t + 1];
        }
        float mu  = s / (float)DTRF;
        float var = qq / (float)DTRF - mu * mu;
        red[48 + t * 2]     = mu;
        red[48 + t * 2 + 1] = rsqrtf(var + 1e-5f);
    }
    __syncthreads();

    // ---- phase 2: normalize in place, convert to tf32 ----
    {
        float mu0 = red[48], rs0 = red[49], mu1 = red[50], rs1 = red[51];
        for (int i = t; i < 2560; i += 384) {
            int r = i / 40, c4 = i % 40;
            int hb = r >> 5, p = r & 31;
            int d = p * EE + c4 * 4;
            float mu = hb ? mu1 : mu0, rs = hb ? rs1 : rs0;
            float4 v  = *(float4*)&As[r][c4 * 4];
            float4 gg = *(const float4*)&ln_g[d];
            float4 bb = *(const float4*)&ln_b[d];
            uint4 u = make_uint4(
                f2tf32((v.x - mu) * rs * gg.x + bb.x),
                f2tf32((v.y - mu) * rs * gg.y + bb.y),
                f2tf32((v.z - mu) * rs * gg.z + bb.z),
                f2tf32((v.w - mu) * rs * gg.w + bb.w));
            *(uint4*)&As[r][c4 * 4] = u;
        }
    }
    __syncthreads();

    // ---- GEMM ----
    float acc[20][4] = {};
    for (int kc = 0; kc < 10; kc++) {
        if (kc) __syncthreads();
#pragma unroll
        for (int i = 0; i < 5; i++) {
            int idx = t + i * 384;
            int m = idx / 640, rem = idx % 640;
            int n = rem >> 2, c = rem & 3;
            uint4 u = make_uint4(f2tf32(bst[i].x), f2tf32(bst[i].y),
                                 f2tf32(bst[i].z), f2tf32(bst[i].w));
            *(uint4*)&Bs[m][n][c * 4] = u;
        }
        __syncthreads();
        if (kc + 1 < 10) {
            int k0 = (kc + 1) * 16;
#pragma unroll
            for (int i = 0; i < 5; i++) {
                int idx = t + i * 384;
                int m = idx / 640, rem = idx % 640;
                int n = rem >> 2, c = rem & 3;
                bst[i] = *(const float4*)&W[m][n * EE + k0 + c * 4];
            }
        }
#pragma unroll
        for (int ks = 0; ks < 2; ks++) {
            const int kA = kc * 16 + ks * 8;
            uint32_t af[4];
            af[0] = As[wm * 16 + g][kA + tg];
            af[1] = As[wm * 16 + g + 8][kA + tg];
            af[2] = As[wm * 16 + g][kA + tg + 4];
            af[3] = As[wm * 16 + g + 8][kA + tg + 4];
#pragma unroll
            for (int n8 = 0; n8 < 20; n8++) {
                uint32_t bf[2];
                bf[0] = Bs[mat][n8 * 8 + g][ks * 8 + tg];
                bf[1] = Bs[mat][n8 * 8 + g][ks * 8 + tg + 4];
                mma_tf32(acc[n8], af, bf);
            }
        }
    }

    const float* bias = BI[mat];
    float* out = O[mat];
    const int r0 = mb + wm * 16 + g;
#pragma unroll
    for (int n8 = 0; n8 < 20; n8++) {
        const int n0 = n8 * 8 + tg * 2;
        const float bb0 = bias[n0], bb1 = bias[n0 + 1];
        out[(size_t)r0 * EE + n0]           = acc[n8][0] + bb0;
        out[(size_t)r0 * EE + n0 + 1]       = acc[n8][1] + bb1;
        out[(size_t)(r0 + 8) * EE + n0]     = acc[n8][2] + bb0;
        out[(size_t)(r0 + 8) * EE + n0 + 1] = acc[n8][3] + bb1;
    }
}

// ---------------------------------------------------------------------------
// Kernel 2c: attention per batch row. 512 blocks x 128 threads.
// sq/sv rows LD=164 (float4), kt LD=33 (conflict-free transpose + broadcast
// scalar reads), att LD=33. Parallel softmax via shfl.
// ---------------------------------------------------------------------------
__global__ __launch_bounds__(128) void k2c_attn()
{
    extern __shared__ float sm2c[];
    float (*sq)[164] = (float(*)[164])sm2c;
    float (*kt)[33]  = (float(*)[33]) (sm2c + 32 * 164);
    float (*sv)[164] = (float(*)[164])(sm2c + 32 * 164 + 160 * 33);
    float (*att)[33] = (float(*)[33]) (sm2c + 64 * 164 + 160 * 33);

    const int b = blockIdx.x;
    const int t = threadIdx.x;
    const float inv_scale = rsqrtf(160.0f);
    const size_t base = (size_t)b * PP * EE;

    for (int i = t; i < PP * EE; i += 128) {
        int p = i / EE, e = i % EE;
        sq[p][e] = g_q[base + i] * inv_scale;
        kt[e][p] = g_k[base + i];
        sv[p][e] = g_v[base + i];
    }
    __syncthreads();

    // dot[p][q] : 256 (p,q4) pairs over 2 iterations -> p covers 0..31
#pragma unroll
    for (int it = 0; it < 2; it++) {
        const int idx = t + it * 128;
        const int p = idx >> 3, q4 = idx & 7;
        float acc[4] = {};
#pragma unroll 4
        for (int e4 = 0; e4 < 40; e4++) {
            float4 qv = *(const float4*)&sq[p][e4 * 4];
#pragma unroll
            for (int c = 0; c < 4; c++) {
                acc[c] += qv.x * kt[e4 * 4 + 0][q4 * 4 + c];
                acc[c] += qv.y * kt[e4 * 4 + 1][q4 * 4 + c];
                acc[c] += qv.z * kt[e4 * 4 + 2][q4 * 4 + c];
                acc[c] += qv.w * kt[e4 * 4 + 3][q4 * 4 + c];
            }
        }
#pragma unroll
        for (int c = 0; c < 4; c++) att[p][q4 * 4 + c] = acc[c];
    }
    __syncthreads();

    // softmax over p (dim=1): thread (q = t>>2, pg = t&3), 8 p each; shfl over 4
    {
        const int q = t >> 2, pg = t & 3;
        float m = -1e30f;
#pragma unroll
        for (int i = 0; i < 8; i++) m = fmaxf(m, att[pg * 8 + i][q]);
        m = fmaxf(m, __shfl_xor_sync(~0u, m, 1));
        m = fmaxf(m, __shfl_xor_sync(~0u, m, 2));
        float s = 0.f;
        float ev[8];
#pragma unroll
        for (int i = 0; i < 8; i++) {
            ev[i] = __expf(att[pg * 8 + i][q] - m);
            s += ev[i];
        }
        s += __shfl_xor_sync(~0u, s, 1);
        s += __shfl_xor_sync(~0u, s, 2);
        float inv = 1.f / s;
#pragma unroll
        for (int i = 0; i < 8; i++) att[pg * 8 + i][q] = ev[i] * inv;
    }
    __syncthreads();

    // h = att @ V + cl_padded -> g_h   (float4 over e)
    const float* clrow = g_cl + (size_t)b * DCL;
#pragma unroll
    for (int j = 0; j < 10; j++) {
        int idx4 = t + j * 128;          // (p, e4)
        int p = idx4 / 40, e4 = idx4 % 40;
        float4 a = make_float4(0.f, 0.f, 0.f, 0.f);
#pragma unroll
        for (int q = 0; q < 32; q++) {
            float w = att[p][q];
            float4 vv = *(const float4*)&sv[q][e4 * 4];
            a.x += w * vv.x; a.y += w * vv.y;
            a.z += w * vv.z; a.w += w * vv.w;
        }
        int d = p * EE + e4 * 4;
        float cl0 = (d + 0 >= PADN && d + 0 < PADN + DCL) ? clrow[d + 0 - PADN] : 0.f;
        float cl1 = (d + 1 >= PADN && d + 1 < PADN + DCL) ? clrow[d + 1 - PADN] : 0.f;
        float cl2 = (d + 2 >= PADN && d + 2 < PADN + DCL) ? clrow[d + 2 - PADN] : 0.f;
        float cl3 = (d + 3 >= PADN && d + 3 < PADN + DCL) ? clrow[d + 3 - PADN] : 0.f;
        *(float4*)&g_h[base + d] =
            make_float4(a.x + cl0, a.y + cl1, a.z + cl2, a.w + cl3);
    }
}

// ---------------------------------------------------------------------------
// Kernel 2d: BT GEMM + Supact + residual (tf32 mma)
// ---------------------------------------------------------------------------
__global__ __launch_bounds__(256) void k2d_bt(
    const float* __restrict__ bt_w, const float* __restrict__ bt_b,
    const float* __restrict__ bt_gain, const float* __restrict__ bt_bias,
    const float* __restrict__ sup_gamma, const float* __restrict__ sup_beta)
{
    extern __shared__ uint32_t sm2d[];
    uint32_t (*As)[164]     = (uint32_t(*)[164])sm2d;
    uint32_t (*Bs)[16][168] = (uint32_t(*)[16][168])(sm2d + 128 * 164);

    const int t    = threadIdx.x;
    const int lane = t & 31;
    const int warp = t >> 5;
    const int g    = lane >> 2;
    const int tg   = lane & 3;
    const int mb   = blockIdx.x * 128;
    const float btg = bt_gain[0], btb = bt_bias[0];

    float4 bst[3];
#pragma unroll
    for (int i = 0; i < 3; i++) {
        int idx = t + i * 256;
        if (idx < 640) {
            int e = idx / 40, f4 = idx % 40;
            bst[i] = *(const float4*)&bt_w[(size_t)e * EE + f4 * 4];
        }
    }

    for (int i = t; i < 5120; i += 256) {
        int r = i / 40, c4 = i % 40;
        float4 v = *(const float4*)&g_h[(size_t)(mb + r) * EE + c4 * 4];
        uint4 u = make_uint4(f2tf32(v.x * btg + btb), f2tf32(v.y * btg + btb),
                             f2tf32(v.z * btg + btb), f2tf32(v.w * btg + btb));
        *(uint4*)&As[r][c4 * 4] = u;
    }

    float acc[20][4] = {};
    for (int kc = 0; kc < 10; kc++) {
        const int buf = kc & 1;
#pragma unroll
        for (int i = 0; i < 3; i++) {
            int idx = t + i * 256;
            if (idx < 640) {
                int e = idx / 40, f4 = idx % 40;
                uint4 u = make_uint4(f2tf32(bst[i].x), f2tf32(bst[i].y),
                                     f2tf32(bst[i].z), f2tf32(bst[i].w));
                *(uint4*)&Bs[buf][e][f4 * 4] = u;
            }
        }
        __syncthreads();
        if (kc + 1 < 10) {
            int k0 = (kc + 1) * 16;
#pragma unroll
            for (int i = 0; i < 3; i++) {
                int idx = t + i * 256;
                if (idx < 640) {
                    int e = idx / 40, f4 = idx % 40;
                    bst[i] = *(const float4*)&bt_w[(size_t)(k0 + e) * EE + f4 * 4];
                }
            }
        }
#pragma unroll
        for (int ks = 0; ks < 2; ks++) {
            const int kA = kc * 16 + ks * 8;
            uint32_t af[4];
            af[0] = As[warp * 16 + g][kA + tg];
            af[1] = As[warp * 16 + g + 8][kA + tg];
            af[2] = As[warp * 16 + g][kA + tg + 4];
            af[3] = As[warp * 16 + g + 8][kA + tg + 4];
#pragma unroll
            for (int n8 = 0; n8 < 20; n8++) {
                uint32_t bf[2];
                bf[0] = Bs[buf][ks * 8 + tg][n8 * 8 + g];
                bf[1] = Bs[buf][ks * 8 + tg + 4][n8 * 8 + g];
                mma_tf32(acc[n8], af, bf);
            }
        }
    }

    const int r0 = mb + warp * 16 + g;
#pragma unroll
    for (int n8 = 0; n8 < 20; n8++) {
        const int n0 = n8 * 8 + tg * 2;
        const float bb0 = bt_b[n0], bb1 = bt_b[n0 + 1];
#pragma unroll
        for (int half = 0; half < 2; half++) {
            const int row = r0 + half * 8;
            const int gi0 = (row & 31) * EE + n0;
            float o0 = acc[n8][half * 2 + 0] + bb0;
            float o1 = acc[n8][half * 2 + 1] + bb1;
            float gm0 = sup_gamma[gi0],     gm1 = sup_gamma[gi0 + 1];
            float sb0 = sup_beta[gi0],      sb1 = sup_beta[gi0 + 1];
            float h0  = g_h[(size_t)row * EE + n0];
            float h1  = g_h[(size_t)row * EE + n0 + 1];
            float s0 = 1.f / (1.f + __expf(-sb0 * o0));
            float s1 = 1.f / (1.f + __expf(-sb1 * o1));
            g_y[(size_t)row * EE + n0]     = (gm0 + s0 * (1.f - gm0)) * o0 + h0;
            g_y[(size_t)row * EE + n0 + 1] = (gm1 + s1 * (1.f - gm1)) * o1 + h1;
        }
    }
}

// ---------------------------------------------------------------------------
// Kernel 3: z = y @ lin_w^T  (fp16 m16n8k16 mma + ldmatrix, fp32 accum)
// ---------------------------------------------------------------------------
#define K3_BM 128
#define K3_BN 64
#define K3_BK 32
#define K3_LDH 40

__global__ __launch_bounds__(256) void k3_f16(
    const float* __restrict__ lin_w, const float* __restrict__ lin_b,
    const float* __restrict__ og_p, const float* __restrict__ ob_p,
    float* __restrict__ out)
{
    __shared__ __half As[2][K3_BM][K3_LDH];
    __shared__ __half Bs[2][K3_BN][K3_LDH];

    const int t    = threadIdx.x;
    const int lane = t & 31;
    const int warp = t >> 5;
    const int wm   = warp >> 1;
    const int wn   = warp & 1;
    const int g    = lane >> 2;
    const int tg   = lane & 3;

    const int mbase = blockIdx.y * K3_BM;
    const int nbase = blockIdx.x * K3_BN;

    const int  ar = t >> 1, akh = (t & 1) * 16;
    const int  br = t >> 2, bkh = (t & 3) * 8;
    const float* Ag = g_y + (size_t)(mbase + ar) * DTRF + akh;
    const int  brow = nbase + br;
    const bool bok  = (brow < DOUT);
    const float* Bg = lin_w + (size_t)(bok ? brow : 0) * DTRF + bkh;

    float acc[2][4][4] = {};
    float4 a_st[4];  float4 b_st[2];

#pragma unroll
    for (int i = 0; i < 4; i++) a_st[i] = *(const float4*)&Ag[i * 4];
#pragma unroll
    for (int i = 0; i < 2; i++)
        b_st[i] = bok ? *(const float4*)&Bg[i * 4]
                      : make_float4(0.f, 0.f, 0.f, 0.f);

    const int NIT = DTRF / K3_BK;
    for (int it = 0; it < NIT; it++) {
        const int buf = it & 1;
        {
            uint32_t w0 = pack2h(a_st[0].x, a_st[0].y);
            uint32_t w1 = pack2h(a_st[0].z, a_st[0].w);
            uint32_t w2 = pack2h(a_st[1].x, a_st[1].y);
            uint32_t w3 = pack2h(a_st[1].z, a_st[1].w);
            *(uint4*)&As[buf][ar][akh] = make_uint4(w0, w1, w2, w3);
            w0 = pack2h(a_st[2].x, a_st[2].y);
            w1 = pack2h(a_st[2].z, a_st[2].w);
            w2 = pack2h(a_st[3].x, a_st[3].y);
            w3 = pack2h(a_st[3].z, a_st[3].w);
            *(uint4*)&As[buf][ar][akh + 8] = make_uint4(w0, w1, w2, w3);
            w0 = pack2h(b_st[0].x, b_st[0].y);
            w1 = pack2h(b_st[0].z, b_st[0].w);
            w2 = pack2h(b_st[1].x, b_st[1].y);
            w3 = pack2h(b_st[1].z, b_st[1].w);
            *(uint4*)&Bs[buf][br][bkh] = make_uint4(w0, w1, w2, w3);
        }
        __syncthreads();

        if (it + 1 < NIT) {
            const float* An = Ag + (it + 1) * K3_BK;
            const float* Bn = Bg + (it + 1) * K3_BK;
#pragma unroll
            for (int i = 0; i < 4; i++) a_st[i] = *(const float4*)&An[i * 4];
#pragma unroll
            for (int i = 0; i < 2; i++)
                b_st[i] = bok ? *(const float4*)&Bn[i * 4]
                              : make_float4(0.f, 0.f, 0.f, 0.f);
        }

#pragma unroll
        for (int ks = 0; ks < 2; ks++) {
            const int k0 = ks * 16;
            uint32_t af[2][4];
#pragma unroll
            for (int mi = 0; mi < 2; mi++) {
                const int rbase2 = wm * 32 + mi * 16;
                uint32_t addr = (uint32_t)__cvta_generic_to_shared(
                    &As[buf][rbase2 + (lane & 15)][k0 + (lane >> 4) * 8]);
                ldsm_x4(af[mi][0], af[mi][1], af[mi][2], af[mi][3], addr);
            }
            uint32_t bf[2][4];
#pragma unroll
            for (int nh = 0; nh < 2; nh++) {
                const int nbase2 = wn * 32 + nh * 16;
                uint32_t addr = (uint32_t)__cvta_generic_to_shared(
                    &Bs[buf][nbase2 + (lane & 7) + ((lane >> 4) & 1) * 8]
                          [k0 + ((lane >> 3) & 1) * 8]);
                ldsm_x4(bf[nh][0], bf[nh][1], bf[nh][2], bf[nh][3], addr);
            }
#pragma unroll
            for (int mi = 0; mi < 2; mi++)
#pragma unroll
                for (int ni = 0; ni < 4; ni++) {
                    const int nh = ni >> 1, sub = ni & 1;
                    mma_f16(acc[mi][ni], af[mi],
                            bf[nh][sub * 2], bf[nh][sub * 2 + 1]);
                }
        }
    }

    const float og = og_p[0], ob = ob_p[0];
#pragma unroll
    for (int mi = 0; mi < 2; mi++) {
        const int m0 = mbase + wm * 32 + mi * 16 + g;
#pragma unroll
        for (int ni = 0; ni < 4; ni++) {
            const int n0 = nbase + wn * 32 + ni * 8 + tg * 2;
            if (n0 + 1 < DOUT) {
                const float lb0 = lin_b[n0], lb1 = lin_b[n0 + 1];
                out[(size_t)m0 * DOUT + n0]           = (acc[mi][ni][0] + lb0) * og + ob;
                out[(size_t)m0 * DOUT + n0 + 1]       = (acc[mi][ni][1] + lb1) * og + ob;
                out[(size_t)(m0 + 8) * DOUT + n0]     = (acc[mi][ni][2] + lb0) * og + ob;
                out[(size_t)(m0 + 8) * DOUT + n0 + 1] = (acc[mi][ni][3] + lb1) * og + ob;
            } else if (n0 < DOUT) {
                const float lb0 = lin_b[n0];
                out[(size_t)m0 * DOUT + n0]       = (acc[mi][ni][0] + lb0) * og + ob;
                out[(size_t)(m0 + 8) * DOUT + n0] = (acc[mi][ni][2] + lb0) * og + ob;
            }
        }
    }
}

// ---------------------------------------------------------------------------
extern "C" void kernel_launch(void* const* d_in, const int* in_sizes, int n_in,
                              void* d_out, int out_size)
{
    const float* x         = (const float*)d_in[0];
    const float* stdv      = (const float*)d_in[1];
    const float* meanv     = (const float*)d_in[2];
    const float* mat       = (const float*)d_in[3];
    const float* ln_g      = (const float*)d_in[4];
    const float* ln_b      = (const float*)d_in[5];
    const float* wq        = (const float*)d_in[6];
    const float* bq        = (const float*)d_in[7];
    const float* wk        = (const float*)d_in[8];
    const float* bk        = (const float*)d_in[9];
    const float* wv        = (const float*)d_in[10];
    const float* bv        = (const float*)d_in[11];
    const float* bt_w      = (const float*)d_in[12];
    const float* bt_b      = (const float*)d_in[13];
    const float* bt_gain   = (const float*)d_in[14];
    const float* bt_bias   = (const float*)d_in[15];
    const float* sup_gamma = (const float*)d_in[16];
    const float* sup_beta  = (const float*)d_in[17];
    const float* lin_w     = (const float*)d_in[18];
    const float* lin_b     = (const float*)d_in[19];
    const float* out_gain  = (const float*)d_in[20];
    const float* out_bias  = (const float*)d_in[21];
    float* out = (float*)d_out;

    const int smem2b = (64 * 164 + 3 * 160 * 20) * 4;                      // 80384
    const int smem2c = (64 * 164 + 160 * 33 + 32 * 33) * 4 + 32 * 164 * 4; // 67328
    const int smem2d = (128 * 164 + 2 * 16 * 168) * 4;                     // 105472

    cudaFuncSetAttribute(k2b_qkv, cudaFuncAttributeMaxDynamicSharedMemorySize, smem2b);
    cudaFuncSetAttribute(k2c_attn, cudaFuncAttributeMaxDynamicSharedMemorySize, smem2c);
    cudaFuncSetAttribute(k2d_bt,  cudaFuncAttributeMaxDynamicSharedMemorySize, smem2d);

    k1_clgemm<<<dim3(40, 8), 256>>>(x, stdv, meanv, mat);
    k2b_qkv <<<M2 / 64, 384, smem2b>>>(ln_g, ln_b, wq, bq, wk, bk, wv, bv);
    k2c_attn<<<B_SZ, 128, smem2c>>>();
    k2d_bt  <<<M2 / 128, 256, smem2d>>>(bt_w, bt_b, bt_gain, bt_bias,
                                        sup_gamma, sup_beta);
    k3_f16  <<<dim3((DOUT + K3_BN - 1) / K3_BN, B_SZ / K3_BM), 256>>>(
        lin_w, lin_b, out_gain, out_bias, out);
}

// round 9
// speedup vs baseline: 3.2673x; 1.3055x over previous
#include <cuda_runtime.h>
#include <cuda_fp16.h>
#include <math.h>
#include <stdint.h>

// Problem constants
#define B_SZ  512
#define DIN   64
#define DCL   4998
#define DTRF  5120
#define PADN  61
#define PP    32
#define EE    160
#define DOUT  3000
#define M2    (B_SZ * PP)          // 16384 rows of 160

// Global scratch
__device__ float g_cl[B_SZ * DCL];
__device__ float g_q [M2 * EE];
__device__ float g_k [M2 * EE];
__device__ float g_v [M2 * EE];
__device__ float g_h [M2 * EE];
__device__ __align__(256) __half g_yh[M2 * EE];        // y in fp16 (k3 A operand)
__device__ __align__(256) __half g_wh[DOUT * DTRF];    // lin_w in fp16 (k3 B operand)

// ---------------------------------------------------------------------------
// helpers
// ---------------------------------------------------------------------------
__device__ __forceinline__ uint32_t f2tf32(float f) {
    uint32_t u;
    asm("cvt.rna.tf32.f32 %0, %1;" : "=r"(u) : "f"(f));
    return u;
}
__device__ __forceinline__ void mma_tf32(float* c, const uint32_t* a,
                                         const uint32_t* b) {
    asm volatile(
        "mma.sync.aligned.m16n8k8.row.col.f32.tf32.tf32.f32 "
        "{%0,%1,%2,%3}, {%4,%5,%6,%7}, {%8,%9}, {%0,%1,%2,%3};\n"
        : "+f"(c[0]), "+f"(c[1]), "+f"(c[2]), "+f"(c[3])
        : "r"(a[0]), "r"(a[1]), "r"(a[2]), "r"(a[3]),
          "r"(b[0]), "r"(b[1]));
}
__device__ __forceinline__ uint32_t pack2h(float a, float b) {
    __half2 h = __floats2half2_rn(a, b);
    return *(uint32_t*)&h;
}
__device__ __forceinline__ void mma_f16(float* c, const uint32_t* a,
                                        uint32_t b0, uint32_t b1) {
    asm volatile(
        "mma.sync.aligned.m16n8k16.row.col.f32.f16.f16.f32 "
        "{%0,%1,%2,%3}, {%4,%5,%6,%7}, {%8,%9}, {%0,%1,%2,%3};\n"
        : "+f"(c[0]), "+f"(c[1]), "+f"(c[2]), "+f"(c[3])
        : "r"(a[0]), "r"(a[1]), "r"(a[2]), "r"(a[3]),
          "r"(b0), "r"(b1));
}
__device__ __forceinline__ void ldsm_x4(uint32_t& r0, uint32_t& r1,
                                        uint32_t& r2, uint32_t& r3,
                                        uint32_t addr) {
    asm volatile(
        "ldmatrix.sync.aligned.m8n8.x4.shared.b16 {%0,%1,%2,%3}, [%4];"
        : "=r"(r0), "=r"(r1), "=r"(r2), "=r"(r3) : "r"(addr));
}
__device__ __forceinline__ void cp16(uint32_t dst, const void* src) {
    asm volatile("cp.async.cg.shared.global [%0], [%1], 16;"
                 :: "r"(dst), "l"(src));
}

// ---------------------------------------------------------------------------
// Kernel 0: convert lin_w -> g_wh (fp16). 3000*5120/8 threads of 8 elems.
// ---------------------------------------------------------------------------
__global__ __launch_bounds__(256) void k0_wh(const float* __restrict__ w)
{
    size_t i = ((size_t)blockIdx.x * 256 + threadIdx.x) * 8;
    float4 a = *(const float4*)(w + i);
    float4 b = *(const float4*)(w + i + 4);
    uint4 u;
    u.x = pack2h(a.x, a.y); u.y = pack2h(a.z, a.w);
    u.z = pack2h(b.x, b.y); u.w = pack2h(b.z, b.w);
    *(uint4*)(g_wh + i) = u;
}

// ---------------------------------------------------------------------------
// Kernel 1: cl = (x*std + mean) @ mat   64x128 tile, 8x4 per thread
// ---------------------------------------------------------------------------
__global__ __launch_bounds__(256) void k1_clgemm(
    const float* __restrict__ x, const float* __restrict__ stdv,
    const float* __restrict__ meanv, const float* __restrict__ mat)
{
    __shared__ float u_s[64 * 64];
    const int rbase = blockIdx.y * 64;
    const int cbase = blockIdx.x * 128;
    const int tid = threadIdx.x;

    for (int idx = tid; idx < 64 * 64; idx += 256) {
        int r = idx >> 6, k = idx & 63;
        u_s[idx] = x[(rbase + r) * DIN + k] * stdv[k] + meanv[k];
    }
    __syncthreads();

    const int ty = tid >> 5;
    const int tx = tid & 31;
    int   c[4];  bool cv[4];
#pragma unroll
    for (int j = 0; j < 4; j++) { c[j] = cbase + tx + 32 * j; cv[j] = (c[j] < DCL); }

    float acc[8][4] = {};
#pragma unroll 4
    for (int k = 0; k < 64; k++) {
        float a[8], b[4];
#pragma unroll
        for (int i = 0; i < 8; i++) a[i] = u_s[(ty + 8 * i) * 64 + k];
#pragma unroll
        for (int j = 0; j < 4; j++) b[j] = cv[j] ? mat[k * DCL + c[j]] : 0.f;
#pragma unroll
        for (int i = 0; i < 8; i++)
#pragma unroll
            for (int j = 0; j < 4; j++)
                acc[i][j] += a[i] * b[j];
    }
#pragma unroll
    for (int i = 0; i < 8; i++) {
        int row = rbase + ty + 8 * i;
#pragma unroll
        for (int j = 0; j < 4; j++)
            if (cv[j]) g_cl[row * DCL + c[j]] = acc[i][j];
    }
}

// ---------------------------------------------------------------------------
// Kernel 2b: fused LayerNorm + QKV GEMM (tf32 mma).
// ---------------------------------------------------------------------------
__global__ __launch_bounds__(384) void k2b_qkv(
    const float* __restrict__ ln_g, const float* __restrict__ ln_b,
    const float* __restrict__ wq, const float* __restrict__ bq,
    const float* __restrict__ wk, const float* __restrict__ bk,
    const float* __restrict__ wv, const float* __restrict__ bv)
{
    extern __shared__ uint32_t sm2b[];
    uint32_t (*As)[164] = (uint32_t(*)[164])sm2b;
    uint32_t (*Bs)[160][20] = (uint32_t(*)[160][20])(sm2b + 64 * 164);
    __shared__ float red[64];

    const int t    = threadIdx.x;
    const int lane = t & 31;
    const int warp = t >> 5;
    const int mat  = warp >> 2;
    const int wm   = warp & 3;
    const int g    = lane >> 2;
    const int tg   = lane & 3;
    const int mb   = blockIdx.x * 64;
    const int b0   = mb >> 5;

    const float* W[3]  = {wq, wk, wv};
    const float* BI[3] = {bq, bk, bv};
    float*       O[3]  = {g_q, g_k, g_v};

    float4 bst[5];
#pragma unroll
    for (int i = 0; i < 5; i++) {
        int idx = t + i * 384;
        int m = idx / 640, rem = idx % 640;
        int n = rem >> 2, c = rem & 3;
        bst[i] = *(const float4*)&W[m][n * EE + c * 4];
    }

    const float* cl0 = g_cl + (size_t)b0 * DCL;
    const float* cl1 = g_cl + (size_t)(b0 + 1) * DCL;
    float s0 = 0.f, q0 = 0.f, s1 = 0.f, q1 = 0.f;
    for (int i = t; i < 2560; i += 384) {
        int r = i / 40, c4 = i % 40;
        int hb = r >> 5, p = r & 31;
        int d = p * EE + c4 * 4;
        const float* clr = hb ? cl1 : cl0;
        float v[4];
#pragma unroll
        for (int j = 0; j < 4; j++) {
            int dd = d + j;
            v[j] = (dd >= PADN && dd < PADN + DCL) ? clr[dd - PADN] : 0.f;
        }
        *(float4*)&As[r][c4 * 4] = make_float4(v[0], v[1], v[2], v[3]);
        float ls = v[0] + v[1] + v[2] + v[3];
        float lq = v[0] * v[0] + v[1] * v[1] + v[2] * v[2] + v[3] * v[3];
        if (hb) { s1 += ls; q1 += lq; } else { s0 += ls; q0 += lq; }
    }
#pragma unroll
    for (int o = 16; o > 0; o >>= 1) {
        s0 += __shfl_xor_sync(~0u, s0, o);
        q0 += __shfl_xor_sync(~0u, q0, o);
        s1 += __shfl_xor_sync(~0u, s1, o);
        q1 += __shfl_xor_sync(~0u, q1, o);
    }
    if (lane == 0) {
        red[warp * 4 + 0] = s0; red[warp * 4 + 1] = q0;
        red[warp * 4 + 2] = s1; red[warp * 4 + 3] = q1;
    }
    __syncthreads();
    if (t < 2) {
        float s = 0.f, qq = 0.f;
        for (int w = 0; w < 12; w++) {
            s  += red[w * 4 + 2 * t];
            qq += red[w * 4 + 2 * t + 1];
        }
        float mu  = s / (float)DTRF;
        float var = qq / (float)DTRF - mu * mu;
        red[48 + t * 2]     = mu;
        red[48 + t * 2 + 1] = rsqrtf(var + 1e-5f);
    }
    __syncthreads();

    {
        float mu0 = red[48], rs0 = red[49], mu1 = red[50], rs1 = red[51];
        for (int i = t; i < 2560; i += 384) {
            int r = i / 40, c4 = i % 40;
            int hb = r >> 5, p = r & 31;
            int d = p * EE + c4 * 4;
            float mu = hb ? mu1 : mu0, rs = hb ? rs1 : rs0;
            float4 v  = *(float4*)&As[r][c4 * 4];
            float4 gg = *(const float4*)&ln_g[d];
            float4 bb = *(const float4*)&ln_b[d];
            uint4 u = make_uint4(
                f2tf32((v.x - mu) * rs * gg.x + bb.x),
                f2tf32((v.y - mu) * rs * gg.y + bb.y),
                f2tf32((v.z - mu) * rs * gg.z + bb.z),
                f2tf32((v.w - mu) * rs * gg.w + bb.w));
            *(uint4*)&As[r][c4 * 4] = u;
        }
    }
    __syncthreads();

    float acc[20][4] = {};
    for (int kc = 0; kc < 10; kc++) {
        if (kc) __syncthreads();
#pragma unroll
        for (int i = 0; i < 5; i++) {
            int idx = t + i * 384;
            int m = idx / 640, rem = idx % 640;
            int n = rem >> 2, c = rem & 3;
            uint4 u = make_uint4(f2tf32(bst[i].x), f2tf32(bst[i].y),
                                 f2tf32(bst[i].z), f2tf32(bst[i].w));
            *(uint4*)&Bs[m][n][c * 4] = u;
        }
        __syncthreads();
        if (kc + 1 < 10) {
            int k0 = (kc + 1) * 16;
#pragma unroll
            for (int i = 0; i < 5; i++) {
                int idx = t + i * 384;
                int m = idx / 640, rem = idx % 640;
                int n = rem >> 2, c = rem & 3;
                bst[i] = *(const float4*)&W[m][n * EE + k0 + c * 4];
            }
        }
#pragma unroll
        for (int ks = 0; ks < 2; ks++) {
            const int kA = kc * 16 + ks * 8;
            uint32_t af[4];
            af[0] = As[wm * 16 + g][kA + tg];
            af[1] = As[wm * 16 + g + 8][kA + tg];
            af[2] = As[wm * 16 + g][kA + tg + 4];
            af[3] = As[wm * 16 + g + 8][kA + tg + 4];
#pragma unroll
            for (int n8 = 0; n8 < 20; n8++) {
                uint32_t bf[2];
                bf[0] = Bs[mat][n8 * 8 + g][ks * 8 + tg];
                bf[1] = Bs[mat][n8 * 8 + g][ks * 8 + tg + 4];
                mma_tf32(acc[n8], af, bf);
            }
        }
    }

    const float* bias = BI[mat];
    float* out = O[mat];
    const int r0 = mb + wm * 16 + g;
#pragma unroll
    for (int n8 = 0; n8 < 20; n8++) {
        const int n0 = n8 * 8 + tg * 2;
        const float bb0 = bias[n0], bb1 = bias[n0 + 1];
        out[(size_t)r0 * EE + n0]           = acc[n8][0] + bb0;
        out[(size_t)r0 * EE + n0 + 1]       = acc[n8][1] + bb1;
        out[(size_t)(r0 + 8) * EE + n0]     = acc[n8][2] + bb0;
        out[(size_t)(r0 + 8) * EE + n0 + 1] = acc[n8][3] + bb1;
    }
}

// ---------------------------------------------------------------------------
// Kernel 2c: attention per batch row. 512 blocks x 128 threads.
// ---------------------------------------------------------------------------
__global__ __launch_bounds__(128) void k2c_attn()
{
    extern __shared__ float sm2c[];
    float (*sq)[164] = (float(*)[164])sm2c;
    float (*kt)[33]  = (float(*)[33]) (sm2c + 32 * 164);
    float (*sv)[164] = (float(*)[164])(sm2c + 32 * 164 + 160 * 33);
    float (*att)[33] = (float(*)[33]) (sm2c + 64 * 164 + 160 * 33);

    const int b = blockIdx.x;
    const int t = threadIdx.x;
    const float inv_scale = rsqrtf(160.0f);
    const size_t base = (size_t)b * PP * EE;

    for (int i = t; i < PP * EE; i += 128) {
        int p = i / EE, e = i % EE;
        sq[p][e] = g_q[base + i] * inv_scale;
        kt[e][p] = g_k[base + i];
        sv[p][e] = g_v[base + i];
    }
    __syncthreads();

#pragma unroll
    for (int it = 0; it < 2; it++) {
        const int idx = t + it * 128;
        const int p = idx >> 3, q4 = idx & 7;
        float acc[4] = {};
#pragma unroll 4
        for (int e4 = 0; e4 < 40; e4++) {
            float4 qv = *(const float4*)&sq[p][e4 * 4];
#pragma unroll
            for (int c = 0; c < 4; c++) {
                acc[c] += qv.x * kt[e4 * 4 + 0][q4 * 4 + c];
                acc[c] += qv.y * kt[e4 * 4 + 1][q4 * 4 + c];
                acc[c] += qv.z * kt[e4 * 4 + 2][q4 * 4 + c];
                acc[c] += qv.w * kt[e4 * 4 + 3][q4 * 4 + c];
            }
        }
#pragma unroll
        for (int c = 0; c < 4; c++) att[p][q4 * 4 + c] = acc[c];
    }
    __syncthreads();

    {
        const int q = t >> 2, pg = t & 3;
        float m = -1e30f;
#pragma unroll
        for (int i = 0; i < 8; i++) m = fmaxf(m, att[pg * 8 + i][q]);
        m = fmaxf(m, __shfl_xor_sync(~0u, m, 1));
        m = fmaxf(m, __shfl_xor_sync(~0u, m, 2));
        float s = 0.f;
        float ev[8];
#pragma unroll
        for (int i = 0; i < 8; i++) {
            ev[i] = __expf(att[pg * 8 + i][q] - m);
            s += ev[i];
        }
        s += __shfl_xor_sync(~0u, s, 1);
        s += __shfl_xor_sync(~0u, s, 2);
        float inv = 1.f / s;
#pragma unroll
        for (int i = 0; i < 8; i++) att[pg * 8 + i][q] = ev[i] * inv;
    }
    __syncthreads();

    const float* clrow = g_cl + (size_t)b * DCL;
#pragma unroll
    for (int j = 0; j < 10; j++) {
        int idx4 = t + j * 128;
        int p = idx4 / 40, e4 = idx4 % 40;
        float4 a = make_float4(0.f, 0.f, 0.f, 0.f);
#pragma unroll
        for (int q = 0; q < 32; q++) {
            float w = att[p][q];
            float4 vv = *(const float4*)&sv[q][e4 * 4];
            a.x += w * vv.x; a.y += w * vv.y;
            a.z += w * vv.z; a.w += w * vv.w;
        }
        int d = p * EE + e4 * 4;
        float cl0 = (d + 0 >= PADN && d + 0 < PADN + DCL) ? clrow[d + 0 - PADN] : 0.f;
        float cl1 = (d + 1 >= PADN && d + 1 < PADN + DCL) ? clrow[d + 1 - PADN] : 0.f;
        float cl2 = (d + 2 >= PADN && d + 2 < PADN + DCL) ? clrow[d + 2 - PADN] : 0.f;
        float cl3 = (d + 3 >= PADN && d + 3 < PADN + DCL) ? clrow[d + 3 - PADN] : 0.f;
        *(float4*)&g_h[base + d] =
            make_float4(a.x + cl0, a.y + cl1, a.z + cl2, a.w + cl3);
    }
}

// ---------------------------------------------------------------------------
// Kernel 2d: BT GEMM + Supact + residual (tf32 mma). BM=64, grid 256.
// Warps: wm = warp&3 -> rows wm*16; wn = warp>>2 -> N half (10 n8-tiles each).
// Writes g_yh (fp16).
// ---------------------------------------------------------------------------
__global__ __launch_bounds__(256) void k2d_bt(
    const float* __restrict__ bt_w, const float* __restrict__ bt_b,
    const float* __restrict__ bt_gain, const float* __restrict__ bt_bias,
    const float* __restrict__ sup_gamma, const float* __restrict__ sup_beta)
{
    extern __shared__ uint32_t sm2d[];
    uint32_t (*As)[164]     = (uint32_t(*)[164])sm2d;               // [64][164]
    uint32_t (*Bs)[16][168] = (uint32_t(*)[16][168])(sm2d + 64 * 164);

    const int t    = threadIdx.x;
    const int lane = t & 31;
    const int warp = t >> 5;
    const int wm   = warp & 3;
    const int wn   = warp >> 2;
    const int g    = lane >> 2;
    const int tg   = lane & 3;
    const int mb   = blockIdx.x * 64;
    const float btg = bt_gain[0], btb = bt_bias[0];

    float4 bst[3];
#pragma unroll
    for (int i = 0; i < 3; i++) {
        int idx = t + i * 256;
        if (idx < 640) {
            int e = idx / 40, f4 = idx % 40;
            bst[i] = *(const float4*)&bt_w[(size_t)e * EE + f4 * 4];
        }
    }

    for (int i = t; i < 2560; i += 256) {
        int r = i / 40, c4 = i % 40;
        float4 v = *(const float4*)&g_h[(size_t)(mb + r) * EE + c4 * 4];
        uint4 u = make_uint4(f2tf32(v.x * btg + btb), f2tf32(v.y * btg + btb),
                             f2tf32(v.z * btg + btb), f2tf32(v.w * btg + btb));
        *(uint4*)&As[r][c4 * 4] = u;
    }

    float acc[10][4] = {};
    for (int kc = 0; kc < 10; kc++) {
        const int buf = kc & 1;
#pragma unroll
        for (int i = 0; i < 3; i++) {
            int idx = t + i * 256;
            if (idx < 640) {
                int e = idx / 40, f4 = idx % 40;
                uint4 u = make_uint4(f2tf32(bst[i].x), f2tf32(bst[i].y),
                                     f2tf32(bst[i].z), f2tf32(bst[i].w));
                *(uint4*)&Bs[buf][e][f4 * 4] = u;
            }
        }
        __syncthreads();
        if (kc + 1 < 10) {
            int k0 = (kc + 1) * 16;
#pragma unroll
            for (int i = 0; i < 3; i++) {
                int idx = t + i * 256;
                if (idx < 640) {
                    int e = idx / 40, f4 = idx % 40;
                    bst[i] = *(const float4*)&bt_w[(size_t)(k0 + e) * EE + f4 * 4];
                }
            }
        }
#pragma unroll
        for (int ks = 0; ks < 2; ks++) {
            const int kA = kc * 16 + ks * 8;
            uint32_t af[4];
            af[0] = As[wm * 16 + g][kA + tg];
            af[1] = As[wm * 16 + g + 8][kA + tg];
            af[2] = As[wm * 16 + g][kA + tg + 4];
            af[3] = As[wm * 16 + g + 8][kA + tg + 4];
#pragma unroll
            for (int j = 0; j < 10; j++) {
                const int n8 = wn * 10 + j;
                uint32_t bf[2];
                bf[0] = Bs[buf][ks * 8 + tg][n8 * 8 + g];
                bf[1] = Bs[buf][ks * 8 + tg + 4][n8 * 8 + g];
                mma_tf32(acc[j], af, bf);
            }
        }
    }

    const int r0 = mb + wm * 16 + g;
#pragma unroll
    for (int j = 0; j < 10; j++) {
        const int n0 = (wn * 10 + j) * 8 + tg * 2;
        const float bb0 = bt_b[n0], bb1 = bt_b[n0 + 1];
#pragma unroll
        for (int half = 0; half < 2; half++) {
            const int row = r0 + half * 8;
            const int gi0 = (row & 31) * EE + n0;
            float o0 = acc[j][half * 2 + 0] + bb0;
            float o1 = acc[j][half * 2 + 1] + bb1;
            float gm0 = sup_gamma[gi0],     gm1 = sup_gamma[gi0 + 1];
            float sb0 = sup_beta[gi0],      sb1 = sup_beta[gi0 + 1];
            float h0  = g_h[(size_t)row * EE + n0];
            float h1  = g_h[(size_t)row * EE + n0 + 1];
            float s0 = 1.f / (1.f + __expf(-sb0 * o0));
            float s1 = 1.f / (1.f + __expf(-sb1 * o1));
            float y0 = (gm0 + s0 * (1.f - gm0)) * o0 + h0;
            float y1 = (gm1 + s1 * (1.f - gm1)) * o1 + h1;
            *(__half2*)&g_yh[(size_t)row * EE + n0] = __floats2half2_rn(y0, y1);
        }
    }
}

// ---------------------------------------------------------------------------
// Kernel 3: z = y @ lin_w^T  (fp16 in, cp.async double-buffered, ldmatrix)
// M=512, N=3000, K=5120. BM=128, BN=64, BK=64, 256 threads, 188 CTAs.
// smem rows padded to 72 halves (144B pitch -> ldmatrix conflict-free).
// ---------------------------------------------------------------------------
#define K3_BM 128
#define K3_BN 64
#define K3_BK 64
#define K3_LDH 72
#define K3_NIT (DTRF / K3_BK)    // 80
// half offsets within dynamic smem
#define K3_A_OFF(buf) ((buf) * K3_BM * K3_LDH)
#define K3_B_OFF(buf) (2 * K3_BM * K3_LDH + (buf) * K3_BN * K3_LDH)
#define K3_SMEM ((2 * K3_BM * K3_LDH + 2 * K3_BN * K3_LDH) * 2)   // 55296 B

__global__ __launch_bounds__(256) void k3_f16(
    const float* __restrict__ lin_b,
    const float* __restrict__ og_p, const float* __restrict__ ob_p,
    float* __restrict__ out)
{
    extern __shared__ __align__(16) __half smh[];
    const uint32_t sbase = (uint32_t)__cvta_generic_to_shared(smh);

    const int t    = threadIdx.x;
    const int lane = t & 31;
    const int warp = t >> 5;
    const int wm   = warp >> 1;   // 0..3 -> rows wm*32
    const int wn   = warp & 1;    // 0..1 -> cols wn*32
    const int g    = lane >> 2;
    const int tg   = lane & 3;

    const int mbase = blockIdx.y * K3_BM;
    const int nbase = blockIdx.x * K3_BN;

    // loader chunk mapping (16B = 8 halves per chunk)
    // A: 128 rows x 8 chunks = 1024 -> 4 per thread
    // B:  64 rows x 8 chunks =  512 -> 2 per thread
    const int arow0 = t >> 3;          // +32 per i
    const int ach   = t & 7;

    float acc[2][4][4] = {};

    // issue loads for iteration it into buffer buf
    auto issue = [&](int it, int buf) {
        const int kh = it * K3_BK;       // half offset in K
#pragma unroll
        for (int i = 0; i < 4; i++) {
            int row = arow0 + i * 32;
            uint32_t dst = sbase +
                (uint32_t)(K3_A_OFF(buf) + row * K3_LDH + ach * 8) * 2;
            cp16(dst, g_yh + (size_t)(mbase + row) * DTRF + kh + ach * 8);
        }
#pragma unroll
        for (int i = 0; i < 2; i++) {
            int row = arow0 + i * 32;
            if (row < K3_BN) {
                int br = nbase + row;
                if (br >= DOUT) br = 0;   // garbage rows never stored
                uint32_t dst = sbase +
                    (uint32_t)(K3_B_OFF(buf) + row * K3_LDH + ach * 8) * 2;
                cp16(dst, g_wh + (size_t)br * DTRF + kh + ach * 8);
            }
        }
        asm volatile("cp.async.commit_group;" ::: "memory");
    };

    issue(0, 0);

    for (int it = 0; it < K3_NIT; it++) {
        const int buf = it & 1;
        asm volatile("cp.async.wait_group 0;" ::: "memory");
        __syncthreads();
        if (it + 1 < K3_NIT) issue(it + 1, buf ^ 1);

        // compute on buf: 4 k16 steps
#pragma unroll
        for (int ks = 0; ks < 4; ks++) {
            const int k0 = ks * 16;
            uint32_t af[2][4];
#pragma unroll
            for (int mi = 0; mi < 2; mi++) {
                const int rb = wm * 32 + mi * 16;
                uint32_t addr = sbase + (uint32_t)(K3_A_OFF(buf) +
                    (rb + (lane & 15)) * K3_LDH + k0 + (lane >> 4) * 8) * 2;
                ldsm_x4(af[mi][0], af[mi][1], af[mi][2], af[mi][3], addr);
            }
            uint32_t bf[2][4];
#pragma unroll
            for (int nh = 0; nh < 2; nh++) {
                const int nb = wn * 32 + nh * 16;
                uint32_t addr = sbase + (uint32_t)(K3_B_OFF(buf) +
                    (nb + (lane & 7) + ((lane >> 4) & 1) * 8) * K3_LDH +
                    k0 + ((lane >> 3) & 1) * 8) * 2;
                ldsm_x4(bf[nh][0], bf[nh][1], bf[nh][2], bf[nh][3], addr);
            }
#pragma unroll
            for (int mi = 0; mi < 2; mi++)
#pragma unroll
                for (int ni = 0; ni < 4; ni++) {
                    const int nh = ni >> 1, sub = ni & 1;
                    mma_f16(acc[mi][ni], af[mi],
                            bf[nh][sub * 2], bf[nh][sub * 2 + 1]);
                }
        }
    }

    const float og = og_p[0], ob = ob_p[0];
#pragma unroll
    for (int mi = 0; mi < 2; mi++) {
        const int m0 = mbase + wm * 32 + mi * 16 + g;
#pragma unroll
        for (int ni = 0; ni < 4; ni++) {
            const int n0 = nbase + wn * 32 + ni * 8 + tg * 2;
            if (n0 + 1 < DOUT) {
                const float lb0 = lin_b[n0], lb1 = lin_b[n0 + 1];
                out[(size_t)m0 * DOUT + n0]           = (acc[mi][ni][0] + lb0) * og + ob;
                out[(size_t)m0 * DOUT + n0 + 1]       = (acc[mi][ni][1] + lb1) * og + ob;
                out[(size_t)(m0 + 8) * DOUT + n0]     = (acc[mi][ni][2] + lb0) * og + ob;
                out[(size_t)(m0 + 8) * DOUT + n0 + 1] = (acc[mi][ni][3] + lb1) * og + ob;
            } else if (n0 < DOUT) {
                const float lb0 = lin_b[n0];
                out[(size_t)m0 * DOUT + n0]       = (acc[mi][ni][0] + lb0) * og + ob;
                out[(size_t)(m0 + 8) * DOUT + n0] = (acc[mi][ni][2] + lb0) * og + ob;
            }
        }
    }
}

// ---------------------------------------------------------------------------
extern "C" void kernel_launch(void* const* d_in, const int* in_sizes, int n_in,
                              void* d_out, int out_size)
{
    const float* x         = (const float*)d_in[0];
    const float* stdv      = (const float*)d_in[1];
    const float* meanv     = (const float*)d_in[2];
    const float* mat       = (const float*)d_in[3];
    const float* ln_g      = (const float*)d_in[4];
    const float* ln_b      = (const float*)d_in[5];
    const float* wq        = (const float*)d_in[6];
    const float* bq        = (const float*)d_in[7];
    const float* wk        = (const float*)d_in[8];
    const float* bk        = (const float*)d_in[9];
    const float* wv        = (const float*)d_in[10];
    const float* bv        = (const float*)d_in[11];
    const float* bt_w      = (const float*)d_in[12];
    const float* bt_b      = (const float*)d_in[13];
    const float* bt_gain   = (const float*)d_in[14];
    const float* bt_bias   = (const float*)d_in[15];
    const float* sup_gamma = (const float*)d_in[16];
    const float* sup_beta  = (const float*)d_in[17];
    const float* lin_w     = (const float*)d_in[18];
    const float* lin_b     = (const float*)d_in[19];
    const float* out_gain  = (const float*)d_in[20];
    const float* out_bias  = (const float*)d_in[21];
    float* out = (float*)d_out;

    const int smem2b = (64 * 164 + 3 * 160 * 20) * 4;                      // 80384
    const int smem2c = (64 * 164 + 160 * 33 + 32 * 33) * 4 + 32 * 164 * 4; // 67328
    const int smem2d = (64 * 164 + 2 * 16 * 168) * 4;                      // 63488

    cudaFuncSetAttribute(k2b_qkv, cudaFuncAttributeMaxDynamicSharedMemorySize, smem2b);
    cudaFuncSetAttribute(k2c_attn, cudaFuncAttributeMaxDynamicSharedMemorySize, smem2c);
    cudaFuncSetAttribute(k2d_bt,  cudaFuncAttributeMaxDynamicSharedMemorySize, smem2d);
    cudaFuncSetAttribute(k3_f16,  cudaFuncAttributeMaxDynamicSharedMemorySize, K3_SMEM);

    k0_wh   <<<DOUT * DTRF / (8 * 256), 256>>>(lin_w);
    k1_clgemm<<<dim3(40, 8), 256>>>(x, stdv, meanv, mat);
    k2b_qkv <<<M2 / 64, 384, smem2b>>>(ln_g, ln_b, wq, bq, wk, bk, wv, bv);
    k2c_attn<<<B_SZ, 128, smem2c>>>();
    k2d_bt  <<<M2 / 64, 256, smem2d>>>(bt_w, bt_b, bt_gain, bt_bias,
                                       sup_gamma, sup_beta);
    k3_f16  <<<dim3((DOUT + K3_BN - 1) / K3_BN, B_SZ / K3_BM), 256, K3_SMEM>>>(
        lin_b, out_gain, out_bias, out);
}

// round 10
// speedup vs baseline: 3.6921x; 1.1300x over previous
#include <cuda_runtime.h>
#include <cuda_fp16.h>
#include <math.h>
#include <stdint.h>

// Problem constants
#define B_SZ  512
#define DIN   64
#define DCL   4998
#define DTRF  5120
#define PADN  61
#define PP    32
#define EE    160
#define DOUT  3000
#define M2    (B_SZ * PP)          // 16384 rows of 160

// Global scratch
__device__ float g_cl[B_SZ * DCL];
__device__ float g_q [M2 * EE];
__device__ float g_k [M2 * EE];
__device__ float g_v [M2 * EE];
__device__ float g_h [M2 * EE];
__device__ __align__(256) __half g_yh[M2 * EE];        // y in fp16 (k3 A operand)
__device__ __align__(256) __half g_wh[DOUT * DTRF];    // lin_w in fp16 (k3 B operand)

// ---------------------------------------------------------------------------
// helpers
// ---------------------------------------------------------------------------
__device__ __forceinline__ uint32_t f2tf32(float f) {
    uint32_t u;
    asm("cvt.rna.tf32.f32 %0, %1;" : "=r"(u) : "f"(f));
    return u;
}
__device__ __forceinline__ void mma_tf32(float* c, const uint32_t* a,
                                         const uint32_t* b) {
    asm volatile(
        "mma.sync.aligned.m16n8k8.row.col.f32.tf32.tf32.f32 "
        "{%0,%1,%2,%3}, {%4,%5,%6,%7}, {%8,%9}, {%0,%1,%2,%3};\n"
        : "+f"(c[0]), "+f"(c[1]), "+f"(c[2]), "+f"(c[3])
        : "r"(a[0]), "r"(a[1]), "r"(a[2]), "r"(a[3]),
          "r"(b[0]), "r"(b[1]));
}
__device__ __forceinline__ uint32_t pack2h(float a, float b) {
    __half2 h = __floats2half2_rn(a, b);
    return *(uint32_t*)&h;
}
__device__ __forceinline__ void mma_f16(float* c, const uint32_t* a,
                                        uint32_t b0, uint32_t b1) {
    asm volatile(
        "mma.sync.aligned.m16n8k16.row.col.f32.f16.f16.f32 "
        "{%0,%1,%2,%3}, {%4,%5,%6,%7}, {%8,%9}, {%0,%1,%2,%3};\n"
        : "+f"(c[0]), "+f"(c[1]), "+f"(c[2]), "+f"(c[3])
        : "r"(a[0]), "r"(a[1]), "r"(a[2]), "r"(a[3]),
          "r"(b0), "r"(b1));
}
__device__ __forceinline__ void ldsm_x4(uint32_t& r0, uint32_t& r1,
                                        uint32_t& r2, uint32_t& r3,
                                        uint32_t addr) {
    asm volatile(
        "ldmatrix.sync.aligned.m8n8.x4.shared.b16 {%0,%1,%2,%3}, [%4];"
        : "=r"(r0), "=r"(r1), "=r"(r2), "=r"(r3) : "r"(addr));
}
__device__ __forceinline__ void cp16(uint32_t dst, const void* src) {
    asm volatile("cp.async.cg.shared.global [%0], [%1], 16;"
                 :: "r"(dst), "l"(src));
}

// ---------------------------------------------------------------------------
// Kernel 0: convert lin_w -> g_wh (fp16).
// ---------------------------------------------------------------------------
__global__ __launch_bounds__(256) void k0_wh(const float* __restrict__ w)
{
    size_t i = ((size_t)blockIdx.x * 256 + threadIdx.x) * 8;
    float4 a = *(const float4*)(w + i);
    float4 b = *(const float4*)(w + i + 4);
    uint4 u;
    u.x = pack2h(a.x, a.y); u.y = pack2h(a.z, a.w);
    u.z = pack2h(b.x, b.y); u.w = pack2h(b.z, b.w);
    *(uint4*)(g_wh + i) = u;
}

// ---------------------------------------------------------------------------
// Kernel 1: cl = (x*std + mean) @ mat   64x128 tile, 8x4 per thread,
// 2-deep software pipeline on mat loads (8 LDGs in flight).
// ---------------------------------------------------------------------------
__global__ __launch_bounds__(256) void k1_clgemm(
    const float* __restrict__ x, const float* __restrict__ stdv,
    const float* __restrict__ meanv, const float* __restrict__ mat)
{
    __shared__ float u_s[64 * 64];
    const int rbase = blockIdx.y * 64;
    const int cbase = blockIdx.x * 128;
    const int tid = threadIdx.x;

    for (int idx = tid; idx < 64 * 64; idx += 256) {
        int r = idx >> 6, k = idx & 63;
        u_s[idx] = x[(rbase + r) * DIN + k] * stdv[k] + meanv[k];
    }
    __syncthreads();

    const int ty = tid >> 5;
    const int tx = tid & 31;
    int   c[4];  bool cv[4];
#pragma unroll
    for (int j = 0; j < 4; j++) { c[j] = cbase + tx + 32 * j; cv[j] = (c[j] < DCL); }

    float acc[8][4] = {};
    float bcur[2][4], bnxt[2][4];
#pragma unroll
    for (int kk = 0; kk < 2; kk++)
#pragma unroll
        for (int j = 0; j < 4; j++)
            bcur[kk][j] = cv[j] ? mat[kk * DCL + c[j]] : 0.f;

    for (int k = 0; k < 64; k += 2) {
        if (k + 2 < 64) {
#pragma unroll
            for (int kk = 0; kk < 2; kk++)
#pragma unroll
                for (int j = 0; j < 4; j++)
                    bnxt[kk][j] = cv[j] ? mat[(k + 2 + kk) * DCL + c[j]] : 0.f;
        }
#pragma unroll
        for (int kk = 0; kk < 2; kk++) {
            float a[8];
#pragma unroll
            for (int i = 0; i < 8; i++) a[i] = u_s[(ty + 8 * i) * 64 + k + kk];
#pragma unroll
            for (int i = 0; i < 8; i++)
#pragma unroll
                for (int j = 0; j < 4; j++)
                    acc[i][j] += a[i] * bcur[kk][j];
        }
#pragma unroll
        for (int kk = 0; kk < 2; kk++)
#pragma unroll
            for (int j = 0; j < 4; j++)
                bcur[kk][j] = bnxt[kk][j];
    }
#pragma unroll
    for (int i = 0; i < 8; i++) {
        int row = rbase + ty + 8 * i;
#pragma unroll
        for (int j = 0; j < 4; j++)
            if (cv[j]) g_cl[row * DCL + c[j]] = acc[i][j];
    }
}

// ---------------------------------------------------------------------------
// Kernel 2b: fused LayerNorm + QKV GEMM (tf32 mma).
// ---------------------------------------------------------------------------
__global__ __launch_bounds__(384) void k2b_qkv(
    const float* __restrict__ ln_g, const float* __restrict__ ln_b,
    const float* __restrict__ wq, const float* __restrict__ bq,
    const float* __restrict__ wk, const float* __restrict__ bk,
    const float* __restrict__ wv, const float* __restrict__ bv)
{
    extern __shared__ uint32_t sm2b[];
    uint32_t (*As)[164] = (uint32_t(*)[164])sm2b;
    uint32_t (*Bs)[160][20] = (uint32_t(*)[160][20])(sm2b + 64 * 164);
    __shared__ float red[64];

    const int t    = threadIdx.x;
    const int lane = t & 31;
    const int warp = t >> 5;
    const int mat  = warp >> 2;
    const int wm   = warp & 3;
    const int g    = lane >> 2;
    const int tg   = lane & 3;
    const int mb   = blockIdx.x * 64;
    const int b0   = mb >> 5;

    const float* W[3]  = {wq, wk, wv};
    const float* BI[3] = {bq, bk, bv};
    float*       O[3]  = {g_q, g_k, g_v};

    float4 bst[5];
#pragma unroll
    for (int i = 0; i < 5; i++) {
        int idx = t + i * 384;
        int m = idx / 640, rem = idx % 640;
        int n = rem >> 2, c = rem & 3;
        bst[i] = *(const float4*)&W[m][n * EE + c * 4];
    }

    const float* cl0 = g_cl + (size_t)b0 * DCL;
    const float* cl1 = g_cl + (size_t)(b0 + 1) * DCL;
    float s0 = 0.f, q0 = 0.f, s1 = 0.f, q1 = 0.f;
    for (int i = t; i < 2560; i += 384) {
        int r = i / 40, c4 = i % 40;
        int hb = r >> 5, p = r & 31;
        int d = p * EE + c4 * 4;
        const float* clr = hb ? cl1 : cl0;
        float v[4];
#pragma unroll
        for (int j = 0; j < 4; j++) {
            int dd = d + j;
            v[j] = (dd >= PADN && dd < PADN + DCL) ? clr[dd - PADN] : 0.f;
        }
        *(float4*)&As[r][c4 * 4] = make_float4(v[0], v[1], v[2], v[3]);
        float ls = v[0] + v[1] + v[2] + v[3];
        float lq = v[0] * v[0] + v[1] * v[1] + v[2] * v[2] + v[3] * v[3];
        if (hb) { s1 += ls; q1 += lq; } else { s0 += ls; q0 += lq; }
    }
#pragma unroll
    for (int o = 16; o > 0; o >>= 1) {
        s0 += __shfl_xor_sync(~0u, s0, o);
        q0 += __shfl_xor_sync(~0u, q0, o);
        s1 += __shfl_xor_sync(~0u, s1, o);
        q1 += __shfl_xor_sync(~0u, q1, o);
    }
    if (lane == 0) {
        red[warp * 4 + 0] = s0; red[warp * 4 + 1] = q0;
        red[warp * 4 + 2] = s1; red[warp * 4 + 3] = q1;
    }
    __syncthreads();
    if (t < 2) {
        float s = 0.f, qq = 0.f;
        for (int w = 0; w < 12; w++) {
            s  += red[w * 4 + 2 * t];
            qq += red[w * 4 + 2 * t + 1];
        }
        float mu  = s / (float)DTRF;
        float var = qq / (float)DTRF - mu * mu;
        red[48 + t * 2]     = mu;
        red[48 + t * 2 + 1] = rsqrtf(var + 1e-5f);
    }
    __syncthreads();

    {
        float mu0 = red[48], rs0 = red[49], mu1 = red[50], rs1 = red[51];
        for (int i = t; i < 2560; i += 384) {
            int r = i / 40, c4 = i % 40;
            int hb = r >> 5, p = r & 31;
            int d = p * EE + c4 * 4;
            float mu = hb ? mu1 : mu0, rs = hb ? rs1 : rs0;
            float4 v  = *(float4*)&As[r][c4 * 4];
            float4 gg = *(const float4*)&ln_g[d];
            float4 bb = *(const float4*)&ln_b[d];
            uint4 u = make_uint4(
                f2tf32((v.x - mu) * rs * gg.x + bb.x),
                f2tf32((v.y - mu) * rs * gg.y + bb.y),
                f2tf32((v.z - mu) * rs * gg.z + bb.z),
                f2tf32((v.w - mu) * rs * gg.w + bb.w));
            *(uint4*)&As[r][c4 * 4] = u;
        }
    }
    __syncthreads();

    float acc[20][4] = {};
    for (int kc = 0; kc < 10; kc++) {
        if (kc) __syncthreads();
#pragma unroll
        for (int i = 0; i < 5; i++) {
            int idx = t + i * 384;
            int m = idx / 640, rem = idx % 640;
            int n = rem >> 2, c = rem & 3;
            uint4 u = make_uint4(f2tf32(bst[i].x), f2tf32(bst[i].y),
                                 f2tf32(bst[i].z), f2tf32(bst[i].w));
            *(uint4*)&Bs[m][n][c * 4] = u;
        }
        __syncthreads();
        if (kc + 1 < 10) {
            int k0 = (kc + 1) * 16;
#pragma unroll
            for (int i = 0; i < 5; i++) {
                int idx = t + i * 384;
                int m = idx / 640, rem = idx % 640;
                int n = rem >> 2, c = rem & 3;
                bst[i] = *(const float4*)&W[m][n * EE + k0 + c * 4];
            }
        }
#pragma unroll
        for (int ks = 0; ks < 2; ks++) {
            const int kA = kc * 16 + ks * 8;
            uint32_t af[4];
            af[0] = As[wm * 16 + g][kA + tg];
            af[1] = As[wm * 16 + g + 8][kA + tg];
            af[2] = As[wm * 16 + g][kA + tg + 4];
            af[3] = As[wm * 16 + g + 8][kA + tg + 4];
#pragma unroll
            for (int n8 = 0; n8 < 20; n8++) {
                uint32_t bf[2];
                bf[0] = Bs[mat][n8 * 8 + g][ks * 8 + tg];
                bf[1] = Bs[mat][n8 * 8 + g][ks * 8 + tg + 4];
                mma_tf32(acc[n8], af, bf);
            }
        }
    }

    const float* bias = BI[mat];
    float* out = O[mat];
    const int r0 = mb + wm * 16 + g;
#pragma unroll
    for (int n8 = 0; n8 < 20; n8++) {
        const int n0 = n8 * 8 + tg * 2;
        const float bb0 = bias[n0], bb1 = bias[n0 + 1];
        out[(size_t)r0 * EE + n0]           = acc[n8][0] + bb0;
        out[(size_t)r0 * EE + n0 + 1]       = acc[n8][1] + bb1;
        out[(size_t)(r0 + 8) * EE + n0]     = acc[n8][2] + bb0;
        out[(size_t)(r0 + 8) * EE + n0 + 1] = acc[n8][3] + bb1;
    }
}

// ---------------------------------------------------------------------------
// Kernel 2c: attention per batch row. 512 blocks x 256 threads.
// sq[32][164], kt[160][36] (float4 reads: conflict-free w/ broadcast),
// sv[32][164] filled via cp.async (overlaps dot+softmax), att[32][33].
// ---------------------------------------------------------------------------
__global__ __launch_bounds__(256) void k2c_attn()
{
    extern __shared__ float sm2c[];
    float (*sq)[164] = (float(*)[164])sm2c;
    float (*kt)[36]  = (float(*)[36]) (sm2c + 32 * 164);
    float (*sv)[164] = (float(*)[164])(sm2c + 32 * 164 + 160 * 36);
    float (*att)[33] = (float(*)[33]) (sm2c + 64 * 164 + 160 * 36);

    const int b = blockIdx.x;
    const int t = threadIdx.x;
    const float inv_scale = rsqrtf(160.0f);
    const size_t base = (size_t)b * PP * EE;

    // fire-and-forget: V -> sv via cp.async (consumed only in AV phase)
#pragma unroll
    for (int i = 0; i < 5; i++) {
        int idx = t + i * 256;
        int p = idx / 40, c4 = idx % 40;
        uint32_t dst = (uint32_t)__cvta_generic_to_shared(&sv[p][c4 * 4]);
        cp16(dst, g_v + base + p * EE + c4 * 4);
    }
    asm volatile("cp.async.commit_group;" ::: "memory");

    // load Q (scaled) + K (transposed)
#pragma unroll
    for (int i = 0; i < 5; i++) {
        int idx = t + i * 256;
        int p = idx / 40, c4 = idx % 40;
        float4 qv = *(const float4*)&g_q[base + p * EE + c4 * 4];
        *(float4*)&sq[p][c4 * 4] = make_float4(qv.x * inv_scale, qv.y * inv_scale,
                                               qv.z * inv_scale, qv.w * inv_scale);
        float4 kv = *(const float4*)&g_k[base + p * EE + c4 * 4];
        kt[c4 * 4 + 0][p] = kv.x;
        kt[c4 * 4 + 1][p] = kv.y;
        kt[c4 * 4 + 2][p] = kv.z;
        kt[c4 * 4 + 3][p] = kv.w;
    }
    __syncthreads();

    // dot[p][q]: one (p,q4) pair per thread, float4 both operands
    {
        const int p = t >> 3, q4 = t & 7;
        float a0 = 0.f, a1 = 0.f, a2 = 0.f, a3 = 0.f;
#pragma unroll 4
        for (int e4 = 0; e4 < 40; e4++) {
            float4 qv = *(const float4*)&sq[p][e4 * 4];
            float4 k0 = *(const float4*)&kt[e4 * 4 + 0][q4 * 4];
            float4 k1 = *(const float4*)&kt[e4 * 4 + 1][q4 * 4];
            float4 k2 = *(const float4*)&kt[e4 * 4 + 2][q4 * 4];
            float4 k3 = *(const float4*)&kt[e4 * 4 + 3][q4 * 4];
            a0 += qv.x * k0.x + qv.y * k1.x + qv.z * k2.x + qv.w * k3.x;
            a1 += qv.x * k0.y + qv.y * k1.y + qv.z * k2.y + qv.w * k3.y;
            a2 += qv.x * k0.z + qv.y * k1.z + qv.z * k2.z + qv.w * k3.z;
            a3 += qv.x * k0.w + qv.y * k1.w + qv.z * k2.w + qv.w * k3.w;
        }
        att[p][q4 * 4 + 0] = a0; att[p][q4 * 4 + 1] = a1;
        att[p][q4 * 4 + 2] = a2; att[p][q4 * 4 + 3] = a3;
    }
    __syncthreads();

    // softmax over p (dim=1): 128 threads, (q = t>>2, pg = t&3), shfl combine
    if (t < 128) {
        const int q = t >> 2, pg = t & 3;
        float m = -1e30f;
#pragma unroll
        for (int i = 0; i < 8; i++) m = fmaxf(m, att[pg * 8 + i][q]);
        m = fmaxf(m, __shfl_xor_sync(~0u, m, 1));
        m = fmaxf(m, __shfl_xor_sync(~0u, m, 2));
        float s = 0.f;
        float ev[8];
#pragma unroll
        for (int i = 0; i < 8; i++) {
            ev[i] = __expf(att[pg * 8 + i][q] - m);
            s += ev[i];
        }
        s += __shfl_xor_sync(~0u, s, 1);
        s += __shfl_xor_sync(~0u, s, 2);
        float inv = 1.f / s;
#pragma unroll
        for (int i = 0; i < 8; i++) att[pg * 8 + i][q] = ev[i] * inv;
    }
    asm volatile("cp.async.wait_group 0;" ::: "memory");
    __syncthreads();

    // h = att @ V + cl_padded -> g_h
    const float* clrow = g_cl + (size_t)b * DCL;
#pragma unroll
    for (int j = 0; j < 5; j++) {
        int idx4 = t + j * 256;
        int p = idx4 / 40, e4 = idx4 % 40;
        float4 a = make_float4(0.f, 0.f, 0.f, 0.f);
#pragma unroll
        for (int q = 0; q < 32; q++) {
            float w = att[p][q];
            float4 vv = *(const float4*)&sv[q][e4 * 4];
            a.x += w * vv.x; a.y += w * vv.y;
            a.z += w * vv.z; a.w += w * vv.w;
        }
        int d = p * EE + e4 * 4;
        float cl0 = (d + 0 >= PADN && d + 0 < PADN + DCL) ? clrow[d + 0 - PADN] : 0.f;
        float cl1 = (d + 1 >= PADN && d + 1 < PADN + DCL) ? clrow[d + 1 - PADN] : 0.f;
        float cl2 = (d + 2 >= PADN && d + 2 < PADN + DCL) ? clrow[d + 2 - PADN] : 0.f;
        float cl3 = (d + 3 >= PADN && d + 3 < PADN + DCL) ? clrow[d + 3 - PADN] : 0.f;
        *(float4*)&g_h[base + d] =
            make_float4(a.x + cl0, a.y + cl1, a.z + cl2, a.w + cl3);
    }
}

// ---------------------------------------------------------------------------
// Kernel 2d: BT GEMM + Supact + residual (tf32 mma). BM=64, grid 256.
// Writes g_yh (fp16).
// ---------------------------------------------------------------------------
__global__ __launch_bounds__(256) void k2d_bt(
    const float* __restrict__ bt_w, const float* __restrict__ bt_b,
    const float* __restrict__ bt_gain, const float* __restrict__ bt_bias,
    const float* __restrict__ sup_gamma, const float* __restrict__ sup_beta)
{
    extern __shared__ uint32_t sm2d[];
    uint32_t (*As)[164]     = (uint32_t(*)[164])sm2d;
    uint32_t (*Bs)[16][168] = (uint32_t(*)[16][168])(sm2d + 64 * 164);

    const int t    = threadIdx.x;
    const int lane = t & 31;
    const int warp = t >> 5;
    const int wm   = warp & 3;
    const int wn   = warp >> 2;
    const int g    = lane >> 2;
    const int tg   = lane & 3;
    const int mb   = blockIdx.x * 64;
    const float btg = bt_gain[0], btb = bt_bias[0];

    float4 bst[3];
#pragma unroll
    for (int i = 0; i < 3; i++) {
        int idx = t + i * 256;
        if (idx < 640) {
            int e = idx / 40, f4 = idx % 40;
            bst[i] = *(const float4*)&bt_w[(size_t)e * EE + f4 * 4];
        }
    }

    for (int i = t; i < 2560; i += 256) {
        int r = i / 40, c4 = i % 40;
        float4 v = *(const float4*)&g_h[(size_t)(mb + r) * EE + c4 * 4];
        uint4 u = make_uint4(f2tf32(v.x * btg + btb), f2tf32(v.y * btg + btb),
                             f2tf32(v.z * btg + btb), f2tf32(v.w * btg + btb));
        *(uint4*)&As[r][c4 * 4] = u;
    }

    float acc[10][4] = {};
    for (int kc = 0; kc < 10; kc++) {
        const int buf = kc & 1;
#pragma unroll
        for (int i = 0; i < 3; i++) {
            int idx = t + i * 256;
            if (idx < 640) {
                int e = idx / 40, f4 = idx % 40;
                uint4 u = make_uint4(f2tf32(bst[i].x), f2tf32(bst[i].y),
                                     f2tf32(bst[i].z), f2tf32(bst[i].w));
                *(uint4*)&Bs[buf][e][f4 * 4] = u;
            }
        }
        __syncthreads();
        if (kc + 1 < 10) {
            int k0 = (kc + 1) * 16;
#pragma unroll
            for (int i = 0; i < 3; i++) {
                int idx = t + i * 256;
                if (idx < 640) {
                    int e = idx / 40, f4 = idx % 40;
                    bst[i] = *(const float4*)&bt_w[(size_t)(k0 + e) * EE + f4 * 4];
                }
            }
        }
#pragma unroll
        for (int ks = 0; ks < 2; ks++) {
            const int kA = kc * 16 + ks * 8;
            uint32_t af[4];
            af[0] = As[wm * 16 + g][kA + tg];
            af[1] = As[wm * 16 + g + 8][kA + tg];
            af[2] = As[wm * 16 + g][kA + tg + 4];
            af[3] = As[wm * 16 + g + 8][kA + tg + 4];
#pragma unroll
            for (int j = 0; j < 10; j++) {
                const int n8 = wn * 10 + j;
                uint32_t bf[2];
                bf[0] = Bs[buf][ks * 8 + tg][n8 * 8 + g];
                bf[1] = Bs[buf][ks * 8 + tg + 4][n8 * 8 + g];
                mma_tf32(acc[j], af, bf);
            }
        }
    }

    const int r0 = mb + wm * 16 + g;
#pragma unroll
    for (int j = 0; j < 10; j++) {
        const int n0 = (wn * 10 + j) * 8 + tg * 2;
        const float bb0 = bt_b[n0], bb1 = bt_b[n0 + 1];
#pragma unroll
        for (int half = 0; half < 2; half++) {
            const int row = r0 + half * 8;
            const int gi0 = (row & 31) * EE + n0;
            float o0 = acc[j][half * 2 + 0] + bb0;
            float o1 = acc[j][half * 2 + 1] + bb1;
            float gm0 = sup_gamma[gi0],     gm1 = sup_gamma[gi0 + 1];
            float sb0 = sup_beta[gi0],      sb1 = sup_beta[gi0 + 1];
            float h0  = g_h[(size_t)row * EE + n0];
            float h1  = g_h[(size_t)row * EE + n0 + 1];
            float s0 = 1.f / (1.f + __expf(-sb0 * o0));
            float s1 = 1.f / (1.f + __expf(-sb1 * o1));
            float y0 = (gm0 + s0 * (1.f - gm0)) * o0 + h0;
            float y1 = (gm1 + s1 * (1.f - gm1)) * o1 + h1;
            *(__half2*)&g_yh[(size_t)row * EE + n0] = __floats2half2_rn(y0, y1);
        }
    }
}

// ---------------------------------------------------------------------------
// Kernel 3: z = y @ lin_w^T  (fp16 in, cp.async double-buffered, ldmatrix)
// ---------------------------------------------------------------------------
#define K3_BM 128
#define K3_BN 64
#define K3_BK 64
#define K3_LDH 72
#define K3_NIT (DTRF / K3_BK)    // 80
#define K3_A_OFF(buf) ((buf) * K3_BM * K3_LDH)
#define K3_B_OFF(buf) (2 * K3_BM * K3_LDH + (buf) * K3_BN * K3_LDH)
#define K3_SMEM ((2 * K3_BM * K3_LDH + 2 * K3_BN * K3_LDH) * 2)   // 55296 B

__global__ __launch_bounds__(256) void k3_f16(
    const float* __restrict__ lin_b,
    const float* __restrict__ og_p, const float* __restrict__ ob_p,
    float* __restrict__ out)
{
    extern __shared__ __align__(16) __half smh[];
    const uint32_t sbase = (uint32_t)__cvta_generic_to_shared(smh);

    const int t    = threadIdx.x;
    const int lane = t & 31;
    const int warp = t >> 5;
    const int wm   = warp >> 1;
    const int wn   = warp & 1;
    const int g    = lane >> 2;
    const int tg   = lane & 3;

    const int mbase = blockIdx.y * K3_BM;
    const int nbase = blockIdx.x * K3_BN;

    const int arow0 = t >> 3;
    const int ach   = t & 7;

    float acc[2][4][4] = {};

    auto issue = [&](int it, int buf) {
        const int kh = it * K3_BK;
#pragma unroll
        for (int i = 0; i < 4; i++) {
            int row = arow0 + i * 32;
            uint32_t dst = sbase +
                (uint32_t)(K3_A_OFF(buf) + row * K3_LDH + ach * 8) * 2;
            cp16(dst, g_yh + (size_t)(mbase + row) * DTRF + kh + ach * 8);
        }
#pragma unroll
        for (int i = 0; i < 2; i++) {
            int row = arow0 + i * 32;
            if (row < K3_BN) {
                int br = nbase + row;
                if (br >= DOUT) br = 0;
                uint32_t dst = sbase +
                    (uint32_t)(K3_B_OFF(buf) + row * K3_LDH + ach * 8) * 2;
                cp16(dst, g_wh + (size_t)br * DTRF + kh + ach * 8);
            }
        }
        asm volatile("cp.async.commit_group;" ::: "memory");
    };

    issue(0, 0);

    for (int it = 0; it < K3_NIT; it++) {
        const int buf = it & 1;
        asm volatile("cp.async.wait_group 0;" ::: "memory");
        __syncthreads();
        if (it + 1 < K3_NIT) issue(it + 1, buf ^ 1);

#pragma unroll
        for (int ks = 0; ks < 4; ks++) {
            const int k0 = ks * 16;
            uint32_t af[2][4];
#pragma unroll
            for (int mi = 0; mi < 2; mi++) {
                const int rb = wm * 32 + mi * 16;
                uint32_t addr = sbase + (uint32_t)(K3_A_OFF(buf) +
                    (rb + (lane & 15)) * K3_LDH + k0 + (lane >> 4) * 8) * 2;
                ldsm_x4(af[mi][0], af[mi][1], af[mi][2], af[mi][3], addr);
            }
            uint32_t bf[2][4];
#pragma unroll
            for (int nh = 0; nh < 2; nh++) {
                const int nb = wn * 32 + nh * 16;
                uint32_t addr = sbase + (uint32_t)(K3_B_OFF(buf) +
                    (nb + (lane & 7) + ((lane >> 4) & 1) * 8) * K3_LDH +
                    k0 + ((lane >> 3) & 1) * 8) * 2;
                ldsm_x4(bf[nh][0], bf[nh][1], bf[nh][2], bf[nh][3], addr);
            }
#pragma unroll
            for (int mi = 0; mi < 2; mi++)
#pragma unroll
                for (int ni = 0; ni < 4; ni++) {
                    const int nh = ni >> 1, sub = ni & 1;
                    mma_f16(acc[mi][ni], af[mi],
                            bf[nh][sub * 2], bf[nh][sub * 2 + 1]);
                }
        }
    }

    const float og = og_p[0], ob = ob_p[0];
#pragma unroll
    for (int mi = 0; mi < 2; mi++) {
        const int m0 = mbase + wm * 32 + mi * 16 + g;
#pragma unroll
        for (int ni = 0; ni < 4; ni++) {
            const int n0 = nbase + wn * 32 + ni * 8 + tg * 2;
            if (n0 + 1 < DOUT) {
                const float lb0 = lin_b[n0], lb1 = lin_b[n0 + 1];
                out[(size_t)m0 * DOUT + n0]           = (acc[mi][ni][0] + lb0) * og + ob;
                out[(size_t)m0 * DOUT + n0 + 1]       = (acc[mi][ni][1] + lb1) * og + ob;
                out[(size_t)(m0 + 8) * DOUT + n0]     = (acc[mi][ni][2] + lb0) * og + ob;
                out[(size_t)(m0 + 8) * DOUT + n0 + 1] = (acc[mi][ni][3] + lb1) * og + ob;
            } else if (n0 < DOUT) {
                const float lb0 = lin_b[n0];
                out[(size_t)m0 * DOUT + n0]       = (acc[mi][ni][0] + lb0) * og + ob;
                out[(size_t)(m0 + 8) * DOUT + n0] = (acc[mi][ni][2] + lb0) * og + ob;
            }
        }
    }
}

// ---------------------------------------------------------------------------
extern "C" void kernel_launch(void* const* d_in, const int* in_sizes, int n_in,
                              void* d_out, int out_size)
{
    const float* x         = (const float*)d_in[0];
    const float* stdv      = (const float*)d_in[1];
    const float* meanv     = (const float*)d_in[2];
    const float* mat       = (const float*)d_in[3];
    const float* ln_g      = (const float*)d_in[4];
    const float* ln_b      = (const float*)d_in[5];
    const float* wq        = (const float*)d_in[6];
    const float* bq        = (const float*)d_in[7];
    const float* wk        = (const float*)d_in[8];
    const float* bk        = (const float*)d_in[9];
    const float* wv        = (const float*)d_in[10];
    const float* bv        = (const float*)d_in[11];
    const float* bt_w      = (const float*)d_in[12];
    const float* bt_b      = (const float*)d_in[13];
    const float* bt_gain   = (const float*)d_in[14];
    const float* bt_bias   = (const float*)d_in[15];
    const float* sup_gamma = (const float*)d_in[16];
    const float* sup_beta  = (const float*)d_in[17];
    const float* lin_w     = (const float*)d_in[18];
    const float* lin_b     = (const float*)d_in[19];
    const float* out_gain  = (const float*)d_in[20];
    const float* out_bias  = (const float*)d_in[21];
    float* out = (float*)d_out;

    const int smem2b = (64 * 164 + 3 * 160 * 20) * 4;                  // 80384
    const int smem2c = (64 * 164 + 160 * 36 + 32 * 33) * 4;            // 69248
    const int smem2d = (64 * 164 + 2 * 16 * 168) * 4;                  // 63488

    cudaFuncSetAttribute(k2b_qkv, cudaFuncAttributeMaxDynamicSharedMemorySize, smem2b);
    cudaFuncSetAttribute(k2c_attn, cudaFuncAttributeMaxDynamicSharedMemorySize, smem2c);
    cudaFuncSetAttribute(k2d_bt,  cudaFuncAttributeMaxDynamicSharedMemorySize, smem2d);
    cudaFuncSetAttribute(k3_f16,  cudaFuncAttributeMaxDynamicSharedMemorySize, K3_SMEM);

    k0_wh   <<<DOUT * DTRF / (8 * 256), 256>>>(lin_w);
    k1_clgemm<<<dim3(40, 8), 256>>>(x, stdv, meanv, mat);
    k2b_qkv <<<M2 / 64, 384, smem2b>>>(ln_g, ln_b, wq, bq, wk, bk, wv, bv);
    k2c_attn<<<B_SZ, 256, smem2c>>>();
    k2d_bt  <<<M2 / 64, 256, smem2d>>>(bt_w, bt_b, bt_gain, bt_bias,
                                       sup_gamma, sup_beta);
    k3_f16  <<<dim3((DOUT + K3_BN - 1) / K3_BN, B_SZ / K3_BM), 256, K3_SMEM>>>(
        lin_b, out_gain, out_bias, out);
}